// round 11
// baseline (speedup 1.0000x reference)
#include <cuda_runtime.h>
#include <cuda_bf16.h>
#include <cstdint>

#define N_NODES 50000
#define N_EDGES 625000
#define IN_DIM  512
#define HID     128
#define OUT_DIM 40
#define N_LAYERS 3
#define NB_SCAN ((N_NODES + 1023) / 1024)
#define N_TILES ((N_NODES + 127) / 128)
#define T_SPLIT (N_TILES / 2)              // 195
#define NODE_SPLIT (T_SPLIT * 128)         // 24960

// ---------------- scratch ---------------------------------------------------
__device__ float g_h[N_NODES * HID];     // h buffer 0
__device__ float g_t[N_NODES * HID];     // h buffer 1
__device__ float g_z[N_NODES * HID];     // z buffer
__device__ int   g_deg[N_NODES];
__device__ int   g_off[N_NODES];
__device__ int   g_cur[N_NODES];
__device__ uint2 g_edge[N_EDGES];        // {src, w_bits}
__device__ int   g_bsum[64];
__device__ uint32_t g_eBh[HID * (IN_DIM / 2)];
__device__ uint32_t g_eBl[HID * (IN_DIM / 2)];
__device__ uint32_t g_W1h[N_LAYERS * HID * (HID / 2)];
__device__ uint32_t g_W1l[N_LAYERS * HID * (HID / 2)];
__device__ uint32_t g_W2h[N_LAYERS * HID * (HID / 2)];
__device__ uint32_t g_W2l[N_LAYERS * HID * (HID / 2)];

// ---------------- helpers ----------------------------------------------------
__device__ __forceinline__ uint32_t smem_u32(const void* p) {
    uint32_t a;
    asm("{ .reg .u64 t; cvta.to.shared.u64 t, %1; cvt.u32.u64 %0, t; }" : "=r"(a) : "l"(p));
    return a;
}
__device__ __forceinline__ void split2(float v0, float v1, uint32_t& hi, uint32_t& lo) {
    uint16_t h0, h1, l0, l1;
    asm("cvt.rn.bf16.f32 %0, %1;" : "=h"(h0) : "f"(v0));
    asm("cvt.rn.bf16.f32 %0, %1;" : "=h"(h1) : "f"(v1));
    float r0 = v0 - __uint_as_float((uint32_t)h0 << 16);
    float r1 = v1 - __uint_as_float((uint32_t)h1 << 16);
    asm("cvt.rn.bf16.f32 %0, %1;" : "=h"(l0) : "f"(r0));
    asm("cvt.rn.bf16.f32 %0, %1;" : "=h"(l1) : "f"(r1));
    hi = ((uint32_t)h1 << 16) | h0;
    lo = ((uint32_t)l1 << 16) | l0;
}
__device__ __forceinline__ void mma_bf16(float* c, uint32_t a0, uint32_t a1,
                                         uint32_t a2, uint32_t a3,
                                         uint32_t b0, uint32_t b1) {
    asm volatile("mma.sync.aligned.m16n8k16.row.col.f32.bf16.bf16.f32 "
                 "{%0,%1,%2,%3}, {%4,%5,%6,%7}, {%8,%9}, {%0,%1,%2,%3};"
                 : "+f"(c[0]), "+f"(c[1]), "+f"(c[2]), "+f"(c[3])
                 : "r"(a0), "r"(a1), "r"(a2), "r"(a3), "r"(b0), "r"(b1));
}
__device__ __forceinline__ void ldsm_x4(uint32_t& r0, uint32_t& r1, uint32_t& r2,
                                        uint32_t& r3, uint32_t addr) {
    asm volatile("ldmatrix.sync.aligned.m8n8.x4.shared.b16 {%0,%1,%2,%3}, [%4];"
                 : "=r"(r0), "=r"(r1), "=r"(r2), "=r"(r3) : "r"(addr));
}

// ---------------- CSR build -------------------------------------------------
__global__ void zero_deg_kernel() {
    int i = blockIdx.x * blockDim.x + threadIdx.x;
    if (i < N_NODES) g_deg[i] = 0;
}
__global__ void hist_kernel(const int* __restrict__ dst) {
    int e = blockIdx.x * blockDim.x + threadIdx.x;
    if (e < N_EDGES) atomicAdd(&g_deg[dst[e]], 1);
}
__global__ void scan1_kernel() {
    __shared__ int s[1024];
    int t = threadIdx.x;
    int i = blockIdx.x * 1024 + t;
    int v = (i < N_NODES) ? g_deg[i] : 0;
    s[t] = v;
    __syncthreads();
    for (int d = 1; d < 1024; d <<= 1) {
        int tmp = (t >= d) ? s[t - d] : 0;
        __syncthreads();
        s[t] += tmp;
        __syncthreads();
    }
    if (i < N_NODES) g_off[i] = s[t] - v;
    if (t == 1023) g_bsum[blockIdx.x] = s[1023];
}
__global__ void scan23_kernel() {
    __shared__ int red[64];
    __shared__ int base_s;
    int t = threadIdx.x;
    if (t < 64) red[t] = (t < NB_SCAN && t < (int)blockIdx.x) ? g_bsum[t] : 0;
    __syncthreads();
    if (t < 32) {
        int s = red[t] + red[t + 32];
        for (int d = 16; d > 0; d >>= 1) s += __shfl_down_sync(0xffffffffu, s, d);
        if (t == 0) base_s = s;
    }
    __syncthreads();
    int i = blockIdx.x * 1024 + t;
    if (i < N_NODES) {
        int o = g_off[i] + base_s;
        g_off[i] = o;
        g_cur[i] = o;
    }
}
__global__ void scatter_kernel(const int* __restrict__ src,
                               const int* __restrict__ dst,
                               const float* __restrict__ ew) {
    int e = blockIdx.x * blockDim.x + threadIdx.x;
    if (e < N_EDGES) {
        int d = dst[e];
        int pos = atomicAdd(&g_cur[d], 1);
        g_edge[pos] = make_uint2((uint32_t)src[e], __float_as_uint(ew[e]));
    }
}

// ---------------- weight prep ------------------------------------------------
__global__ void prep_emb_kernel(const float* __restrict__ W) {
    int idx = blockIdx.x * blockDim.x + threadIdx.x;
    int n = idx >> 8, k2 = idx & 255;
    uint32_t hi, lo;
    split2(W[(size_t)(2 * k2) * HID + n], W[(size_t)(2 * k2 + 1) * HID + n], hi, lo);
    g_eBh[n * 256 + k2] = hi;
    g_eBl[n * 256 + k2] = lo;
}
__global__ void prep_w_kernel(const float* __restrict__ W1, const float* __restrict__ W2) {
    int idx = blockIdx.x * blockDim.x + threadIdx.x;
    if (idx >= N_LAYERS * HID * 64) return;
    int l = idx / (HID * 64);
    int rem = idx - l * HID * 64;
    int n = rem >> 6, k2 = rem & 63;
    const float* w1 = W1 + (size_t)l * HID * HID;
    const float* w2 = W2 + (size_t)l * HID * HID;
    uint32_t hi, lo;
    split2(w1[(2 * k2) * HID + n], w1[(2 * k2 + 1) * HID + n], hi, lo);
    g_W1h[idx] = hi; g_W1l[idx] = lo;
    split2(w2[(2 * k2) * HID + n], w2[(2 * k2 + 1) * HID + n], hi, lo);
    g_W2h[idx] = hi; g_W2l[idx] = lo;
}

// ---------------- emb GEMM: double-buffered k-loop --------------------------
#define ST 36
#define CHW (128 * ST)
#define BUFW (4 * CHW)
__global__ void __launch_bounds__(512, 1)
emb_gemm_kernel(const float* __restrict__ A, const float* __restrict__ bias, int M) {
    extern __shared__ uint32_t sh[];

    const int tid = threadIdx.x, lane = tid & 31, wid = tid >> 5;
    const int g = lane >> 2, tg = lane & 3;
    const int wm = wid & 7, wn = wid >> 3;
    const int row0 = blockIdx.x * 128;

    const int lr = lane & 7, lo8 = (lane >> 3) & 1, hi16 = (lane >> 4) & 1;
    const uint32_t shB = smem_u32(sh);
    const int aRowOff = (wm * 16 + lr + 8 * lo8) * ST + 4 * hi16;
    const int bRowOff = (wn * 64 + lr + 8 * hi16) * ST + 4 * lo8;

    float4 aR[4];
    uint4  bRh[2], bRl[2];

#pragma unroll
    for (int it = 0; it < 4; it++) {
        int e = tid + it * 512;
        int m = e >> 4, j = e & 15;
        int r = row0 + m;
        aR[it] = make_float4(0.f, 0.f, 0.f, 0.f);
        if (r < M) aR[it] = *(const float4*)(A + (size_t)r * IN_DIM + j * 4);
    }
#pragma unroll
    for (int it = 0; it < 2; it++) {
        int e = tid + it * 512;
        int n = e >> 3, q = e & 7;
        bRh[it] = *(const uint4*)(g_eBh + n * 256 + q * 4);
        bRl[it] = *(const uint4*)(g_eBl + n * 256 + q * 4);
    }
    {
        uint32_t* Ah = sh;            uint32_t* Al = sh + CHW;
        uint32_t* Bh = sh + 2 * CHW;  uint32_t* Bl = sh + 3 * CHW;
#pragma unroll
        for (int it = 0; it < 4; it++) {
            int e = tid + it * 512;
            int m = e >> 4, j = e & 15;
            uint32_t h0, l0, h1, l1;
            split2(aR[it].x, aR[it].y, h0, l0);
            split2(aR[it].z, aR[it].w, h1, l1);
            int o = m * ST + j * 2;
            Ah[o] = h0; Ah[o + 1] = h1;
            Al[o] = l0; Al[o + 1] = l1;
        }
#pragma unroll
        for (int it = 0; it < 2; it++) {
            int e = tid + it * 512;
            int n = e >> 3, q = e & 7;
            int o = n * ST + q * 4;
            *(uint4*)(Bh + o) = bRh[it];
            *(uint4*)(Bl + o) = bRl[it];
        }
    }
    __syncthreads();

    float c[8][4];
#pragma unroll
    for (int ni = 0; ni < 8; ni++)
#pragma unroll
        for (int q = 0; q < 4; q++) c[ni][q] = 0.f;

    const int NCH = IN_DIM / 64;
    for (int ci = 0; ci < NCH; ci++) {
        const int p = ci & 1;
        const uint32_t base = shB + (uint32_t)p * BUFW * 4u;
        const uint32_t AhB = base, AlB = base + CHW * 4u;
        const uint32_t BhB = base + 2u * CHW * 4u, BlB = base + 3u * CHW * 4u;

        if (ci + 1 < NCH) {
            int kn = (ci + 1) * 64, kn2 = kn >> 1;
#pragma unroll
            for (int it = 0; it < 4; it++) {
                int e = tid + it * 512;
                int m = e >> 4, j = e & 15;
                int r = row0 + m;
                aR[it] = make_float4(0.f, 0.f, 0.f, 0.f);
                if (r < M) aR[it] = *(const float4*)(A + (size_t)r * IN_DIM + kn + j * 4);
            }
#pragma unroll
            for (int it = 0; it < 2; it++) {
                int e = tid + it * 512;
                int n = e >> 3, q = e & 7;
                bRh[it] = *(const uint4*)(g_eBh + n * 256 + kn2 + q * 4);
                bRl[it] = *(const uint4*)(g_eBl + n * 256 + kn2 + q * 4);
            }
        }

#pragma unroll
        for (int ks2 = 0; ks2 < 32; ks2 += 8) {
            uint32_t a0, a1, a2, a3, l0, l1, l2, l3;
            ldsm_x4(a0, a1, a2, a3, AhB + (uint32_t)(aRowOff + ks2) * 4u);
            ldsm_x4(l0, l1, l2, l3, AlB + (uint32_t)(aRowOff + ks2) * 4u);
            uint32_t bh[8][2], bl[8][2];
#pragma unroll
            for (int q = 0; q < 4; q++) {
                uint32_t r0, r1, r2, r3;
                ldsm_x4(r0, r1, r2, r3, BhB + (uint32_t)(bRowOff + q * 16 * ST + ks2) * 4u);
                bh[2 * q][0] = r0; bh[2 * q][1] = r1;
                bh[2 * q + 1][0] = r2; bh[2 * q + 1][1] = r3;
                ldsm_x4(r0, r1, r2, r3, BlB + (uint32_t)(bRowOff + q * 16 * ST + ks2) * 4u);
                bl[2 * q][0] = r0; bl[2 * q][1] = r1;
                bl[2 * q + 1][0] = r2; bl[2 * q + 1][1] = r3;
            }
#pragma unroll
            for (int ni = 0; ni < 8; ni++) {
                mma_bf16(c[ni], a0, a1, a2, a3, bh[ni][0], bh[ni][1]);
                mma_bf16(c[ni], a0, a1, a2, a3, bl[ni][0], bl[ni][1]);
                mma_bf16(c[ni], l0, l1, l2, l3, bh[ni][0], bh[ni][1]);
            }
        }

        if (ci + 1 < NCH) {
            uint32_t* Ah = sh + (p ^ 1) * BUFW;
            uint32_t* Al = Ah + CHW;
            uint32_t* Bh = Ah + 2 * CHW;
            uint32_t* Bl = Ah + 3 * CHW;
#pragma unroll
            for (int it = 0; it < 4; it++) {
                int e = tid + it * 512;
                int m = e >> 4, j = e & 15;
                uint32_t h0, l0, h1, l1;
                split2(aR[it].x, aR[it].y, h0, l0);
                split2(aR[it].z, aR[it].w, h1, l1);
                int o = m * ST + j * 2;
                Ah[o] = h0; Ah[o + 1] = h1;
                Al[o] = l0; Al[o + 1] = l1;
            }
#pragma unroll
            for (int it = 0; it < 2; it++) {
                int e = tid + it * 512;
                int n = e >> 3, q = e & 7;
                int o = n * ST + q * 4;
                *(uint4*)(Bh + o) = bRh[it];
                *(uint4*)(Bl + o) = bRl[it];
            }
            __syncthreads();
        }
    }

#pragma unroll
    for (int half = 0; half < 2; half++) {
        int row = row0 + wm * 16 + g + half * 8;
        if (row >= M) continue;
#pragma unroll
        for (int ni = 0; ni < 8; ni++) {
            int col = wn * 64 + ni * 8 + tg * 2;
            float2 o;
            o.x = c[ni][half * 2 + 0] + bias[col];
            o.y = c[ni][half * 2 + 1] + bias[col + 1];
            *(float2*)(g_h + (size_t)row * HID + col) = o;
        }
    }
}

// ---------------- aggregation (node range): g_z = hin + gather --------------
__global__ void agg_kernel(const float* __restrict__ hin, int n0, int n1) {
    int node = n0 + ((blockIdx.x * blockDim.x + threadIdx.x) >> 5);
    int lane = threadIdx.x & 31;
    if (node >= n1) return;
    int s = g_off[node];
    int d = g_deg[node];
    float4 acc = *(const float4*)(hin + (size_t)node * HID + lane * 4);
    int i = 0;
    for (; i + 2 <= d; i += 2) {
        uint2 e0 = g_edge[s + i];
        uint2 e1 = g_edge[s + i + 1];
        float w0 = __uint_as_float(e0.y);
        float w1 = __uint_as_float(e1.y);
        float4 h0 = *(const float4*)(hin + (size_t)e0.x * HID + lane * 4);
        float4 h1 = *(const float4*)(hin + (size_t)e1.x * HID + lane * 4);
        acc.x += w0 * h0.x + w1 * h1.x;
        acc.y += w0 * h0.y + w1 * h1.y;
        acc.z += w0 * h0.z + w1 * h1.z;
        acc.w += w0 * h0.w + w1 * h1.w;
    }
    if (i < d) {
        uint2 e0 = g_edge[s + i];
        float w0 = __uint_as_float(e0.y);
        float4 h0 = *(const float4*)(hin + (size_t)e0.x * HID + lane * 4);
        acc.x += w0 * h0.x; acc.y += w0 * h0.y;
        acc.z += w0 * h0.z; acc.w += w0 * h0.w;
    }
    *(float4*)(g_z + (size_t)node * HID + lane * 4) = acc;
}

// ---------------- persistent fused MLP over tile range ----------------------
#define ST2 68
__global__ void __launch_bounds__(512, 1)
mlp_fused_kernel(const float* __restrict__ zin, float* __restrict__ hout,
                 const uint32_t* __restrict__ W1h, const uint32_t* __restrict__ W1l,
                 const uint32_t* __restrict__ W2h, const uint32_t* __restrict__ W2l,
                 const float* __restrict__ b1, const float* __restrict__ b2,
                 int M, int t0, int t1) {
    extern __shared__ uint32_t sh[];
    uint32_t* Ah  = sh;
    uint32_t* Al  = sh + 128 * ST2;
    uint32_t* Wh1 = sh + 2 * 128 * ST2;
    uint32_t* Wl1 = sh + 3 * 128 * ST2;
    uint32_t* Wh2 = sh + 4 * 128 * ST2;
    uint32_t* Wl2 = sh + 5 * 128 * ST2;

    const int tid = threadIdx.x, lane = tid & 31, wid = tid >> 5;
    const int g = lane >> 2, tg = lane & 3;
    const int wm = wid & 7, wn = wid >> 3;

    const int lr = lane & 7, lo8 = (lane >> 3) & 1, hi16 = (lane >> 4) & 1;
    const uint32_t AhB  = smem_u32(Ah),  AlB  = smem_u32(Al);
    const uint32_t Wh1B = smem_u32(Wh1), Wl1B = smem_u32(Wl1);
    const uint32_t Wh2B = smem_u32(Wh2), Wl2B = smem_u32(Wl2);
    const int aRowOff = (wm * 16 + lr + 8 * lo8) * ST2 + 4 * hi16;
    const int bRowOff = (wn * 64 + lr + 8 * hi16) * ST2 + 4 * lo8;

#pragma unroll
    for (int it = 0; it < 4; it++) {
        int e = tid + it * 512;
        int n = e >> 4, q = e & 15;
        int o = n * ST2 + q * 4;
        *(uint4*)(Wh1 + o) = *(const uint4*)(W1h + n * 64 + q * 4);
        *(uint4*)(Wl1 + o) = *(const uint4*)(W1l + n * 64 + q * 4);
        *(uint4*)(Wh2 + o) = *(const uint4*)(W2h + n * 64 + q * 4);
        *(uint4*)(Wl2 + o) = *(const uint4*)(W2l + n * 64 + q * 4);
    }

    for (int tile = t0 + blockIdx.x; tile < t1; tile += gridDim.x) {
        const int row0 = tile * 128;
        __syncthreads();
#pragma unroll
        for (int it = 0; it < 8; it++) {
            int e = tid + it * 512;
            int m = e >> 5, j = e & 31;
            int r = row0 + m;
            float4 v = make_float4(0.f, 0.f, 0.f, 0.f);
            if (r < M) v = *(const float4*)(zin + (size_t)r * HID + j * 4);
            uint32_t h0, l0, h1, l1;
            split2(v.x, v.y, h0, l0);
            split2(v.z, v.w, h1, l1);
            int o = m * ST2 + j * 2;
            Ah[o] = h0; Ah[o + 1] = h1;
            Al[o] = l0; Al[o + 1] = l1;
        }
        __syncthreads();

        float c[8][4];
#pragma unroll
        for (int ni = 0; ni < 8; ni++)
#pragma unroll
            for (int q = 0; q < 4; q++) c[ni][q] = 0.f;

        // GEMM1
#pragma unroll
        for (int ks2 = 0; ks2 < 64; ks2 += 8) {
            uint32_t a0, a1, a2, a3, l0, l1, l2, l3;
            ldsm_x4(a0, a1, a2, a3, AhB + (uint32_t)(aRowOff + ks2) * 4u);
            ldsm_x4(l0, l1, l2, l3, AlB + (uint32_t)(aRowOff + ks2) * 4u);
            uint32_t bh[8][2], bl[8][2];
#pragma unroll
            for (int q = 0; q < 4; q++) {
                uint32_t r0, r1, r2, r3;
                ldsm_x4(r0, r1, r2, r3, Wh1B + (uint32_t)(bRowOff + q * 16 * ST2 + ks2) * 4u);
                bh[2 * q][0] = r0; bh[2 * q][1] = r1;
                bh[2 * q + 1][0] = r2; bh[2 * q + 1][1] = r3;
                ldsm_x4(r0, r1, r2, r3, Wl1B + (uint32_t)(bRowOff + q * 16 * ST2 + ks2) * 4u);
                bl[2 * q][0] = r0; bl[2 * q][1] = r1;
                bl[2 * q + 1][0] = r2; bl[2 * q + 1][1] = r3;
            }
#pragma unroll
            for (int ni = 0; ni < 8; ni++) {
                mma_bf16(c[ni], a0, a1, a2, a3, bh[ni][0], bh[ni][1]);
                mma_bf16(c[ni], a0, a1, a2, a3, bl[ni][0], bl[ni][1]);
                mma_bf16(c[ni], l0, l1, l2, l3, bh[ni][0], bh[ni][1]);
            }
        }
        __syncthreads();

        // relu(c + b1) -> split -> Ah/Al
#pragma unroll
        for (int ni = 0; ni < 8; ni++) {
            int col = wn * 64 + ni * 8 + tg * 2;
            float bb0 = b1[col], bb1 = b1[col + 1];
            int k2 = wn * 32 + ni * 4 + tg;
            int r0 = wm * 16 + g;
            uint32_t hi, lo;
            split2(fmaxf(c[ni][0] + bb0, 0.f), fmaxf(c[ni][1] + bb1, 0.f), hi, lo);
            Ah[r0 * ST2 + k2] = hi; Al[r0 * ST2 + k2] = lo;
            split2(fmaxf(c[ni][2] + bb0, 0.f), fmaxf(c[ni][3] + bb1, 0.f), hi, lo);
            Ah[(r0 + 8) * ST2 + k2] = hi; Al[(r0 + 8) * ST2 + k2] = lo;
        }
        __syncthreads();

#pragma unroll
        for (int ni = 0; ni < 8; ni++)
#pragma unroll
            for (int q = 0; q < 4; q++) c[ni][q] = 0.f;

        // GEMM2
#pragma unroll
        for (int ks2 = 0; ks2 < 64; ks2 += 8) {
            uint32_t a0, a1, a2, a3, l0, l1, l2, l3;
            ldsm_x4(a0, a1, a2, a3, AhB + (uint32_t)(aRowOff + ks2) * 4u);
            ldsm_x4(l0, l1, l2, l3, AlB + (uint32_t)(aRowOff + ks2) * 4u);
            uint32_t bh[8][2], bl[8][2];
#pragma unroll
            for (int q = 0; q < 4; q++) {
                uint32_t r0, r1, r2, r3;
                ldsm_x4(r0, r1, r2, r3, Wh2B + (uint32_t)(bRowOff + q * 16 * ST2 + ks2) * 4u);
                bh[2 * q][0] = r0; bh[2 * q][1] = r1;
                bh[2 * q + 1][0] = r2; bh[2 * q + 1][1] = r3;
                ldsm_x4(r0, r1, r2, r3, Wl2B + (uint32_t)(bRowOff + q * 16 * ST2 + ks2) * 4u);
                bl[2 * q][0] = r0; bl[2 * q][1] = r1;
                bl[2 * q + 1][0] = r2; bl[2 * q + 1][1] = r3;
            }
#pragma unroll
            for (int ni = 0; ni < 8; ni++) {
                mma_bf16(c[ni], a0, a1, a2, a3, bh[ni][0], bh[ni][1]);
                mma_bf16(c[ni], a0, a1, a2, a3, bl[ni][0], bl[ni][1]);
                mma_bf16(c[ni], l0, l1, l2, l3, bh[ni][0], bh[ni][1]);
            }
        }

#pragma unroll
        for (int half = 0; half < 2; half++) {
            int row = row0 + wm * 16 + g + half * 8;
            if (row >= M) continue;
#pragma unroll
            for (int ni = 0; ni < 8; ni++) {
                int col = wn * 64 + ni * 8 + tg * 2;
                float2 o;
                o.x = fmaxf(c[ni][half * 2 + 0] + b2[col], 0.f);
                o.y = fmaxf(c[ni][half * 2 + 1] + b2[col + 1], 0.f);
                *(float2*)(hout + (size_t)row * HID + col) = o;
            }
        }
    }
}

// ---------------- readout ----------------------------------------------------
__global__ void readout_kernel(const float* __restrict__ hin,
                               const float* __restrict__ Wr,
                               const float* __restrict__ br,
                               float* __restrict__ out, int M) {
    extern __shared__ float sm[];
    float* hs = sm;
    float* wt = sm + 128 * 132;
    const int row0 = blockIdx.x * 128;
    const int tr = threadIdx.x >> 3;
    const int cg = threadIdx.x & 7;

    for (int e = threadIdx.x; e < 128 * 128; e += 256) {
        int m = e >> 7, k = e & 127;
        int r = row0 + m;
        hs[m * 132 + k] = (r < M) ? hin[(size_t)r * HID + k] : 0.f;
    }
    for (int e = threadIdx.x; e < 128 * OUT_DIM; e += 256) {
        int k = e / OUT_DIM, c = e % OUT_DIM;
        wt[c * 132 + k] = Wr[e];
    }
    __syncthreads();

    float acc[4][5];
#pragma unroll
    for (int r = 0; r < 4; r++)
#pragma unroll
        for (int c = 0; c < 5; c++) acc[r][c] = 0.f;

    for (int k = 0; k < 128; k += 4) {
        float4 hv[4];
#pragma unroll
        for (int r = 0; r < 4; r++)
            hv[r] = *(const float4*)(hs + (tr * 4 + r) * 132 + k);
#pragma unroll
        for (int c = 0; c < 5; c++) {
            float4 wv = *(const float4*)(wt + (cg * 5 + c) * 132 + k);
#pragma unroll
            for (int r = 0; r < 4; r++)
                acc[r][c] += hv[r].x * wv.x + hv[r].y * wv.y
                           + hv[r].z * wv.z + hv[r].w * wv.w;
        }
    }
#pragma unroll
    for (int r = 0; r < 4; r++) {
        int row = row0 + tr * 4 + r;
        if (row < M) {
#pragma unroll
            for (int c = 0; c < 5; c++) {
                int col = cg * 5 + c;
                out[(size_t)row * OUT_DIM + col] = acc[r][c] + br[col];
            }
        }
    }
}

// ---------------- launch ----------------------------------------------------
extern "C" void kernel_launch(void* const* d_in, const int* in_sizes, int n_in,
                              void* d_out, int out_size) {
    const float* features = (const float*)d_in[0];
    const int*   src      = (const int*)  d_in[1];
    const int*   dst      = (const int*)  d_in[2];
    const float* edge_w   = (const float*)d_in[3];
    const float* emb_W    = (const float*)d_in[4];
    const float* emb_b    = (const float*)d_in[5];
    const float* W1       = (const float*)d_in[6];
    const float* b1       = (const float*)d_in[7];
    const float* W2       = (const float*)d_in[8];
    const float* b2       = (const float*)d_in[9];
    const float* ro_W     = (const float*)d_in[10];
    const float* ro_b     = (const float*)d_in[11];
    float* out = (float*)d_out;

    const int emb_smem = 2 * 4 * 128 * ST * (int)sizeof(uint32_t);   // 147456
    const int mlp_smem = 6 * 128 * ST2 * (int)sizeof(uint32_t);      // 208896
    const int ro_smem  = (128 * 132 + OUT_DIM * 132) * (int)sizeof(float);
    cudaFuncSetAttribute(emb_gemm_kernel,  cudaFuncAttributeMaxDynamicSharedMemorySize, emb_smem);
    cudaFuncSetAttribute(mlp_fused_kernel, cudaFuncAttributeMaxDynamicSharedMemorySize, mlp_smem);
    cudaFuncSetAttribute(readout_kernel,   cudaFuncAttributeMaxDynamicSharedMemorySize, ro_smem);

    float *d_h0, *d_h1, *d_zz;
    cudaGetSymbolAddress((void**)&d_h0, g_h);
    cudaGetSymbolAddress((void**)&d_h1, g_t);
    cudaGetSymbolAddress((void**)&d_zz, g_z);
    uint32_t *d_W1h, *d_W1l, *d_W2h, *d_W2l;
    cudaGetSymbolAddress((void**)&d_W1h, g_W1h);
    cudaGetSymbolAddress((void**)&d_W1l, g_W1l);
    cudaGetSymbolAddress((void**)&d_W2h, g_W2h);
    cudaGetSymbolAddress((void**)&d_W2l, g_W2l);

    cudaStream_t side = cudaStreamPerThread;
    cudaEvent_t evA, evB, evIn[N_LAYERS], evAgg[N_LAYERS];
    cudaEventCreateWithFlags(&evA, cudaEventDisableTiming);
    cudaEventCreateWithFlags(&evB, cudaEventDisableTiming);
    for (int l = 0; l < N_LAYERS; l++) {
        cudaEventCreateWithFlags(&evIn[l], cudaEventDisableTiming);
        cudaEventCreateWithFlags(&evAgg[l], cudaEventDisableTiming);
    }

    cudaEventRecord(evA, 0);
    cudaStreamWaitEvent(side, evA, 0);

    prep_emb_kernel<<<HID * 256 / 256, 256>>>(emb_W);                         // main #0
    prep_w_kernel<<<(N_LAYERS * HID * 64 + 255) / 256, 256>>>(W1, W2);        // main #1
    zero_deg_kernel<<<(N_NODES + 255) / 256, 256, 0, side>>>();               // side
    emb_gemm_kernel<<<N_TILES, 512, emb_smem>>>(features, emb_b, N_NODES);    // main <- profiled
    hist_kernel<<<(N_EDGES + 255) / 256, 256, 0, side>>>(dst);
    scan1_kernel<<<NB_SCAN, 1024, 0, side>>>();
    scan23_kernel<<<NB_SCAN, 1024, 0, side>>>();
    scatter_kernel<<<(N_EDGES + 255) / 256, 256, 0, side>>>(src, dst, edge_w);

    cudaEventRecord(evB, side);
    cudaStreamWaitEvent(0, evB, 0);

    // per layer: agg(half1) on side overlaps agg(half0)+mlp(half0) on main
    const int n_half0 = NODE_SPLIT;
    const int blk0 = (n_half0 * 32 + 255) / 256;
    const int blk1 = ((N_NODES - n_half0) * 32 + 255) / 256;

    const float* hin = d_h0;
    float* hout = d_h1;
    for (int l = 0; l < N_LAYERS; l++) {
        const uint32_t* w1h = d_W1h + (size_t)l * HID * 64;
        const uint32_t* w1l = d_W1l + (size_t)l * HID * 64;
        const uint32_t* w2h = d_W2h + (size_t)l * HID * 64;
        const uint32_t* w2l = d_W2l + (size_t)l * HID * 64;
        const float* bb1 = b1 + (size_t)l * HID;
        const float* bb2 = b2 + (size_t)l * HID;

        cudaEventRecord(evIn[l], 0);
        cudaStreamWaitEvent(side, evIn[l], 0);
        agg_kernel<<<blk1, 256, 0, side>>>(hin, n_half0, N_NODES);
        cudaEventRecord(evAgg[l], side);

        agg_kernel<<<blk0, 256>>>(hin, 0, n_half0);
        mlp_fused_kernel<<<148, 512, mlp_smem>>>(d_zz, hout, w1h, w1l, w2h, w2l,
                                                 bb1, bb2, N_NODES, 0, T_SPLIT);
        cudaStreamWaitEvent(0, evAgg[l], 0);
        mlp_fused_kernel<<<148, 512, mlp_smem>>>(d_zz, hout, w1h, w1l, w2h, w2l,
                                                 bb1, bb2, N_NODES, T_SPLIT, N_TILES);

        const float* t = hin; hin = hout; hout = (float*)t;
    }
    readout_kernel<<<N_TILES, 256, ro_smem>>>(hin, ro_W, ro_b, out, N_NODES);
}

// round 12
// speedup vs baseline: 1.1809x; 1.1809x over previous
#include <cuda_runtime.h>
#include <cuda_bf16.h>
#include <cstdint>

#define N_NODES 50000
#define N_EDGES 625000
#define IN_DIM  512
#define HID     128
#define OUT_DIM 40
#define N_LAYERS 3
#define NB_SCAN ((N_NODES + 1023) / 1024)
#define N_TILES ((N_NODES + 127) / 128)

// ---------------- scratch ---------------------------------------------------
__device__ float g_h[N_NODES * HID];
__device__ float g_z[N_NODES * HID];
__device__ int   g_deg[N_NODES];
__device__ int   g_off[N_NODES];
__device__ int   g_cur[N_NODES];
__device__ uint2 g_edge[N_EDGES];        // {src, w_bits}
__device__ int   g_bsum[64];
__device__ uint32_t g_eBh[HID * (IN_DIM / 2)];
__device__ uint32_t g_eBl[HID * (IN_DIM / 2)];
__device__ uint32_t g_W1h[N_LAYERS * HID * (HID / 2)];
__device__ uint32_t g_W1l[N_LAYERS * HID * (HID / 2)];
__device__ uint32_t g_W2h[N_LAYERS * HID * (HID / 2)];
__device__ uint32_t g_W2l[N_LAYERS * HID * (HID / 2)];

// ---------------- helpers ----------------------------------------------------
__device__ __forceinline__ uint32_t smem_u32(const void* p) {
    uint32_t a;
    asm("{ .reg .u64 t; cvta.to.shared.u64 t, %1; cvt.u32.u64 %0, t; }" : "=r"(a) : "l"(p));
    return a;
}
__device__ __forceinline__ void split2(float v0, float v1, uint32_t& hi, uint32_t& lo) {
    uint16_t h0, h1, l0, l1;
    asm("cvt.rn.bf16.f32 %0, %1;" : "=h"(h0) : "f"(v0));
    asm("cvt.rn.bf16.f32 %0, %1;" : "=h"(h1) : "f"(v1));
    float r0 = v0 - __uint_as_float((uint32_t)h0 << 16);
    float r1 = v1 - __uint_as_float((uint32_t)h1 << 16);
    asm("cvt.rn.bf16.f32 %0, %1;" : "=h"(l0) : "f"(r0));
    asm("cvt.rn.bf16.f32 %0, %1;" : "=h"(l1) : "f"(r1));
    hi = ((uint32_t)h1 << 16) | h0;
    lo = ((uint32_t)l1 << 16) | l0;
}
__device__ __forceinline__ void mma_bf16(float* c, uint32_t a0, uint32_t a1,
                                         uint32_t a2, uint32_t a3,
                                         uint32_t b0, uint32_t b1) {
    asm volatile("mma.sync.aligned.m16n8k16.row.col.f32.bf16.bf16.f32 "
                 "{%0,%1,%2,%3}, {%4,%5,%6,%7}, {%8,%9}, {%0,%1,%2,%3};"
                 : "+f"(c[0]), "+f"(c[1]), "+f"(c[2]), "+f"(c[3])
                 : "r"(a0), "r"(a1), "r"(a2), "r"(a3), "r"(b0), "r"(b1));
}
__device__ __forceinline__ void ldsm_x4(uint32_t& r0, uint32_t& r1, uint32_t& r2,
                                        uint32_t& r3, uint32_t addr) {
    asm volatile("ldmatrix.sync.aligned.m8n8.x4.shared.b16 {%0,%1,%2,%3}, [%4];"
                 : "=r"(r0), "=r"(r1), "=r"(r2), "=r"(r3) : "r"(addr));
}

// ---------------- CSR build -------------------------------------------------
__global__ void zero_deg_kernel() {
    int i = blockIdx.x * blockDim.x + threadIdx.x;
    if (i < N_NODES) g_deg[i] = 0;
}
__global__ void hist_kernel(const int* __restrict__ dst) {
    int e = blockIdx.x * blockDim.x + threadIdx.x;
    if (e < N_EDGES) atomicAdd(&g_deg[dst[e]], 1);
}
__global__ void scan1_kernel() {
    __shared__ int s[1024];
    int t = threadIdx.x;
    int i = blockIdx.x * 1024 + t;
    int v = (i < N_NODES) ? g_deg[i] : 0;
    s[t] = v;
    __syncthreads();
    for (int d = 1; d < 1024; d <<= 1) {
        int tmp = (t >= d) ? s[t - d] : 0;
        __syncthreads();
        s[t] += tmp;
        __syncthreads();
    }
    if (i < N_NODES) g_off[i] = s[t] - v;
    if (t == 1023) g_bsum[blockIdx.x] = s[1023];
}
__global__ void scan23_kernel() {
    __shared__ int red[64];
    __shared__ int base_s;
    int t = threadIdx.x;
    if (t < 64) red[t] = (t < NB_SCAN && t < (int)blockIdx.x) ? g_bsum[t] : 0;
    __syncthreads();
    if (t < 32) {
        int s = red[t] + red[t + 32];
        for (int d = 16; d > 0; d >>= 1) s += __shfl_down_sync(0xffffffffu, s, d);
        if (t == 0) base_s = s;
    }
    __syncthreads();
    int i = blockIdx.x * 1024 + t;
    if (i < N_NODES) {
        int o = g_off[i] + base_s;
        g_off[i] = o;
        g_cur[i] = o;
    }
}
__global__ void scatter_kernel(const int* __restrict__ src,
                               const int* __restrict__ dst,
                               const float* __restrict__ ew) {
    int e = blockIdx.x * blockDim.x + threadIdx.x;
    if (e < N_EDGES) {
        int d = dst[e];
        int pos = atomicAdd(&g_cur[d], 1);
        g_edge[pos] = make_uint2((uint32_t)src[e], __float_as_uint(ew[e]));
    }
}

// ---------------- weight prep ------------------------------------------------
__global__ void prep_emb_kernel(const float* __restrict__ W) {
    int idx = blockIdx.x * blockDim.x + threadIdx.x;
    int n = idx >> 8, k2 = idx & 255;
    uint32_t hi, lo;
    split2(W[(size_t)(2 * k2) * HID + n], W[(size_t)(2 * k2 + 1) * HID + n], hi, lo);
    g_eBh[n * 256 + k2] = hi;
    g_eBl[n * 256 + k2] = lo;
}
__global__ void prep_w_kernel(const float* __restrict__ W1, const float* __restrict__ W2) {
    int idx = blockIdx.x * blockDim.x + threadIdx.x;
    if (idx >= N_LAYERS * HID * 64) return;
    int l = idx / (HID * 64);
    int rem = idx - l * HID * 64;
    int n = rem >> 6, k2 = rem & 63;
    const float* w1 = W1 + (size_t)l * HID * HID;
    const float* w2 = W2 + (size_t)l * HID * HID;
    uint32_t hi, lo;
    split2(w1[(2 * k2) * HID + n], w1[(2 * k2 + 1) * HID + n], hi, lo);
    g_W1h[idx] = hi; g_W1l[idx] = lo;
    split2(w2[(2 * k2) * HID + n], w2[(2 * k2 + 1) * HID + n], hi, lo);
    g_W2h[idx] = hi; g_W2l[idx] = lo;
}

// ---------- emb GEMM v2: 256 thr, 128x64 tile, 2 CTAs/SM ---------------------
// grid (N_TILES, 2). 8 warps of 16x64 (wm = wid, wn via blockIdx.y).
#define ST 36
__global__ void __launch_bounds__(256, 2)
emb_gemm_kernel(const float* __restrict__ A, const float* __restrict__ bias, int M) {
    extern __shared__ uint32_t sh[];
    uint32_t* Ah = sh;                    // [128][ST]
    uint32_t* Al = sh + 128 * ST;
    uint32_t* Bh = sh + 2 * 128 * ST;     // [64][ST]
    uint32_t* Bl = sh + 2 * 128 * ST + 64 * ST;

    const int tid = threadIdx.x, lane = tid & 31, wid = tid >> 5;
    const int g = lane >> 2, tg = lane & 3;
    const int wm = wid;                   // 8 warps in m
    const int row0 = blockIdx.x * 128;
    const int col0 = blockIdx.y * 64;

    const int lr = lane & 7, lo8 = (lane >> 3) & 1, hi16 = (lane >> 4) & 1;
    const uint32_t AhB = smem_u32(Ah), AlB = smem_u32(Al);
    const uint32_t BhB = smem_u32(Bh), BlB = smem_u32(Bl);
    const int aRowOff = (wm * 16 + lr + 8 * lo8) * ST + 4 * hi16;   // words
    const int bRowOff = (lr + 8 * hi16) * ST + 4 * lo8;             // words

    float4 aR[8];
    uint4  bRh[2], bRl[2];

    // prologue: load chunk 0 into registers
#pragma unroll
    for (int it = 0; it < 8; it++) {
        int e = tid + it * 256;               // 2048 float4 slots (128 rows x 16)
        int m = e >> 4, j = e & 15;
        int r = row0 + m;
        aR[it] = make_float4(0.f, 0.f, 0.f, 0.f);
        if (r < M) aR[it] = *(const float4*)(A + (size_t)r * IN_DIM + j * 4);
    }
#pragma unroll
    for (int it = 0; it < 2; it++) {
        int e = tid + it * 256;               // 512 uint4 slots (64 rows x 8)
        int n = e >> 3, q = e & 7;
        bRh[it] = *(const uint4*)(g_eBh + (col0 + n) * 256 + q * 4);
        bRl[it] = *(const uint4*)(g_eBl + (col0 + n) * 256 + q * 4);
    }

    float c[8][4];
#pragma unroll
    for (int ni = 0; ni < 8; ni++)
#pragma unroll
        for (int q = 0; q < 4; q++) c[ni][q] = 0.f;

    const int NCH = IN_DIM / 64;
    for (int ci = 0; ci < NCH; ci++) {
        // store staged registers to smem
#pragma unroll
        for (int it = 0; it < 8; it++) {
            int e = tid + it * 256;
            int m = e >> 4, j = e & 15;
            uint32_t h0, l0, h1, l1;
            split2(aR[it].x, aR[it].y, h0, l0);
            split2(aR[it].z, aR[it].w, h1, l1);
            int o = m * ST + j * 2;
            Ah[o] = h0; Ah[o + 1] = h1;
            Al[o] = l0; Al[o + 1] = l1;
        }
#pragma unroll
        for (int it = 0; it < 2; it++) {
            int e = tid + it * 256;
            int n = e >> 3, q = e & 7;
            int o = n * ST + q * 4;
            *(uint4*)(Bh + o) = bRh[it];
            *(uint4*)(Bl + o) = bRl[it];
        }
        __syncthreads();

        // prefetch next chunk (LDGs overlap MMA below)
        if (ci + 1 < NCH) {
            int kn = (ci + 1) * 64, kn2 = kn >> 1;
#pragma unroll
            for (int it = 0; it < 8; it++) {
                int e = tid + it * 256;
                int m = e >> 4, j = e & 15;
                int r = row0 + m;
                aR[it] = make_float4(0.f, 0.f, 0.f, 0.f);
                if (r < M) aR[it] = *(const float4*)(A + (size_t)r * IN_DIM + kn + j * 4);
            }
#pragma unroll
            for (int it = 0; it < 2; it++) {
                int e = tid + it * 256;
                int n = e >> 3, q = e & 7;
                bRh[it] = *(const uint4*)(g_eBh + (col0 + n) * 256 + kn2 + q * 4);
                bRl[it] = *(const uint4*)(g_eBl + (col0 + n) * 256 + kn2 + q * 4);
            }
        }

#pragma unroll
        for (int ks2 = 0; ks2 < 32; ks2 += 8) {
            uint32_t a0, a1, a2, a3, l0, l1, l2, l3;
            ldsm_x4(a0, a1, a2, a3, AhB + (uint32_t)(aRowOff + ks2) * 4u);
            ldsm_x4(l0, l1, l2, l3, AlB + (uint32_t)(aRowOff + ks2) * 4u);
            uint32_t bh[8][2], bl[8][2];
#pragma unroll
            for (int q = 0; q < 4; q++) {
                uint32_t r0, r1, r2, r3;
                ldsm_x4(r0, r1, r2, r3, BhB + (uint32_t)(bRowOff + q * 16 * ST + ks2) * 4u);
                bh[2 * q][0] = r0; bh[2 * q][1] = r1;
                bh[2 * q + 1][0] = r2; bh[2 * q + 1][1] = r3;
                ldsm_x4(r0, r1, r2, r3, BlB + (uint32_t)(bRowOff + q * 16 * ST + ks2) * 4u);
                bl[2 * q][0] = r0; bl[2 * q][1] = r1;
                bl[2 * q + 1][0] = r2; bl[2 * q + 1][1] = r3;
            }
#pragma unroll
            for (int ni = 0; ni < 8; ni++) {
                mma_bf16(c[ni], a0, a1, a2, a3, bh[ni][0], bh[ni][1]);
                mma_bf16(c[ni], a0, a1, a2, a3, bl[ni][0], bl[ni][1]);
                mma_bf16(c[ni], l0, l1, l2, l3, bh[ni][0], bh[ni][1]);
            }
        }
        __syncthreads();
    }

#pragma unroll
    for (int half = 0; half < 2; half++) {
        int row = row0 + wm * 16 + g + half * 8;
        if (row >= M) continue;
#pragma unroll
        for (int ni = 0; ni < 8; ni++) {
            int col = col0 + ni * 8 + tg * 2;
            float2 o;
            o.x = c[ni][half * 2 + 0] + bias[col];
            o.y = c[ni][half * 2 + 1] + bias[col + 1];
            *(float2*)(g_h + (size_t)row * HID + col) = o;
        }
    }
}

// ---------------- aggregation: z = h + sum_{u->i} w * h[u] -----------------
__global__ void agg_kernel() {
    int node = (blockIdx.x * blockDim.x + threadIdx.x) >> 5;
    int lane = threadIdx.x & 31;
    if (node >= N_NODES) return;
    int s = g_off[node];
    int d = g_deg[node];
    float4 acc = *(const float4*)(g_h + (size_t)node * HID + lane * 4);
    int i = 0;
    for (; i + 2 <= d; i += 2) {
        uint2 e0 = g_edge[s + i];
        uint2 e1 = g_edge[s + i + 1];
        float w0 = __uint_as_float(e0.y);
        float w1 = __uint_as_float(e1.y);
        float4 h0 = *(const float4*)(g_h + (size_t)e0.x * HID + lane * 4);
        float4 h1 = *(const float4*)(g_h + (size_t)e1.x * HID + lane * 4);
        acc.x += w0 * h0.x + w1 * h1.x;
        acc.y += w0 * h0.y + w1 * h1.y;
        acc.z += w0 * h0.z + w1 * h1.z;
        acc.w += w0 * h0.w + w1 * h1.w;
    }
    if (i < d) {
        uint2 e0 = g_edge[s + i];
        float w0 = __uint_as_float(e0.y);
        float4 h0 = *(const float4*)(g_h + (size_t)e0.x * HID + lane * 4);
        acc.x += w0 * h0.x; acc.y += w0 * h0.y;
        acc.z += w0 * h0.z; acc.w += w0 * h0.w;
    }
    *(float4*)(g_z + (size_t)node * HID + lane * 4) = acc;
}

// ---------------- persistent fused MLP (R9 version) --------------------------
#define ST2 68
__global__ void __launch_bounds__(512, 1)
mlp_fused_kernel(const uint32_t* __restrict__ W1h, const uint32_t* __restrict__ W1l,
                 const uint32_t* __restrict__ W2h, const uint32_t* __restrict__ W2l,
                 const float* __restrict__ b1, const float* __restrict__ b2, int M) {
    extern __shared__ uint32_t sh[];
    uint32_t* Ah  = sh;
    uint32_t* Al  = sh + 128 * ST2;
    uint32_t* Wh1 = sh + 2 * 128 * ST2;
    uint32_t* Wl1 = sh + 3 * 128 * ST2;
    uint32_t* Wh2 = sh + 4 * 128 * ST2;
    uint32_t* Wl2 = sh + 5 * 128 * ST2;

    const int tid = threadIdx.x, lane = tid & 31, wid = tid >> 5;
    const int g = lane >> 2, tg = lane & 3;
    const int wm = wid & 7, wn = wid >> 3;

    const int lr = lane & 7, lo8 = (lane >> 3) & 1, hi16 = (lane >> 4) & 1;
    const uint32_t AhB  = smem_u32(Ah),  AlB  = smem_u32(Al);
    const uint32_t Wh1B = smem_u32(Wh1), Wl1B = smem_u32(Wl1);
    const uint32_t Wh2B = smem_u32(Wh2), Wl2B = smem_u32(Wl2);
    const int aRowOff = (wm * 16 + lr + 8 * lo8) * ST2 + 4 * hi16;
    const int bRowOff = (wn * 64 + lr + 8 * hi16) * ST2 + 4 * lo8;

#pragma unroll
    for (int it = 0; it < 4; it++) {
        int e = tid + it * 512;
        int n = e >> 4, q = e & 15;
        int o = n * ST2 + q * 4;
        *(uint4*)(Wh1 + o) = *(const uint4*)(W1h + n * 64 + q * 4);
        *(uint4*)(Wl1 + o) = *(const uint4*)(W1l + n * 64 + q * 4);
        *(uint4*)(Wh2 + o) = *(const uint4*)(W2h + n * 64 + q * 4);
        *(uint4*)(Wl2 + o) = *(const uint4*)(W2l + n * 64 + q * 4);
    }

    for (int tile = blockIdx.x; tile < N_TILES; tile += gridDim.x) {
        const int row0 = tile * 128;
        __syncthreads();
#pragma unroll
        for (int it = 0; it < 8; it++) {
            int e = tid + it * 512;
            int m = e >> 5, j = e & 31;
            int r = row0 + m;
            float4 v = make_float4(0.f, 0.f, 0.f, 0.f);
            if (r < M) v = *(const float4*)(g_z + (size_t)r * HID + j * 4);
            uint32_t h0, l0, h1, l1;
            split2(v.x, v.y, h0, l0);
            split2(v.z, v.w, h1, l1);
            int o = m * ST2 + j * 2;
            Ah[o] = h0; Ah[o + 1] = h1;
            Al[o] = l0; Al[o + 1] = l1;
        }
        __syncthreads();

        float c[8][4];
#pragma unroll
        for (int ni = 0; ni < 8; ni++)
#pragma unroll
            for (int q = 0; q < 4; q++) c[ni][q] = 0.f;

        // GEMM1
#pragma unroll
        for (int ks2 = 0; ks2 < 64; ks2 += 8) {
            uint32_t a0, a1, a2, a3, l0, l1, l2, l3;
            ldsm_x4(a0, a1, a2, a3, AhB + (uint32_t)(aRowOff + ks2) * 4u);
            ldsm_x4(l0, l1, l2, l3, AlB + (uint32_t)(aRowOff + ks2) * 4u);
            uint32_t bh[8][2], bl[8][2];
#pragma unroll
            for (int q = 0; q < 4; q++) {
                uint32_t r0, r1, r2, r3;
                ldsm_x4(r0, r1, r2, r3, Wh1B + (uint32_t)(bRowOff + q * 16 * ST2 + ks2) * 4u);
                bh[2 * q][0] = r0; bh[2 * q][1] = r1;
                bh[2 * q + 1][0] = r2; bh[2 * q + 1][1] = r3;
                ldsm_x4(r0, r1, r2, r3, Wl1B + (uint32_t)(bRowOff + q * 16 * ST2 + ks2) * 4u);
                bl[2 * q][0] = r0; bl[2 * q][1] = r1;
                bl[2 * q + 1][0] = r2; bl[2 * q + 1][1] = r3;
            }
#pragma unroll
            for (int ni = 0; ni < 8; ni++) {
                mma_bf16(c[ni], a0, a1, a2, a3, bh[ni][0], bh[ni][1]);
                mma_bf16(c[ni], a0, a1, a2, a3, bl[ni][0], bl[ni][1]);
                mma_bf16(c[ni], l0, l1, l2, l3, bh[ni][0], bh[ni][1]);
            }
        }
        __syncthreads();

        // relu(c + b1) -> split -> Ah/Al
#pragma unroll
        for (int ni = 0; ni < 8; ni++) {
            int col = wn * 64 + ni * 8 + tg * 2;
            float bb0 = b1[col], bb1 = b1[col + 1];
            int k2 = wn * 32 + ni * 4 + tg;
            int r0 = wm * 16 + g;
            uint32_t hi, lo;
            split2(fmaxf(c[ni][0] + bb0, 0.f), fmaxf(c[ni][1] + bb1, 0.f), hi, lo);
            Ah[r0 * ST2 + k2] = hi; Al[r0 * ST2 + k2] = lo;
            split2(fmaxf(c[ni][2] + bb0, 0.f), fmaxf(c[ni][3] + bb1, 0.f), hi, lo);
            Ah[(r0 + 8) * ST2 + k2] = hi; Al[(r0 + 8) * ST2 + k2] = lo;
        }
        __syncthreads();

#pragma unroll
        for (int ni = 0; ni < 8; ni++)
#pragma unroll
            for (int q = 0; q < 4; q++) c[ni][q] = 0.f;

        // GEMM2
#pragma unroll
        for (int ks2 = 0; ks2 < 64; ks2 += 8) {
            uint32_t a0, a1, a2, a3, l0, l1, l2, l3;
            ldsm_x4(a0, a1, a2, a3, AhB + (uint32_t)(aRowOff + ks2) * 4u);
            ldsm_x4(l0, l1, l2, l3, AlB + (uint32_t)(aRowOff + ks2) * 4u);
            uint32_t bh[8][2], bl[8][2];
#pragma unroll
            for (int q = 0; q < 4; q++) {
                uint32_t r0, r1, r2, r3;
                ldsm_x4(r0, r1, r2, r3, Wh2B + (uint32_t)(bRowOff + q * 16 * ST2 + ks2) * 4u);
                bh[2 * q][0] = r0; bh[2 * q][1] = r1;
                bh[2 * q + 1][0] = r2; bh[2 * q + 1][1] = r3;
                ldsm_x4(r0, r1, r2, r3, Wl2B + (uint32_t)(bRowOff + q * 16 * ST2 + ks2) * 4u);
                bl[2 * q][0] = r0; bl[2 * q][1] = r1;
                bl[2 * q + 1][0] = r2; bl[2 * q + 1][1] = r3;
            }
#pragma unroll
            for (int ni = 0; ni < 8; ni++) {
                mma_bf16(c[ni], a0, a1, a2, a3, bh[ni][0], bh[ni][1]);
                mma_bf16(c[ni], a0, a1, a2, a3, bl[ni][0], bl[ni][1]);
                mma_bf16(c[ni], l0, l1, l2, l3, bh[ni][0], bh[ni][1]);
            }
        }

#pragma unroll
        for (int half = 0; half < 2; half++) {
            int row = row0 + wm * 16 + g + half * 8;
            if (row >= M) continue;
#pragma unroll
            for (int ni = 0; ni < 8; ni++) {
                int col = wn * 64 + ni * 8 + tg * 2;
                float2 o;
                o.x = fmaxf(c[ni][half * 2 + 0] + b2[col], 0.f);
                o.y = fmaxf(c[ni][half * 2 + 1] + b2[col + 1], 0.f);
                *(float2*)(g_h + (size_t)row * HID + col) = o;
            }
        }
    }
}

// ---------------- readout ----------------------------------------------------
__global__ void readout_kernel(const float* __restrict__ Wr,
                               const float* __restrict__ br,
                               float* __restrict__ out, int M) {
    extern __shared__ float sm[];
    float* hs = sm;
    float* wt = sm + 128 * 132;
    const int row0 = blockIdx.x * 128;
    const int tr = threadIdx.x >> 3;
    const int cg = threadIdx.x & 7;

    for (int e = threadIdx.x; e < 128 * 128; e += 256) {
        int m = e >> 7, k = e & 127;
        int r = row0 + m;
        hs[m * 132 + k] = (r < M) ? g_h[(size_t)r * HID + k] : 0.f;
    }
    for (int e = threadIdx.x; e < 128 * OUT_DIM; e += 256) {
        int k = e / OUT_DIM, c = e % OUT_DIM;
        wt[c * 132 + k] = Wr[e];
    }
    __syncthreads();

    float acc[4][5];
#pragma unroll
    for (int r = 0; r < 4; r++)
#pragma unroll
        for (int c = 0; c < 5; c++) acc[r][c] = 0.f;

    for (int k = 0; k < 128; k += 4) {
        float4 hv[4];
#pragma unroll
        for (int r = 0; r < 4; r++)
            hv[r] = *(const float4*)(hs + (tr * 4 + r) * 132 + k);
#pragma unroll
        for (int c = 0; c < 5; c++) {
            float4 wv = *(const float4*)(wt + (cg * 5 + c) * 132 + k);
#pragma unroll
            for (int r = 0; r < 4; r++)
                acc[r][c] += hv[r].x * wv.x + hv[r].y * wv.y
                           + hv[r].z * wv.z + hv[r].w * wv.w;
        }
    }
#pragma unroll
    for (int r = 0; r < 4; r++) {
        int row = row0 + tr * 4 + r;
        if (row < M) {
#pragma unroll
            for (int c = 0; c < 5; c++) {
                int col = cg * 5 + c;
                out[(size_t)row * OUT_DIM + col] = acc[r][c] + br[col];
            }
        }
    }
}

// ---------------- launch ----------------------------------------------------
extern "C" void kernel_launch(void* const* d_in, const int* in_sizes, int n_in,
                              void* d_out, int out_size) {
    const float* features = (const float*)d_in[0];
    const int*   src      = (const int*)  d_in[1];
    const int*   dst      = (const int*)  d_in[2];
    const float* edge_w   = (const float*)d_in[3];
    const float* emb_W    = (const float*)d_in[4];
    const float* emb_b    = (const float*)d_in[5];
    const float* W1       = (const float*)d_in[6];
    const float* b1       = (const float*)d_in[7];
    const float* W2       = (const float*)d_in[8];
    const float* b2       = (const float*)d_in[9];
    const float* ro_W     = (const float*)d_in[10];
    const float* ro_b     = (const float*)d_in[11];
    float* out = (float*)d_out;

    const int emb_smem = (2 * 128 * ST + 2 * 64 * ST) * (int)sizeof(uint32_t);  // 55296
    const int mlp_smem = 6 * 128 * ST2 * (int)sizeof(uint32_t);                 // 208896
    const int ro_smem  = (128 * 132 + OUT_DIM * 132) * (int)sizeof(float);
    cudaFuncSetAttribute(emb_gemm_kernel,  cudaFuncAttributeMaxDynamicSharedMemorySize, emb_smem);
    cudaFuncSetAttribute(mlp_fused_kernel, cudaFuncAttributeMaxDynamicSharedMemorySize, mlp_smem);
    cudaFuncSetAttribute(readout_kernel,   cudaFuncAttributeMaxDynamicSharedMemorySize, ro_smem);

    uint32_t *d_W1h, *d_W1l, *d_W2h, *d_W2l;
    cudaGetSymbolAddress((void**)&d_W1h, g_W1h);
    cudaGetSymbolAddress((void**)&d_W1l, g_W1l);
    cudaGetSymbolAddress((void**)&d_W2h, g_W2h);
    cudaGetSymbolAddress((void**)&d_W2l, g_W2l);

    cudaStream_t side = cudaStreamPerThread;
    cudaEvent_t evA, evB;
    cudaEventCreateWithFlags(&evA, cudaEventDisableTiming);
    cudaEventCreateWithFlags(&evB, cudaEventDisableTiming);

    cudaEventRecord(evA, 0);
    cudaStreamWaitEvent(side, evA, 0);

    prep_emb_kernel<<<HID * 256 / 256, 256>>>(emb_W);                         // main
    prep_w_kernel<<<(N_LAYERS * HID * 64 + 255) / 256, 256>>>(W1, W2);        // main
    zero_deg_kernel<<<(N_NODES + 255) / 256, 256, 0, side>>>();               // side
    emb_gemm_kernel<<<dim3(N_TILES, 2), 256, emb_smem>>>(features, emb_b, N_NODES); // main <- profiled
    hist_kernel<<<(N_EDGES + 255) / 256, 256, 0, side>>>(dst);
    scan1_kernel<<<NB_SCAN, 1024, 0, side>>>();
    scan23_kernel<<<NB_SCAN, 1024, 0, side>>>();
    scatter_kernel<<<(N_EDGES + 255) / 256, 256, 0, side>>>(src, dst, edge_w);

    cudaEventRecord(evB, side);
    cudaStreamWaitEvent(0, evB, 0);

    const int agg_blocks = (N_NODES * 32 + 255) / 256;
    for (int l = 0; l < N_LAYERS; l++) {
        agg_kernel<<<agg_blocks, 256>>>();
        mlp_fused_kernel<<<148, 512, mlp_smem>>>(
            d_W1h + (size_t)l * HID * 64, d_W1l + (size_t)l * HID * 64,
            d_W2h + (size_t)l * HID * 64, d_W2l + (size_t)l * HID * 64,
            b1 + (size_t)l * HID, b2 + (size_t)l * HID, N_NODES);
    }
    readout_kernel<<<N_TILES, 256, ro_smem>>>(ro_W, ro_b, out, N_NODES);
}

// round 13
// speedup vs baseline: 1.3151x; 1.1136x over previous
#include <cuda_runtime.h>
#include <cuda_bf16.h>
#include <cstdint>

#define N_NODES 50000
#define N_EDGES 625000
#define IN_DIM  512
#define HID     128
#define OUT_DIM 40
#define N_LAYERS 3
#define NB_SCAN ((N_NODES + 1023) / 1024)
#define N_TILES ((N_NODES + 127) / 128)

// ---------------- scratch ---------------------------------------------------
__device__ float g_h[N_NODES * HID];
__device__ float g_z[N_NODES * HID];
__device__ int   g_deg[N_NODES];
__device__ int   g_off[N_NODES];
__device__ int   g_cur[N_NODES];
__device__ uint2 g_edge[N_EDGES];        // {src, w_bits}
__device__ int   g_bsum[64];
__device__ uint32_t g_eBh[HID * (IN_DIM / 2)];
__device__ uint32_t g_eBl[HID * (IN_DIM / 2)];
__device__ uint32_t g_W1h[N_LAYERS * HID * (HID / 2)];
__device__ uint32_t g_W1l[N_LAYERS * HID * (HID / 2)];
__device__ uint32_t g_W2h[N_LAYERS * HID * (HID / 2)];
__device__ uint32_t g_W2l[N_LAYERS * HID * (HID / 2)];
__device__ uint32_t g_roh[64 * 64];      // ro_W split/packed, [n(64 pad)][k2(64)]
__device__ uint32_t g_rol[64 * 64];

// ---------------- helpers ----------------------------------------------------
__device__ __forceinline__ uint32_t smem_u32(const void* p) {
    uint32_t a;
    asm("{ .reg .u64 t; cvta.to.shared.u64 t, %1; cvt.u32.u64 %0, t; }" : "=r"(a) : "l"(p));
    return a;
}
__device__ __forceinline__ void split2(float v0, float v1, uint32_t& hi, uint32_t& lo) {
    uint16_t h0, h1, l0, l1;
    asm("cvt.rn.bf16.f32 %0, %1;" : "=h"(h0) : "f"(v0));
    asm("cvt.rn.bf16.f32 %0, %1;" : "=h"(h1) : "f"(v1));
    float r0 = v0 - __uint_as_float((uint32_t)h0 << 16);
    float r1 = v1 - __uint_as_float((uint32_t)h1 << 16);
    asm("cvt.rn.bf16.f32 %0, %1;" : "=h"(l0) : "f"(r0));
    asm("cvt.rn.bf16.f32 %0, %1;" : "=h"(l1) : "f"(r1));
    hi = ((uint32_t)h1 << 16) | h0;
    lo = ((uint32_t)l1 << 16) | l0;
}
__device__ __forceinline__ void mma_bf16(float* c, uint32_t a0, uint32_t a1,
                                         uint32_t a2, uint32_t a3,
                                         uint32_t b0, uint32_t b1) {
    asm volatile("mma.sync.aligned.m16n8k16.row.col.f32.bf16.bf16.f32 "
                 "{%0,%1,%2,%3}, {%4,%5,%6,%7}, {%8,%9}, {%0,%1,%2,%3};"
                 : "+f"(c[0]), "+f"(c[1]), "+f"(c[2]), "+f"(c[3])
                 : "r"(a0), "r"(a1), "r"(a2), "r"(a3), "r"(b0), "r"(b1));
}
__device__ __forceinline__ void ldsm_x4(uint32_t& r0, uint32_t& r1, uint32_t& r2,
                                        uint32_t& r3, uint32_t addr) {
    asm volatile("ldmatrix.sync.aligned.m8n8.x4.shared.b16 {%0,%1,%2,%3}, [%4];"
                 : "=r"(r0), "=r"(r1), "=r"(r2), "=r"(r3) : "r"(addr));
}

// ---------------- CSR build -------------------------------------------------
__global__ void zero_deg_kernel() {
    int i = blockIdx.x * blockDim.x + threadIdx.x;
    if (i < N_NODES) g_deg[i] = 0;
}
__global__ void hist_kernel(const int* __restrict__ dst) {
    int e = blockIdx.x * blockDim.x + threadIdx.x;
    if (e < N_EDGES) atomicAdd(&g_deg[dst[e]], 1);
}
__global__ void scan1_kernel() {
    __shared__ int s[1024];
    int t = threadIdx.x;
    int i = blockIdx.x * 1024 + t;
    int v = (i < N_NODES) ? g_deg[i] : 0;
    s[t] = v;
    __syncthreads();
    for (int d = 1; d < 1024; d <<= 1) {
        int tmp = (t >= d) ? s[t - d] : 0;
        __syncthreads();
        s[t] += tmp;
        __syncthreads();
    }
    if (i < N_NODES) g_off[i] = s[t] - v;
    if (t == 1023) g_bsum[blockIdx.x] = s[1023];
}
__global__ void scan23_kernel() {
    __shared__ int red[64];
    __shared__ int base_s;
    int t = threadIdx.x;
    if (t < 64) red[t] = (t < NB_SCAN && t < (int)blockIdx.x) ? g_bsum[t] : 0;
    __syncthreads();
    if (t < 32) {
        int s = red[t] + red[t + 32];
        for (int d = 16; d > 0; d >>= 1) s += __shfl_down_sync(0xffffffffu, s, d);
        if (t == 0) base_s = s;
    }
    __syncthreads();
    int i = blockIdx.x * 1024 + t;
    if (i < N_NODES) {
        int o = g_off[i] + base_s;
        g_off[i] = o;
        g_cur[i] = o;
    }
}
__global__ void scatter_kernel(const int* __restrict__ src,
                               const int* __restrict__ dst,
                               const float* __restrict__ ew) {
    int e = blockIdx.x * blockDim.x + threadIdx.x;
    if (e < N_EDGES) {
        int d = dst[e];
        int pos = atomicAdd(&g_cur[d], 1);
        g_edge[pos] = make_uint2((uint32_t)src[e], __float_as_uint(ew[e]));
    }
}

// ---------------- weight prep ------------------------------------------------
__global__ void prep_emb_kernel(const float* __restrict__ W) {
    int idx = blockIdx.x * blockDim.x + threadIdx.x;
    int n = idx >> 8, k2 = idx & 255;
    uint32_t hi, lo;
    split2(W[(size_t)(2 * k2) * HID + n], W[(size_t)(2 * k2 + 1) * HID + n], hi, lo);
    g_eBh[n * 256 + k2] = hi;
    g_eBl[n * 256 + k2] = lo;
}
__global__ void prep_w_kernel(const float* __restrict__ W1, const float* __restrict__ W2) {
    int idx = blockIdx.x * blockDim.x + threadIdx.x;
    if (idx >= N_LAYERS * HID * 64) return;
    int l = idx / (HID * 64);
    int rem = idx - l * HID * 64;
    int n = rem >> 6, k2 = rem & 63;
    const float* w1 = W1 + (size_t)l * HID * HID;
    const float* w2 = W2 + (size_t)l * HID * HID;
    uint32_t hi, lo;
    split2(w1[(2 * k2) * HID + n], w1[(2 * k2 + 1) * HID + n], hi, lo);
    g_W1h[idx] = hi; g_W1l[idx] = lo;
    split2(w2[(2 * k2) * HID + n], w2[(2 * k2 + 1) * HID + n], hi, lo);
    g_W2h[idx] = hi; g_W2l[idx] = lo;
}
__global__ void prep_ro_kernel(const float* __restrict__ Wr) {   // [128][40]
    int idx = blockIdx.x * blockDim.x + threadIdx.x;             // 64*64
    if (idx >= 64 * 64) return;
    int n = idx >> 6, k2 = idx & 63;
    uint32_t hi = 0, lo = 0;
    if (n < OUT_DIM)
        split2(Wr[(2 * k2) * OUT_DIM + n], Wr[(2 * k2 + 1) * OUT_DIM + n], hi, lo);
    g_roh[idx] = hi;
    g_rol[idx] = lo;
}

// ---------------- emb GEMM: double-buffered k-loop (R9) ---------------------
#define ST 36
#define CHW (128 * ST)
#define BUFW (4 * CHW)
__global__ void __launch_bounds__(512, 1)
emb_gemm_kernel(const float* __restrict__ A, const float* __restrict__ bias, int M) {
    extern __shared__ uint32_t sh[];

    const int tid = threadIdx.x, lane = tid & 31, wid = tid >> 5;
    const int g = lane >> 2, tg = lane & 3;
    const int wm = wid & 7, wn = wid >> 3;
    const int row0 = blockIdx.x * 128;

    const int lr = lane & 7, lo8 = (lane >> 3) & 1, hi16 = (lane >> 4) & 1;
    const uint32_t shB = smem_u32(sh);
    const int aRowOff = (wm * 16 + lr + 8 * lo8) * ST + 4 * hi16;
    const int bRowOff = (wn * 64 + lr + 8 * hi16) * ST + 4 * lo8;

    float4 aR[4];
    uint4  bRh[2], bRl[2];

#pragma unroll
    for (int it = 0; it < 4; it++) {
        int e = tid + it * 512;
        int m = e >> 4, j = e & 15;
        int r = row0 + m;
        aR[it] = make_float4(0.f, 0.f, 0.f, 0.f);
        if (r < M) aR[it] = *(const float4*)(A + (size_t)r * IN_DIM + j * 4);
    }
#pragma unroll
    for (int it = 0; it < 2; it++) {
        int e = tid + it * 512;
        int n = e >> 3, q = e & 7;
        bRh[it] = *(const uint4*)(g_eBh + n * 256 + q * 4);
        bRl[it] = *(const uint4*)(g_eBl + n * 256 + q * 4);
    }
    {
        uint32_t* Ah = sh;            uint32_t* Al = sh + CHW;
        uint32_t* Bh = sh + 2 * CHW;  uint32_t* Bl = sh + 3 * CHW;
#pragma unroll
        for (int it = 0; it < 4; it++) {
            int e = tid + it * 512;
            int m = e >> 4, j = e & 15;
            uint32_t h0, l0, h1, l1;
            split2(aR[it].x, aR[it].y, h0, l0);
            split2(aR[it].z, aR[it].w, h1, l1);
            int o = m * ST + j * 2;
            Ah[o] = h0; Ah[o + 1] = h1;
            Al[o] = l0; Al[o + 1] = l1;
        }
#pragma unroll
        for (int it = 0; it < 2; it++) {
            int e = tid + it * 512;
            int n = e >> 3, q = e & 7;
            int o = n * ST + q * 4;
            *(uint4*)(Bh + o) = bRh[it];
            *(uint4*)(Bl + o) = bRl[it];
        }
    }
    __syncthreads();

    float c[8][4];
#pragma unroll
    for (int ni = 0; ni < 8; ni++)
#pragma unroll
        for (int q = 0; q < 4; q++) c[ni][q] = 0.f;

    const int NCH = IN_DIM / 64;
    for (int ci = 0; ci < NCH; ci++) {
        const int p = ci & 1;
        const uint32_t base = shB + (uint32_t)p * BUFW * 4u;
        const uint32_t AhB = base, AlB = base + CHW * 4u;
        const uint32_t BhB = base + 2u * CHW * 4u, BlB = base + 3u * CHW * 4u;

        if (ci + 1 < NCH) {
            int kn = (ci + 1) * 64, kn2 = kn >> 1;
#pragma unroll
            for (int it = 0; it < 4; it++) {
                int e = tid + it * 512;
                int m = e >> 4, j = e & 15;
                int r = row0 + m;
                aR[it] = make_float4(0.f, 0.f, 0.f, 0.f);
                if (r < M) aR[it] = *(const float4*)(A + (size_t)r * IN_DIM + kn + j * 4);
            }
#pragma unroll
            for (int it = 0; it < 2; it++) {
                int e = tid + it * 512;
                int n = e >> 3, q = e & 7;
                bRh[it] = *(const uint4*)(g_eBh + n * 256 + kn2 + q * 4);
                bRl[it] = *(const uint4*)(g_eBl + n * 256 + kn2 + q * 4);
            }
        }

#pragma unroll
        for (int ks2 = 0; ks2 < 32; ks2 += 8) {
            uint32_t a0, a1, a2, a3, l0, l1, l2, l3;
            ldsm_x4(a0, a1, a2, a3, AhB + (uint32_t)(aRowOff + ks2) * 4u);
            ldsm_x4(l0, l1, l2, l3, AlB + (uint32_t)(aRowOff + ks2) * 4u);
            uint32_t bh[8][2], bl[8][2];
#pragma unroll
            for (int q = 0; q < 4; q++) {
                uint32_t r0, r1, r2, r3;
                ldsm_x4(r0, r1, r2, r3, BhB + (uint32_t)(bRowOff + q * 16 * ST + ks2) * 4u);
                bh[2 * q][0] = r0; bh[2 * q][1] = r1;
                bh[2 * q + 1][0] = r2; bh[2 * q + 1][1] = r3;
                ldsm_x4(r0, r1, r2, r3, BlB + (uint32_t)(bRowOff + q * 16 * ST + ks2) * 4u);
                bl[2 * q][0] = r0; bl[2 * q][1] = r1;
                bl[2 * q + 1][0] = r2; bl[2 * q + 1][1] = r3;
            }
#pragma unroll
            for (int ni = 0; ni < 8; ni++) {
                mma_bf16(c[ni], a0, a1, a2, a3, bh[ni][0], bh[ni][1]);
                mma_bf16(c[ni], a0, a1, a2, a3, bl[ni][0], bl[ni][1]);
                mma_bf16(c[ni], l0, l1, l2, l3, bh[ni][0], bh[ni][1]);
            }
        }

        if (ci + 1 < NCH) {
            uint32_t* Ah = sh + (p ^ 1) * BUFW;
            uint32_t* Al = Ah + CHW;
            uint32_t* Bh = Ah + 2 * CHW;
            uint32_t* Bl = Ah + 3 * CHW;
#pragma unroll
            for (int it = 0; it < 4; it++) {
                int e = tid + it * 512;
                int m = e >> 4, j = e & 15;
                uint32_t h0, l0, h1, l1;
                split2(aR[it].x, aR[it].y, h0, l0);
                split2(aR[it].z, aR[it].w, h1, l1);
                int o = m * ST + j * 2;
                Ah[o] = h0; Ah[o + 1] = h1;
                Al[o] = l0; Al[o + 1] = l1;
            }
#pragma unroll
            for (int it = 0; it < 2; it++) {
                int e = tid + it * 512;
                int n = e >> 3, q = e & 7;
                int o = n * ST + q * 4;
                *(uint4*)(Bh + o) = bRh[it];
                *(uint4*)(Bl + o) = bRl[it];
            }
            __syncthreads();
        }
    }

#pragma unroll
    for (int half = 0; half < 2; half++) {
        int row = row0 + wm * 16 + g + half * 8;
        if (row >= M) continue;
#pragma unroll
        for (int ni = 0; ni < 8; ni++) {
            int col = wn * 64 + ni * 8 + tg * 2;
            float2 o;
            o.x = c[ni][half * 2 + 0] + bias[col];
            o.y = c[ni][half * 2 + 1] + bias[col + 1];
            *(float2*)(g_h + (size_t)row * HID + col) = o;
        }
    }
}

// ---------------- aggregation ------------------------------------------------
__global__ void agg_kernel() {
    int node = (blockIdx.x * blockDim.x + threadIdx.x) >> 5;
    int lane = threadIdx.x & 31;
    if (node >= N_NODES) return;
    int s = g_off[node];
    int d = g_deg[node];
    float4 acc = *(const float4*)(g_h + (size_t)node * HID + lane * 4);
    int i = 0;
    for (; i + 2 <= d; i += 2) {
        uint2 e0 = g_edge[s + i];
        uint2 e1 = g_edge[s + i + 1];
        float w0 = __uint_as_float(e0.y);
        float w1 = __uint_as_float(e1.y);
        float4 h0 = *(const float4*)(g_h + (size_t)e0.x * HID + lane * 4);
        float4 h1 = *(const float4*)(g_h + (size_t)e1.x * HID + lane * 4);
        acc.x += w0 * h0.x + w1 * h1.x;
        acc.y += w0 * h0.y + w1 * h1.y;
        acc.z += w0 * h0.z + w1 * h1.z;
        acc.w += w0 * h0.w + w1 * h1.w;
    }
    if (i < d) {
        uint2 e0 = g_edge[s + i];
        float w0 = __uint_as_float(e0.y);
        float4 h0 = *(const float4*)(g_h + (size_t)e0.x * HID + lane * 4);
        acc.x += w0 * h0.x; acc.y += w0 * h0.y;
        acc.z += w0 * h0.z; acc.w += w0 * h0.w;
    }
    *(float4*)(g_z + (size_t)node * HID + lane * 4) = acc;
}

// ---------------- persistent fused MLP with cross-tile z prefetch -----------
#define ST2 68
__global__ void __launch_bounds__(512, 1)
mlp_fused_kernel(const uint32_t* __restrict__ W1h, const uint32_t* __restrict__ W1l,
                 const uint32_t* __restrict__ W2h, const uint32_t* __restrict__ W2l,
                 const float* __restrict__ b1, const float* __restrict__ b2, int M) {
    extern __shared__ uint32_t sh[];
    uint32_t* Ah  = sh;
    uint32_t* Al  = sh + 128 * ST2;
    uint32_t* Wh1 = sh + 2 * 128 * ST2;
    uint32_t* Wl1 = sh + 3 * 128 * ST2;
    uint32_t* Wh2 = sh + 4 * 128 * ST2;
    uint32_t* Wl2 = sh + 5 * 128 * ST2;

    const int tid = threadIdx.x, lane = tid & 31, wid = tid >> 5;
    const int g = lane >> 2, tg = lane & 3;
    const int wm = wid & 7, wn = wid >> 3;

    const int lr = lane & 7, lo8 = (lane >> 3) & 1, hi16 = (lane >> 4) & 1;
    const uint32_t AhB  = smem_u32(Ah),  AlB  = smem_u32(Al);
    const uint32_t Wh1B = smem_u32(Wh1), Wl1B = smem_u32(Wl1);
    const uint32_t Wh2B = smem_u32(Wh2), Wl2B = smem_u32(Wl2);
    const int aRowOff = (wm * 16 + lr + 8 * lo8) * ST2 + 4 * hi16;
    const int bRowOff = (wn * 64 + lr + 8 * hi16) * ST2 + 4 * lo8;

#pragma unroll
    for (int it = 0; it < 4; it++) {
        int e = tid + it * 512;
        int n = e >> 4, q = e & 15;
        int o = n * ST2 + q * 4;
        *(uint4*)(Wh1 + o) = *(const uint4*)(W1h + n * 64 + q * 4);
        *(uint4*)(Wl1 + o) = *(const uint4*)(W1l + n * 64 + q * 4);
        *(uint4*)(Wh2 + o) = *(const uint4*)(W2h + n * 64 + q * 4);
        *(uint4*)(Wl2 + o) = *(const uint4*)(W2l + n * 64 + q * 4);
    }

    // prefetch z for first tile
    float4 zR[8];
    {
        const int row0 = blockIdx.x * 128;
#pragma unroll
        for (int it = 0; it < 8; it++) {
            int e = tid + it * 512;
            int m = e >> 5, j = e & 31;
            int r = row0 + m;
            zR[it] = make_float4(0.f, 0.f, 0.f, 0.f);
            if (r < M) zR[it] = *(const float4*)(g_z + (size_t)r * HID + j * 4);
        }
    }

    for (int tile = blockIdx.x; tile < N_TILES; tile += gridDim.x) {
        const int row0 = tile * 128;
        __syncthreads();   // prev tile's GEMM2 done with Ah/Al; W staging visible

        // store prefetched z -> split -> Ah/Al
#pragma unroll
        for (int it = 0; it < 8; it++) {
            int e = tid + it * 512;
            int m = e >> 5, j = e & 31;
            uint32_t h0, l0, h1, l1;
            split2(zR[it].x, zR[it].y, h0, l0);
            split2(zR[it].z, zR[it].w, h1, l1);
            int o = m * ST2 + j * 2;
            Ah[o] = h0; Ah[o + 1] = h1;
            Al[o] = l0; Al[o + 1] = l1;
        }
        // issue next tile's z LDGs (latency hidden behind GEMM1+GEMM2)
        if (tile + (int)gridDim.x < N_TILES) {
            const int nrow0 = (tile + gridDim.x) * 128;
#pragma unroll
            for (int it = 0; it < 8; it++) {
                int e = tid + it * 512;
                int m = e >> 5, j = e & 31;
                int r = nrow0 + m;
                zR[it] = make_float4(0.f, 0.f, 0.f, 0.f);
                if (r < M) zR[it] = *(const float4*)(g_z + (size_t)r * HID + j * 4);
            }
        }
        __syncthreads();

        float c[8][4];
#pragma unroll
        for (int ni = 0; ni < 8; ni++)
#pragma unroll
            for (int q = 0; q < 4; q++) c[ni][q] = 0.f;

        // GEMM1
#pragma unroll
        for (int ks2 = 0; ks2 < 64; ks2 += 8) {
            uint32_t a0, a1, a2, a3, l0, l1, l2, l3;
            ldsm_x4(a0, a1, a2, a3, AhB + (uint32_t)(aRowOff + ks2) * 4u);
            ldsm_x4(l0, l1, l2, l3, AlB + (uint32_t)(aRowOff + ks2) * 4u);
            uint32_t bh[8][2], bl[8][2];
#pragma unroll
            for (int q = 0; q < 4; q++) {
                uint32_t r0, r1, r2, r3;
                ldsm_x4(r0, r1, r2, r3, Wh1B + (uint32_t)(bRowOff + q * 16 * ST2 + ks2) * 4u);
                bh[2 * q][0] = r0; bh[2 * q][1] = r1;
                bh[2 * q + 1][0] = r2; bh[2 * q + 1][1] = r3;
                ldsm_x4(r0, r1, r2, r3, Wl1B + (uint32_t)(bRowOff + q * 16 * ST2 + ks2) * 4u);
                bl[2 * q][0] = r0; bl[2 * q][1] = r1;
                bl[2 * q + 1][0] = r2; bl[2 * q + 1][1] = r3;
            }
#pragma unroll
            for (int ni = 0; ni < 8; ni++) {
                mma_bf16(c[ni], a0, a1, a2, a3, bh[ni][0], bh[ni][1]);
                mma_bf16(c[ni], a0, a1, a2, a3, bl[ni][0], bl[ni][1]);
                mma_bf16(c[ni], l0, l1, l2, l3, bh[ni][0], bh[ni][1]);
            }
        }
        __syncthreads();

        // relu(c + b1) -> split -> Ah/Al
#pragma unroll
        for (int ni = 0; ni < 8; ni++) {
            int col = wn * 64 + ni * 8 + tg * 2;
            float bb0 = b1[col], bb1 = b1[col + 1];
            int k2 = wn * 32 + ni * 4 + tg;
            int r0 = wm * 16 + g;
            uint32_t hi, lo;
            split2(fmaxf(c[ni][0] + bb0, 0.f), fmaxf(c[ni][1] + bb1, 0.f), hi, lo);
            Ah[r0 * ST2 + k2] = hi; Al[r0 * ST2 + k2] = lo;
            split2(fmaxf(c[ni][2] + bb0, 0.f), fmaxf(c[ni][3] + bb1, 0.f), hi, lo);
            Ah[(r0 + 8) * ST2 + k2] = hi; Al[(r0 + 8) * ST2 + k2] = lo;
        }
        __syncthreads();

#pragma unroll
        for (int ni = 0; ni < 8; ni++)
#pragma unroll
            for (int q = 0; q < 4; q++) c[ni][q] = 0.f;

        // GEMM2
#pragma unroll
        for (int ks2 = 0; ks2 < 64; ks2 += 8) {
            uint32_t a0, a1, a2, a3, l0, l1, l2, l3;
            ldsm_x4(a0, a1, a2, a3, AhB + (uint32_t)(aRowOff + ks2) * 4u);
            ldsm_x4(l0, l1, l2, l3, AlB + (uint32_t)(aRowOff + ks2) * 4u);
            uint32_t bh[8][2], bl[8][2];
#pragma unroll
            for (int q = 0; q < 4; q++) {
                uint32_t r0, r1, r2, r3;
                ldsm_x4(r0, r1, r2, r3, Wh2B + (uint32_t)(bRowOff + q * 16 * ST2 + ks2) * 4u);
                bh[2 * q][0] = r0; bh[2 * q][1] = r1;
                bh[2 * q + 1][0] = r2; bh[2 * q + 1][1] = r3;
                ldsm_x4(r0, r1, r2, r3, Wl2B + (uint32_t)(bRowOff + q * 16 * ST2 + ks2) * 4u);
                bl[2 * q][0] = r0; bl[2 * q][1] = r1;
                bl[2 * q + 1][0] = r2; bl[2 * q + 1][1] = r3;
            }
#pragma unroll
            for (int ni = 0; ni < 8; ni++) {
                mma_bf16(c[ni], a0, a1, a2, a3, bh[ni][0], bh[ni][1]);
                mma_bf16(c[ni], a0, a1, a2, a3, bl[ni][0], bl[ni][1]);
                mma_bf16(c[ni], l0, l1, l2, l3, bh[ni][0], bh[ni][1]);
            }
        }

#pragma unroll
        for (int half = 0; half < 2; half++) {
            int row = row0 + wm * 16 + g + half * 8;
            if (row >= M) continue;
#pragma unroll
            for (int ni = 0; ni < 8; ni++) {
                int col = wn * 64 + ni * 8 + tg * 2;
                float2 o;
                o.x = fmaxf(c[ni][half * 2 + 0] + b2[col], 0.f);
                o.y = fmaxf(c[ni][half * 2 + 1] + b2[col + 1], 0.f);
                *(float2*)(g_h + (size_t)row * HID + col) = o;
            }
        }
    }
}

// ---------------- MMA readout: out[M,40] = h @ ro_W + ro_b ------------------
__global__ void __launch_bounds__(256, 2)
readout_mma_kernel(const float* __restrict__ br, float* __restrict__ out, int M) {
    extern __shared__ uint32_t sh[];
    uint32_t* Ah = sh;                    // [128][ST2]
    uint32_t* Al = sh + 128 * ST2;
    uint32_t* Rh = sh + 2 * 128 * ST2;    // [64][ST2]
    uint32_t* Rl = sh + 2 * 128 * ST2 + 64 * ST2;

    const int tid = threadIdx.x, lane = tid & 31, wid = tid >> 5;
    const int g = lane >> 2, tg = lane & 3;
    const int wm = wid;                   // 8 warps, 16 rows each
    const int row0 = blockIdx.x * 128;

    const int lr = lane & 7, lo8 = (lane >> 3) & 1, hi16 = (lane >> 4) & 1;
    const uint32_t AhB = smem_u32(Ah), AlB = smem_u32(Al);
    const uint32_t RhB = smem_u32(Rh), RlB = smem_u32(Rl);
    const int aRowOff = (wm * 16 + lr + 8 * lo8) * ST2 + 4 * hi16;
    const int bRowOff = (lr + 8 * hi16) * ST2 + 4 * lo8;

    // stage h tile split
#pragma unroll
    for (int it = 0; it < 16; it++) {
        int e = tid + it * 256;           // 4096 float4
        int m = e >> 5, j = e & 31;
        int r = row0 + m;
        float4 v = make_float4(0.f, 0.f, 0.f, 0.f);
        if (r < M) v = *(const float4*)(g_h + (size_t)r * HID + j * 4);
        uint32_t h0, l0, h1, l1;
        split2(v.x, v.y, h0, l0);
        split2(v.z, v.w, h1, l1);
        int o = m * ST2 + j * 2;
        Ah[o] = h0; Ah[o + 1] = h1;
        Al[o] = l0; Al[o + 1] = l1;
    }
    // stage ro
#pragma unroll
    for (int it = 0; it < 4; it++) {
        int e = tid + it * 256;           // 1024 uint4
        int n = e >> 4, q = e & 15;
        int o = n * ST2 + q * 4;
        *(uint4*)(Rh + o) = *(const uint4*)(g_roh + n * 64 + q * 4);
        *(uint4*)(Rl + o) = *(const uint4*)(g_rol + n * 64 + q * 4);
    }
    __syncthreads();

    float c[5][4];
#pragma unroll
    for (int ni = 0; ni < 5; ni++)
#pragma unroll
        for (int q = 0; q < 4; q++) c[ni][q] = 0.f;

#pragma unroll
    for (int ks2 = 0; ks2 < 64; ks2 += 8) {
        uint32_t a0, a1, a2, a3, l0, l1, l2, l3;
        ldsm_x4(a0, a1, a2, a3, AhB + (uint32_t)(aRowOff + ks2) * 4u);
        ldsm_x4(l0, l1, l2, l3, AlB + (uint32_t)(aRowOff + ks2) * 4u);
        uint32_t bh[6][2], bl[6][2];
#pragma unroll
        for (int q = 0; q < 3; q++) {     // n rows 0..47 cover ni 0..5
            uint32_t r0, r1, r2, r3;
            ldsm_x4(r0, r1, r2, r3, RhB + (uint32_t)(bRowOff + q * 16 * ST2 + ks2) * 4u);
            bh[2 * q][0] = r0; bh[2 * q][1] = r1;
            bh[2 * q + 1][0] = r2; bh[2 * q + 1][1] = r3;
            ldsm_x4(r0, r1, r2, r3, RlB + (uint32_t)(bRowOff + q * 16 * ST2 + ks2) * 4u);
            bl[2 * q][0] = r0; bl[2 * q][1] = r1;
            bl[2 * q + 1][0] = r2; bl[2 * q + 1][1] = r3;
        }
#pragma unroll
        for (int ni = 0; ni < 5; ni++) {
            mma_bf16(c[ni], a0, a1, a2, a3, bh[ni][0], bh[ni][1]);
            mma_bf16(c[ni], a0, a1, a2, a3, bl[ni][0], bl[ni][1]);
            mma_bf16(c[ni], l0, l1, l2, l3, bh[ni][0], bh[ni][1]);
        }
    }

#pragma unroll
    for (int half = 0; half < 2; half++) {
        int row = row0 + wm * 16 + g + half * 8;
        if (row >= M) continue;
#pragma unroll
        for (int ni = 0; ni < 5; ni++) {
            int col = ni * 8 + tg * 2;
            if (col >= OUT_DIM) continue;
            float2 o;
            o.x = c[ni][half * 2 + 0] + br[col];
            o.y = c[ni][half * 2 + 1] + br[col + 1];
            *(float2*)(out + (size_t)row * OUT_DIM + col) = o;
        }
    }
}

// ---------------- launch ----------------------------------------------------
extern "C" void kernel_launch(void* const* d_in, const int* in_sizes, int n_in,
                              void* d_out, int out_size) {
    const float* features = (const float*)d_in[0];
    const int*   src      = (const int*)  d_in[1];
    const int*   dst      = (const int*)  d_in[2];
    const float* edge_w   = (const float*)d_in[3];
    const float* emb_W    = (const float*)d_in[4];
    const float* emb_b    = (const float*)d_in[5];
    const float* W1       = (const float*)d_in[6];
    const float* b1       = (const float*)d_in[7];
    const float* W2       = (const float*)d_in[8];
    const float* b2       = (const float*)d_in[9];
    const float* ro_W     = (const float*)d_in[10];
    const float* ro_b     = (const float*)d_in[11];
    float* out = (float*)d_out;

    const int emb_smem = 2 * 4 * 128 * ST * (int)sizeof(uint32_t);       // 147456
    const int mlp_smem = 6 * 128 * ST2 * (int)sizeof(uint32_t);          // 208896
    const int ro_smem  = (2 * 128 + 2 * 64) * ST2 * (int)sizeof(uint32_t); // 104448
    cudaFuncSetAttribute(emb_gemm_kernel,   cudaFuncAttributeMaxDynamicSharedMemorySize, emb_smem);
    cudaFuncSetAttribute(mlp_fused_kernel,  cudaFuncAttributeMaxDynamicSharedMemorySize, mlp_smem);
    cudaFuncSetAttribute(readout_mma_kernel, cudaFuncAttributeMaxDynamicSharedMemorySize, ro_smem);

    uint32_t *d_W1h, *d_W1l, *d_W2h, *d_W2l;
    cudaGetSymbolAddress((void**)&d_W1h, g_W1h);
    cudaGetSymbolAddress((void**)&d_W1l, g_W1l);
    cudaGetSymbolAddress((void**)&d_W2h, g_W2h);
    cudaGetSymbolAddress((void**)&d_W2l, g_W2l);

    cudaStream_t side = cudaStreamPerThread;
    cudaEvent_t evA, evB;
    cudaEventCreateWithFlags(&evA, cudaEventDisableTiming);
    cudaEventCreateWithFlags(&evB, cudaEventDisableTiming);

    cudaEventRecord(evA, 0);
    cudaStreamWaitEvent(side, evA, 0);

    prep_emb_kernel<<<HID * 256 / 256, 256>>>(emb_W);                         // main
    prep_w_kernel<<<(N_LAYERS * HID * 64 + 255) / 256, 256>>>(W1, W2);        // main
    zero_deg_kernel<<<(N_NODES + 255) / 256, 256, 0, side>>>();               // side
    emb_gemm_kernel<<<N_TILES, 512, emb_smem>>>(features, emb_b, N_NODES);    // main <- profiled
    prep_ro_kernel<<<(64 * 64 + 255) / 256, 256>>>(ro_W);                     // main
    hist_kernel<<<(N_EDGES + 255) / 256, 256, 0, side>>>(dst);
    scan1_kernel<<<NB_SCAN, 1024, 0, side>>>();
    scan23_kernel<<<NB_SCAN, 1024, 0, side>>>();
    scatter_kernel<<<(N_EDGES + 255) / 256, 256, 0, side>>>(src, dst, edge_w);

    cudaEventRecord(evB, side);
    cudaStreamWaitEvent(0, evB, 0);

    const int agg_blocks = (N_NODES * 32 + 255) / 256;
    for (int l = 0; l < N_LAYERS; l++) {
        agg_kernel<<<agg_blocks, 256>>>();
        mlp_fused_kernel<<<148, 512, mlp_smem>>>(
            d_W1h + (size_t)l * HID * 64, d_W1l + (size_t)l * HID * 64,
            d_W2h + (size_t)l * HID * 64, d_W2l + (size_t)l * HID * 64,
            b1 + (size_t)l * HID, b2 + (size_t)l * HID, N_NODES);
    }
    readout_mma_kernel<<<N_TILES, 256, ro_smem>>>(ro_b, out, N_NODES);
}

// round 14
// speedup vs baseline: 1.3178x; 1.0021x over previous
#include <cuda_runtime.h>
#include <cuda_bf16.h>
#include <cstdint>

#define N_NODES 50000
#define N_EDGES 625000
#define IN_DIM  512
#define HID     128
#define OUT_DIM 40
#define N_LAYERS 3
#define NB_SCAN ((N_NODES + 1023) / 1024)
#define N_TILES ((N_NODES + 127) / 128)
#define NT64 ((N_NODES + 63) / 64)          // 782 half-tiles

// ---------------- scratch ---------------------------------------------------
__device__ float g_h[N_NODES * HID];
__device__ float g_z[N_NODES * HID];
__device__ int   g_deg[N_NODES];
__device__ int   g_off[N_NODES];
__device__ int   g_cur[N_NODES];
__device__ uint2 g_edge[N_EDGES];        // {src, w_bits}
__device__ int   g_bsum[64];
__device__ uint32_t g_eBh[HID * (IN_DIM / 2)];
__device__ uint32_t g_eBl[HID * (IN_DIM / 2)];
__device__ uint32_t g_W1h[N_LAYERS * HID * (HID / 2)];
__device__ uint32_t g_W1l[N_LAYERS * HID * (HID / 2)];
__device__ uint32_t g_W2h[N_LAYERS * HID * (HID / 2)];
__device__ uint32_t g_W2l[N_LAYERS * HID * (HID / 2)];
__device__ uint32_t g_roh[64 * 64];
__device__ uint32_t g_rol[64 * 64];

// ---------------- helpers ----------------------------------------------------
__device__ __forceinline__ uint32_t smem_u32(const void* p) {
    uint32_t a;
    asm("{ .reg .u64 t; cvta.to.shared.u64 t, %1; cvt.u32.u64 %0, t; }" : "=r"(a) : "l"(p));
    return a;
}
__device__ __forceinline__ void split2(float v0, float v1, uint32_t& hi, uint32_t& lo) {
    uint16_t h0, h1, l0, l1;
    asm("cvt.rn.bf16.f32 %0, %1;" : "=h"(h0) : "f"(v0));
    asm("cvt.rn.bf16.f32 %0, %1;" : "=h"(h1) : "f"(v1));
    float r0 = v0 - __uint_as_float((uint32_t)h0 << 16);
    float r1 = v1 - __uint_as_float((uint32_t)h1 << 16);
    asm("cvt.rn.bf16.f32 %0, %1;" : "=h"(l0) : "f"(r0));
    asm("cvt.rn.bf16.f32 %0, %1;" : "=h"(l1) : "f"(r1));
    hi = ((uint32_t)h1 << 16) | h0;
    lo = ((uint32_t)l1 << 16) | l0;
}
__device__ __forceinline__ void mma_bf16(float* c, uint32_t a0, uint32_t a1,
                                         uint32_t a2, uint32_t a3,
                                         uint32_t b0, uint32_t b1) {
    asm volatile("mma.sync.aligned.m16n8k16.row.col.f32.bf16.bf16.f32 "
                 "{%0,%1,%2,%3}, {%4,%5,%6,%7}, {%8,%9}, {%0,%1,%2,%3};"
                 : "+f"(c[0]), "+f"(c[1]), "+f"(c[2]), "+f"(c[3])
                 : "r"(a0), "r"(a1), "r"(a2), "r"(a3), "r"(b0), "r"(b1));
}
__device__ __forceinline__ void ldsm_x4(uint32_t& r0, uint32_t& r1, uint32_t& r2,
                                        uint32_t& r3, uint32_t addr) {
    asm volatile("ldmatrix.sync.aligned.m8n8.x4.shared.b16 {%0,%1,%2,%3}, [%4];"
                 : "=r"(r0), "=r"(r1), "=r"(r2), "=r"(r3) : "r"(addr));
}

// ---------------- CSR build -------------------------------------------------
__global__ void zero_deg_kernel() {
    int i = blockIdx.x * blockDim.x + threadIdx.x;
    if (i < N_NODES) g_deg[i] = 0;
}
__global__ void hist_kernel(const int* __restrict__ dst) {
    int e = blockIdx.x * blockDim.x + threadIdx.x;
    if (e < N_EDGES) atomicAdd(&g_deg[dst[e]], 1);
}
__global__ void scan1_kernel() {
    __shared__ int s[1024];
    int t = threadIdx.x;
    int i = blockIdx.x * 1024 + t;
    int v = (i < N_NODES) ? g_deg[i] : 0;
    s[t] = v;
    __syncthreads();
    for (int d = 1; d < 1024; d <<= 1) {
        int tmp = (t >= d) ? s[t - d] : 0;
        __syncthreads();
        s[t] += tmp;
        __syncthreads();
    }
    if (i < N_NODES) g_off[i] = s[t] - v;
    if (t == 1023) g_bsum[blockIdx.x] = s[1023];
}
__global__ void scan23_kernel() {
    __shared__ int red[64];
    __shared__ int base_s;
    int t = threadIdx.x;
    if (t < 64) red[t] = (t < NB_SCAN && t < (int)blockIdx.x) ? g_bsum[t] : 0;
    __syncthreads();
    if (t < 32) {
        int s = red[t] + red[t + 32];
        for (int d = 16; d > 0; d >>= 1) s += __shfl_down_sync(0xffffffffu, s, d);
        if (t == 0) base_s = s;
    }
    __syncthreads();
    int i = blockIdx.x * 1024 + t;
    if (i < N_NODES) {
        int o = g_off[i] + base_s;
        g_off[i] = o;
        g_cur[i] = o;
    }
}
__global__ void scatter_kernel(const int* __restrict__ src,
                               const int* __restrict__ dst,
                               const float* __restrict__ ew) {
    int e = blockIdx.x * blockDim.x + threadIdx.x;
    if (e < N_EDGES) {
        int d = dst[e];
        int pos = atomicAdd(&g_cur[d], 1);
        g_edge[pos] = make_uint2((uint32_t)src[e], __float_as_uint(ew[e]));
    }
}

// ---------------- weight prep ------------------------------------------------
__global__ void prep_emb_kernel(const float* __restrict__ W) {
    int idx = blockIdx.x * blockDim.x + threadIdx.x;
    int n = idx >> 8, k2 = idx & 255;
    uint32_t hi, lo;
    split2(W[(size_t)(2 * k2) * HID + n], W[(size_t)(2 * k2 + 1) * HID + n], hi, lo);
    g_eBh[n * 256 + k2] = hi;
    g_eBl[n * 256 + k2] = lo;
}
__global__ void prep_w_kernel(const float* __restrict__ W1, const float* __restrict__ W2) {
    int idx = blockIdx.x * blockDim.x + threadIdx.x;
    if (idx >= N_LAYERS * HID * 64) return;
    int l = idx / (HID * 64);
    int rem = idx - l * HID * 64;
    int n = rem >> 6, k2 = rem & 63;
    const float* w1 = W1 + (size_t)l * HID * HID;
    const float* w2 = W2 + (size_t)l * HID * HID;
    uint32_t hi, lo;
    split2(w1[(2 * k2) * HID + n], w1[(2 * k2 + 1) * HID + n], hi, lo);
    g_W1h[idx] = hi; g_W1l[idx] = lo;
    split2(w2[(2 * k2) * HID + n], w2[(2 * k2 + 1) * HID + n], hi, lo);
    g_W2h[idx] = hi; g_W2l[idx] = lo;
}
__global__ void prep_ro_kernel(const float* __restrict__ Wr) {
    int idx = blockIdx.x * blockDim.x + threadIdx.x;
    if (idx >= 64 * 64) return;
    int n = idx >> 6, k2 = idx & 63;
    uint32_t hi = 0, lo = 0;
    if (n < OUT_DIM)
        split2(Wr[(2 * k2) * OUT_DIM + n], Wr[(2 * k2 + 1) * OUT_DIM + n], hi, lo);
    g_roh[idx] = hi;
    g_rol[idx] = lo;
}

// ---------------- emb GEMM: double-buffered k-loop (R9) ---------------------
#define ST 36
#define CHW (128 * ST)
#define BUFW (4 * CHW)
__global__ void __launch_bounds__(512, 1)
emb_gemm_kernel(const float* __restrict__ A, const float* __restrict__ bias, int M) {
    extern __shared__ uint32_t sh[];

    const int tid = threadIdx.x, lane = tid & 31, wid = tid >> 5;
    const int g = lane >> 2, tg = lane & 3;
    const int wm = wid & 7, wn = wid >> 3;
    const int row0 = blockIdx.x * 128;

    const int lr = lane & 7, lo8 = (lane >> 3) & 1, hi16 = (lane >> 4) & 1;
    const uint32_t shB = smem_u32(sh);
    const int aRowOff = (wm * 16 + lr + 8 * lo8) * ST + 4 * hi16;
    const int bRowOff = (wn * 64 + lr + 8 * hi16) * ST + 4 * lo8;

    float4 aR[4];
    uint4  bRh[2], bRl[2];

#pragma unroll
    for (int it = 0; it < 4; it++) {
        int e = tid + it * 512;
        int m = e >> 4, j = e & 15;
        int r = row0 + m;
        aR[it] = make_float4(0.f, 0.f, 0.f, 0.f);
        if (r < M) aR[it] = *(const float4*)(A + (size_t)r * IN_DIM + j * 4);
    }
#pragma unroll
    for (int it = 0; it < 2; it++) {
        int e = tid + it * 512;
        int n = e >> 3, q = e & 7;
        bRh[it] = *(const uint4*)(g_eBh + n * 256 + q * 4);
        bRl[it] = *(const uint4*)(g_eBl + n * 256 + q * 4);
    }
    {
        uint32_t* Ah = sh;            uint32_t* Al = sh + CHW;
        uint32_t* Bh = sh + 2 * CHW;  uint32_t* Bl = sh + 3 * CHW;
#pragma unroll
        for (int it = 0; it < 4; it++) {
            int e = tid + it * 512;
            int m = e >> 4, j = e & 15;
            uint32_t h0, l0, h1, l1;
            split2(aR[it].x, aR[it].y, h0, l0);
            split2(aR[it].z, aR[it].w, h1, l1);
            int o = m * ST + j * 2;
            Ah[o] = h0; Ah[o + 1] = h1;
            Al[o] = l0; Al[o + 1] = l1;
        }
#pragma unroll
        for (int it = 0; it < 2; it++) {
            int e = tid + it * 512;
            int n = e >> 3, q = e & 7;
            int o = n * ST + q * 4;
            *(uint4*)(Bh + o) = bRh[it];
            *(uint4*)(Bl + o) = bRl[it];
        }
    }
    __syncthreads();

    float c[8][4];
#pragma unroll
    for (int ni = 0; ni < 8; ni++)
#pragma unroll
        for (int q = 0; q < 4; q++) c[ni][q] = 0.f;

    const int NCH = IN_DIM / 64;
    for (int ci = 0; ci < NCH; ci++) {
        const int p = ci & 1;
        const uint32_t base = shB + (uint32_t)p * BUFW * 4u;
        const uint32_t AhB = base, AlB = base + CHW * 4u;
        const uint32_t BhB = base + 2u * CHW * 4u, BlB = base + 3u * CHW * 4u;

        if (ci + 1 < NCH) {
            int kn = (ci + 1) * 64, kn2 = kn >> 1;
#pragma unroll
            for (int it = 0; it < 4; it++) {
                int e = tid + it * 512;
                int m = e >> 4, j = e & 15;
                int r = row0 + m;
                aR[it] = make_float4(0.f, 0.f, 0.f, 0.f);
                if (r < M) aR[it] = *(const float4*)(A + (size_t)r * IN_DIM + kn + j * 4);
            }
#pragma unroll
            for (int it = 0; it < 2; it++) {
                int e = tid + it * 512;
                int n = e >> 3, q = e & 7;
                bRh[it] = *(const uint4*)(g_eBh + n * 256 + kn2 + q * 4);
                bRl[it] = *(const uint4*)(g_eBl + n * 256 + kn2 + q * 4);
            }
        }

#pragma unroll
        for (int ks2 = 0; ks2 < 32; ks2 += 8) {
            uint32_t a0, a1, a2, a3, l0, l1, l2, l3;
            ldsm_x4(a0, a1, a2, a3, AhB + (uint32_t)(aRowOff + ks2) * 4u);
            ldsm_x4(l0, l1, l2, l3, AlB + (uint32_t)(aRowOff + ks2) * 4u);
            uint32_t bh[8][2], bl[8][2];
#pragma unroll
            for (int q = 0; q < 4; q++) {
                uint32_t r0, r1, r2, r3;
                ldsm_x4(r0, r1, r2, r3, BhB + (uint32_t)(bRowOff + q * 16 * ST + ks2) * 4u);
                bh[2 * q][0] = r0; bh[2 * q][1] = r1;
                bh[2 * q + 1][0] = r2; bh[2 * q + 1][1] = r3;
                ldsm_x4(r0, r1, r2, r3, BlB + (uint32_t)(bRowOff + q * 16 * ST + ks2) * 4u);
                bl[2 * q][0] = r0; bl[2 * q][1] = r1;
                bl[2 * q + 1][0] = r2; bl[2 * q + 1][1] = r3;
            }
#pragma unroll
            for (int ni = 0; ni < 8; ni++) {
                mma_bf16(c[ni], a0, a1, a2, a3, bh[ni][0], bh[ni][1]);
                mma_bf16(c[ni], a0, a1, a2, a3, bl[ni][0], bl[ni][1]);
                mma_bf16(c[ni], l0, l1, l2, l3, bh[ni][0], bh[ni][1]);
            }
        }

        if (ci + 1 < NCH) {
            uint32_t* Ah = sh + (p ^ 1) * BUFW;
            uint32_t* Al = Ah + CHW;
            uint32_t* Bh = Ah + 2 * CHW;
            uint32_t* Bl = Ah + 3 * CHW;
#pragma unroll
            for (int it = 0; it < 4; it++) {
                int e = tid + it * 512;
                int m = e >> 4, j = e & 15;
                uint32_t h0, l0, h1, l1;
                split2(aR[it].x, aR[it].y, h0, l0);
                split2(aR[it].z, aR[it].w, h1, l1);
                int o = m * ST + j * 2;
                Ah[o] = h0; Ah[o + 1] = h1;
                Al[o] = l0; Al[o + 1] = l1;
            }
#pragma unroll
            for (int it = 0; it < 2; it++) {
                int e = tid + it * 512;
                int n = e >> 3, q = e & 7;
                int o = n * ST + q * 4;
                *(uint4*)(Bh + o) = bRh[it];
                *(uint4*)(Bl + o) = bRl[it];
            }
            __syncthreads();
        }
    }

#pragma unroll
    for (int half = 0; half < 2; half++) {
        int row = row0 + wm * 16 + g + half * 8;
        if (row >= M) continue;
#pragma unroll
        for (int ni = 0; ni < 8; ni++) {
            int col = wn * 64 + ni * 8 + tg * 2;
            float2 o;
            o.x = c[ni][half * 2 + 0] + bias[col];
            o.y = c[ni][half * 2 + 1] + bias[col + 1];
            *(float2*)(g_h + (size_t)row * HID + col) = o;
        }
    }
}

// ---------------- aggregation ------------------------------------------------
__global__ void agg_kernel() {
    int node = (blockIdx.x * blockDim.x + threadIdx.x) >> 5;
    int lane = threadIdx.x & 31;
    if (node >= N_NODES) return;
    int s = g_off[node];
    int d = g_deg[node];
    float4 acc = *(const float4*)(g_h + (size_t)node * HID + lane * 4);
    int i = 0;
    for (; i + 2 <= d; i += 2) {
        uint2 e0 = g_edge[s + i];
        uint2 e1 = g_edge[s + i + 1];
        float w0 = __uint_as_float(e0.y);
        float w1 = __uint_as_float(e1.y);
        float4 h0 = *(const float4*)(g_h + (size_t)e0.x * HID + lane * 4);
        float4 h1 = *(const float4*)(g_h + (size_t)e1.x * HID + lane * 4);
        acc.x += w0 * h0.x + w1 * h1.x;
        acc.y += w0 * h0.y + w1 * h1.y;
        acc.z += w0 * h0.z + w1 * h1.z;
        acc.w += w0 * h0.w + w1 * h1.w;
    }
    if (i < d) {
        uint2 e0 = g_edge[s + i];
        float w0 = __uint_as_float(e0.y);
        float4 h0 = *(const float4*)(g_h + (size_t)e0.x * HID + lane * 4);
        acc.x += w0 * h0.x; acc.y += w0 * h0.y;
        acc.z += w0 * h0.z; acc.w += w0 * h0.w;
    }
    *(float4*)(g_z + (size_t)node * HID + lane * 4) = acc;
}

// ------ persistent MLP: 2 async warp-groups share weights, named barriers ---
#define ST2 68
#define BARG() asm volatile("bar.sync %0, %1;" :: "r"(grp + 1), "r"(256) : "memory")
__global__ void __launch_bounds__(512, 1)
mlp_fused_kernel(const uint32_t* __restrict__ W1h, const uint32_t* __restrict__ W1l,
                 const uint32_t* __restrict__ W2h, const uint32_t* __restrict__ W2l,
                 const float* __restrict__ b1, const float* __restrict__ b2, int M) {
    extern __shared__ uint32_t sh[];
    // layout (words): A0h[64*ST2] A0l A1h A1l | Wh1[128*ST2] Wl1 Wh2 Wl2
    uint32_t* Wh1 = sh + 4 * 64 * ST2;
    uint32_t* Wl1 = Wh1 + 128 * ST2;
    uint32_t* Wh2 = Wl1 + 128 * ST2;
    uint32_t* Wl2 = Wh2 + 128 * ST2;

    const int tid = threadIdx.x, lane = tid & 31, wid = tid >> 5;
    const int grp = wid >> 3;            // 0 or 1
    const int wg  = wid & 7;             // warp in group
    const int tg_ = tid & 255;           // thread in group
    const int g = lane >> 2, tg = lane & 3;
    const int wm = wg & 3, wn = wg >> 2; // 4 x 2 warps, 16x64 each (64x128 tile)

    uint32_t* Ah = sh + grp * 2 * 64 * ST2;
    uint32_t* Al = Ah + 64 * ST2;

    const int lr = lane & 7, lo8 = (lane >> 3) & 1, hi16 = (lane >> 4) & 1;
    const uint32_t AhB  = smem_u32(Ah),  AlB  = smem_u32(Al);
    const uint32_t Wh1B = smem_u32(Wh1), Wl1B = smem_u32(Wl1);
    const uint32_t Wh2B = smem_u32(Wh2), Wl2B = smem_u32(Wl2);
    const int aRowOff = (wm * 16 + lr + 8 * lo8) * ST2 + 4 * hi16;
    const int bRowOff = (wn * 64 + lr + 8 * hi16) * ST2 + 4 * lo8;

    // stage weights once (all 512 threads), joint barrier
#pragma unroll
    for (int it = 0; it < 4; it++) {
        int e = tid + it * 512;
        int n = e >> 4, q = e & 15;
        int o = n * ST2 + q * 4;
        *(uint4*)(Wh1 + o) = *(const uint4*)(W1h + n * 64 + q * 4);
        *(uint4*)(Wl1 + o) = *(const uint4*)(W1l + n * 64 + q * 4);
        *(uint4*)(Wh2 + o) = *(const uint4*)(W2h + n * 64 + q * 4);
        *(uint4*)(Wl2 + o) = *(const uint4*)(W2l + n * 64 + q * 4);
    }
    __syncthreads();

    const int stride = gridDim.x * 2;
    const int t0 = blockIdx.x * 2 + grp;

    // prefetch z for first tile
    float4 zR[8];
    {
        const int row0 = t0 * 64;
#pragma unroll
        for (int it = 0; it < 8; it++) {
            int e = tg_ + it * 256;               // 2048 = 64 rows x 32 f4
            int m = e >> 5, j = e & 31;
            int r = row0 + m;
            zR[it] = make_float4(0.f, 0.f, 0.f, 0.f);
            if (r < M) zR[it] = *(const float4*)(g_z + (size_t)r * HID + j * 4);
        }
    }

    for (int tile = t0; tile < NT64; tile += stride) {
        const int row0 = tile * 64;
        BARG();   // prev tile's GEMM2 done reading A

        // store prefetched z -> split -> A
#pragma unroll
        for (int it = 0; it < 8; it++) {
            int e = tg_ + it * 256;
            int m = e >> 5, j = e & 31;
            uint32_t h0, l0, h1, l1;
            split2(zR[it].x, zR[it].y, h0, l0);
            split2(zR[it].z, zR[it].w, h1, l1);
            int o = m * ST2 + j * 2;
            Ah[o] = h0; Ah[o + 1] = h1;
            Al[o] = l0; Al[o + 1] = l1;
        }
        // prefetch next tile's z
        if (tile + stride < NT64) {
            const int nrow0 = (tile + stride) * 64;
#pragma unroll
            for (int it = 0; it < 8; it++) {
                int e = tg_ + it * 256;
                int m = e >> 5, j = e & 31;
                int r = nrow0 + m;
                zR[it] = make_float4(0.f, 0.f, 0.f, 0.f);
                if (r < M) zR[it] = *(const float4*)(g_z + (size_t)r * HID + j * 4);
            }
        }
        BARG();

        float c[8][4];
#pragma unroll
        for (int ni = 0; ni < 8; ni++)
#pragma unroll
            for (int q = 0; q < 4; q++) c[ni][q] = 0.f;

        // GEMM1: 64x128 = A(64xK) * W1
#pragma unroll
        for (int ks2 = 0; ks2 < 64; ks2 += 8) {
            uint32_t a0, a1, a2, a3, l0, l1, l2, l3;
            ldsm_x4(a0, a1, a2, a3, AhB + (uint32_t)(aRowOff + ks2) * 4u);
            ldsm_x4(l0, l1, l2, l3, AlB + (uint32_t)(aRowOff + ks2) * 4u);
            uint32_t bh[8][2], bl[8][2];
#pragma unroll
            for (int q = 0; q < 4; q++) {
                uint32_t r0, r1, r2, r3;
                ldsm_x4(r0, r1, r2, r3, Wh1B + (uint32_t)(bRowOff + q * 16 * ST2 + ks2) * 4u);
                bh[2 * q][0] = r0; bh[2 * q][1] = r1;
                bh[2 * q + 1][0] = r2; bh[2 * q + 1][1] = r3;
                ldsm_x4(r0, r1, r2, r3, Wl1B + (uint32_t)(bRowOff + q * 16 * ST2 + ks2) * 4u);
                bl[2 * q][0] = r0; bl[2 * q][1] = r1;
                bl[2 * q + 1][0] = r2; bl[2 * q + 1][1] = r3;
            }
#pragma unroll
            for (int ni = 0; ni < 8; ni++) {
                mma_bf16(c[ni], a0, a1, a2, a3, bh[ni][0], bh[ni][1]);
                mma_bf16(c[ni], a0, a1, a2, a3, bl[ni][0], bl[ni][1]);
                mma_bf16(c[ni], l0, l1, l2, l3, bh[ni][0], bh[ni][1]);
            }
        }
        BARG();

        // relu(c + b1) -> split -> A
#pragma unroll
        for (int ni = 0; ni < 8; ni++) {
            int col = wn * 64 + ni * 8 + tg * 2;
            float bb0 = b1[col], bb1 = b1[col + 1];
            int k2 = wn * 32 + ni * 4 + tg;
            int r0 = wm * 16 + g;
            uint32_t hi, lo;
            split2(fmaxf(c[ni][0] + bb0, 0.f), fmaxf(c[ni][1] + bb1, 0.f), hi, lo);
            Ah[r0 * ST2 + k2] = hi; Al[r0 * ST2 + k2] = lo;
            split2(fmaxf(c[ni][2] + bb0, 0.f), fmaxf(c[ni][3] + bb1, 0.f), hi, lo);
            Ah[(r0 + 8) * ST2 + k2] = hi; Al[(r0 + 8) * ST2 + k2] = lo;
        }
        BARG();

#pragma unroll
        for (int ni = 0; ni < 8; ni++)
#pragma unroll
            for (int q = 0; q < 4; q++) c[ni][q] = 0.f;

        // GEMM2
#pragma unroll
        for (int ks2 = 0; ks2 < 64; ks2 += 8) {
            uint32_t a0, a1, a2, a3, l0, l1, l2, l3;
            ldsm_x4(a0, a1, a2, a3, AhB + (uint32_t)(aRowOff + ks2) * 4u);
            ldsm_x4(l0, l1, l2, l3, AlB + (uint32_t)(aRowOff + ks2) * 4u);
            uint32_t bh[8][2], bl[8][2];
#pragma unroll
            for (int q = 0; q < 4; q++) {
                uint32_t r0, r1, r2, r3;
                ldsm_x4(r0, r1, r2, r3, Wh2B + (uint32_t)(bRowOff + q * 16 * ST2 + ks2) * 4u);
                bh[2 * q][0] = r0; bh[2 * q][1] = r1;
                bh[2 * q + 1][0] = r2; bh[2 * q + 1][1] = r3;
                ldsm_x4(r0, r1, r2, r3, Wl2B + (uint32_t)(bRowOff + q * 16 * ST2 + ks2) * 4u);
                bl[2 * q][0] = r0; bl[2 * q][1] = r1;
                bl[2 * q + 1][0] = r2; bl[2 * q + 1][1] = r3;
            }
#pragma unroll
            for (int ni = 0; ni < 8; ni++) {
                mma_bf16(c[ni], a0, a1, a2, a3, bh[ni][0], bh[ni][1]);
                mma_bf16(c[ni], a0, a1, a2, a3, bl[ni][0], bl[ni][1]);
                mma_bf16(c[ni], l0, l1, l2, l3, bh[ni][0], bh[ni][1]);
            }
        }

        // epilogue
#pragma unroll
        for (int half = 0; half < 2; half++) {
            int row = row0 + wm * 16 + g + half * 8;
            if (row >= M) continue;
#pragma unroll
            for (int ni = 0; ni < 8; ni++) {
                int col = wn * 64 + ni * 8 + tg * 2;
                float2 o;
                o.x = fmaxf(c[ni][half * 2 + 0] + b2[col], 0.f);
                o.y = fmaxf(c[ni][half * 2 + 1] + b2[col + 1], 0.f);
                *(float2*)(g_h + (size_t)row * HID + col) = o;
            }
        }
    }
}

// ---------------- MMA readout (R13) ------------------------------------------
__global__ void __launch_bounds__(256, 2)
readout_mma_kernel(const float* __restrict__ br, float* __restrict__ out, int M) {
    extern __shared__ uint32_t sh[];
    uint32_t* Ah = sh;
    uint32_t* Al = sh + 128 * ST2;
    uint32_t* Rh = sh + 2 * 128 * ST2;
    uint32_t* Rl = sh + 2 * 128 * ST2 + 64 * ST2;

    const int tid = threadIdx.x, lane = tid & 31, wid = tid >> 5;
    const int g = lane >> 2, tg = lane & 3;
    const int wm = wid;
    const int row0 = blockIdx.x * 128;

    const int lr = lane & 7, lo8 = (lane >> 3) & 1, hi16 = (lane >> 4) & 1;
    const uint32_t AhB = smem_u32(Ah), AlB = smem_u32(Al);
    const uint32_t RhB = smem_u32(Rh), RlB = smem_u32(Rl);
    const int aRowOff = (wm * 16 + lr + 8 * lo8) * ST2 + 4 * hi16;
    const int bRowOff = (lr + 8 * hi16) * ST2 + 4 * lo8;

#pragma unroll
    for (int it = 0; it < 16; it++) {
        int e = tid + it * 256;
        int m = e >> 5, j = e & 31;
        int r = row0 + m;
        float4 v = make_float4(0.f, 0.f, 0.f, 0.f);
        if (r < M) v = *(const float4*)(g_h + (size_t)r * HID + j * 4);
        uint32_t h0, l0, h1, l1;
        split2(v.x, v.y, h0, l0);
        split2(v.z, v.w, h1, l1);
        int o = m * ST2 + j * 2;
        Ah[o] = h0; Ah[o + 1] = h1;
        Al[o] = l0; Al[o + 1] = l1;
    }
#pragma unroll
    for (int it = 0; it < 4; it++) {
        int e = tid + it * 256;
        int n = e >> 4, q = e & 15;
        int o = n * ST2 + q * 4;
        *(uint4*)(Rh + o) = *(const uint4*)(g_roh + n * 64 + q * 4);
        *(uint4*)(Rl + o) = *(const uint4*)(g_rol + n * 64 + q * 4);
    }
    __syncthreads();

    float c[5][4];
#pragma unroll
    for (int ni = 0; ni < 5; ni++)
#pragma unroll
        for (int q = 0; q < 4; q++) c[ni][q] = 0.f;

#pragma unroll
    for (int ks2 = 0; ks2 < 64; ks2 += 8) {
        uint32_t a0, a1, a2, a3, l0, l1, l2, l3;
        ldsm_x4(a0, a1, a2, a3, AhB + (uint32_t)(aRowOff + ks2) * 4u);
        ldsm_x4(l0, l1, l2, l3, AlB + (uint32_t)(aRowOff + ks2) * 4u);
        uint32_t bh[6][2], bl[6][2];
#pragma unroll
        for (int q = 0; q < 3; q++) {
            uint32_t r0, r1, r2, r3;
            ldsm_x4(r0, r1, r2, r3, RhB + (uint32_t)(bRowOff + q * 16 * ST2 + ks2) * 4u);
            bh[2 * q][0] = r0; bh[2 * q][1] = r1;
            bh[2 * q + 1][0] = r2; bh[2 * q + 1][1] = r3;
            ldsm_x4(r0, r1, r2, r3, RlB + (uint32_t)(bRowOff + q * 16 * ST2 + ks2) * 4u);
            bl[2 * q][0] = r0; bl[2 * q][1] = r1;
            bl[2 * q + 1][0] = r2; bl[2 * q + 1][1] = r3;
        }
#pragma unroll
        for (int ni = 0; ni < 5; ni++) {
            mma_bf16(c[ni], a0, a1, a2, a3, bh[ni][0], bh[ni][1]);
            mma_bf16(c[ni], a0, a1, a2, a3, bl[ni][0], bl[ni][1]);
            mma_bf16(c[ni], l0, l1, l2, l3, bh[ni][0], bh[ni][1]);
        }
    }

#pragma unroll
    for (int half = 0; half < 2; half++) {
        int row = row0 + wm * 16 + g + half * 8;
        if (row >= M) continue;
#pragma unroll
        for (int ni = 0; ni < 5; ni++) {
            int col = ni * 8 + tg * 2;
            if (col >= OUT_DIM) continue;
            float2 o;
            o.x = c[ni][half * 2 + 0] + br[col];
            o.y = c[ni][half * 2 + 1] + br[col + 1];
            *(float2*)(out + (size_t)row * OUT_DIM + col) = o;
        }
    }
}

// ---------------- launch ----------------------------------------------------
extern "C" void kernel_launch(void* const* d_in, const int* in_sizes, int n_in,
                              void* d_out, int out_size) {
    const float* features = (const float*)d_in[0];
    const int*   src      = (const int*)  d_in[1];
    const int*   dst      = (const int*)  d_in[2];
    const float* edge_w   = (const float*)d_in[3];
    const float* emb_W    = (const float*)d_in[4];
    const float* emb_b    = (const float*)d_in[5];
    const float* W1       = (const float*)d_in[6];
    const float* b1       = (const float*)d_in[7];
    const float* W2       = (const float*)d_in[8];
    const float* b2       = (const float*)d_in[9];
    const float* ro_W     = (const float*)d_in[10];
    const float* ro_b     = (const float*)d_in[11];
    float* out = (float*)d_out;

    const int emb_smem = 2 * 4 * 128 * ST * (int)sizeof(uint32_t);
    const int mlp_smem = (4 * 64 + 4 * 128) * ST2 * (int)sizeof(uint32_t);   // 208896
    const int ro_smem  = (2 * 128 + 2 * 64) * ST2 * (int)sizeof(uint32_t);
    cudaFuncSetAttribute(emb_gemm_kernel,    cudaFuncAttributeMaxDynamicSharedMemorySize, emb_smem);
    cudaFuncSetAttribute(mlp_fused_kernel,   cudaFuncAttributeMaxDynamicSharedMemorySize, mlp_smem);
    cudaFuncSetAttribute(readout_mma_kernel, cudaFuncAttributeMaxDynamicSharedMemorySize, ro_smem);

    uint32_t *d_W1h, *d_W1l, *d_W2h, *d_W2l;
    cudaGetSymbolAddress((void**)&d_W1h, g_W1h);
    cudaGetSymbolAddress((void**)&d_W1l, g_W1l);
    cudaGetSymbolAddress((void**)&d_W2h, g_W2h);
    cudaGetSymbolAddress((void**)&d_W2l, g_W2l);

    cudaStream_t side = cudaStreamPerThread;
    cudaEvent_t evA, evB;
    cudaEventCreateWithFlags(&evA, cudaEventDisableTiming);
    cudaEventCreateWithFlags(&evB, cudaEventDisableTiming);

    cudaEventRecord(evA, 0);
    cudaStreamWaitEvent(side, evA, 0);

    prep_emb_kernel<<<HID * 256 / 256, 256>>>(emb_W);                         // main
    prep_w_kernel<<<(N_LAYERS * HID * 64 + 255) / 256, 256>>>(W1, W2);        // main
    zero_deg_kernel<<<(N_NODES + 255) / 256, 256, 0, side>>>();               // side
    emb_gemm_kernel<<<N_TILES, 512, emb_smem>>>(features, emb_b, N_NODES);    // main <- profiled
    prep_ro_kernel<<<(64 * 64 + 255) / 256, 256>>>(ro_W);                     // main
    hist_kernel<<<(N_EDGES + 255) / 256, 256, 0, side>>>(dst);
    scan1_kernel<<<NB_SCAN, 1024, 0, side>>>();
    scan23_kernel<<<NB_SCAN, 1024, 0, side>>>();
    scatter_kernel<<<(N_EDGES + 255) / 256, 256, 0, side>>>(src, dst, edge_w);

    cudaEventRecord(evB, side);
    cudaStreamWaitEvent(0, evB, 0);

    const int agg_blocks = (N_NODES * 32 + 255) / 256;
    for (int l = 0; l < N_LAYERS; l++) {
        agg_kernel<<<agg_blocks, 256>>>();
        mlp_fused_kernel<<<148, 512, mlp_smem>>>(
            d_W1h + (size_t)l * HID * 64, d_W1l + (size_t)l * HID * 64,
            d_W2h + (size_t)l * HID * 64, d_W2l + (size_t)l * HID * 64,
            b1 + (size_t)l * HID, b2 + (size_t)l * HID, N_NODES);
    }
    readout_mma_kernel<<<N_TILES, 256, ro_smem>>>(ro_b, out, N_NODES);
}

// round 15
// speedup vs baseline: 1.3793x; 1.0466x over previous
#include <cuda_runtime.h>
#include <cuda_bf16.h>
#include <cstdint>

#define N_NODES 50000
#define N_EDGES 625000
#define IN_DIM  512
#define HID     128
#define OUT_DIM 40
#define N_LAYERS 3
#define NB_SCAN ((N_NODES + 1023) / 1024)
#define N_TILES ((N_NODES + 127) / 128)
#define NT64 ((N_NODES + 63) / 64)

// ---------------- scratch ---------------------------------------------------
__device__ float g_h[N_NODES * HID];
__device__ float g_z[N_NODES * HID];
__device__ int   g_deg[N_NODES];
__device__ int   g_off[N_NODES];
__device__ int   g_cur[N_NODES];
__device__ uint2 g_edge[N_EDGES];
__device__ int   g_bsum[64];
__device__ uint32_t g_eBh[HID * (IN_DIM / 2)];
__device__ uint32_t g_eBl[HID * (IN_DIM / 2)];
__device__ uint32_t g_W1h[N_LAYERS * HID * (HID / 2)];
__device__ uint32_t g_W1l[N_LAYERS * HID * (HID / 2)];
__device__ uint32_t g_W2h[N_LAYERS * HID * (HID / 2)];
__device__ uint32_t g_W2l[N_LAYERS * HID * (HID / 2)];
__device__ uint32_t g_roh[64 * 64];
__device__ uint32_t g_rol[64 * 64];

// ---------------- helpers ----------------------------------------------------
__device__ __forceinline__ uint32_t smem_u32(const void* p) {
    uint32_t a;
    asm("{ .reg .u64 t; cvta.to.shared.u64 t, %1; cvt.u32.u64 %0, t; }" : "=r"(a) : "l"(p));
    return a;
}
__device__ __forceinline__ void split2(float v0, float v1, uint32_t& hi, uint32_t& lo) {
    uint16_t h0, h1, l0, l1;
    asm("cvt.rn.bf16.f32 %0, %1;" : "=h"(h0) : "f"(v0));
    asm("cvt.rn.bf16.f32 %0, %1;" : "=h"(h1) : "f"(v1));
    float r0 = v0 - __uint_as_float((uint32_t)h0 << 16);
    float r1 = v1 - __uint_as_float((uint32_t)h1 << 16);
    asm("cvt.rn.bf16.f32 %0, %1;" : "=h"(l0) : "f"(r0));
    asm("cvt.rn.bf16.f32 %0, %1;" : "=h"(l1) : "f"(r1));
    hi = ((uint32_t)h1 << 16) | h0;
    lo = ((uint32_t)l1 << 16) | l0;
}
__device__ __forceinline__ void mma_bf16(float* c, uint32_t a0, uint32_t a1,
                                         uint32_t a2, uint32_t a3,
                                         uint32_t b0, uint32_t b1) {
    asm volatile("mma.sync.aligned.m16n8k16.row.col.f32.bf16.bf16.f32 "
                 "{%0,%1,%2,%3}, {%4,%5,%6,%7}, {%8,%9}, {%0,%1,%2,%3};"
                 : "+f"(c[0]), "+f"(c[1]), "+f"(c[2]), "+f"(c[3])
                 : "r"(a0), "r"(a1), "r"(a2), "r"(a3), "r"(b0), "r"(b1));
}
__device__ __forceinline__ void ldsm_x4(uint32_t& r0, uint32_t& r1, uint32_t& r2,
                                        uint32_t& r3, uint32_t addr) {
    asm volatile("ldmatrix.sync.aligned.m8n8.x4.shared.b16 {%0,%1,%2,%3}, [%4];"
                 : "=r"(r0), "=r"(r1), "=r"(r2), "=r"(r3) : "r"(addr));
}

// ---------------- CSR build -------------------------------------------------
__global__ void zero_deg_kernel() {
    int i = blockIdx.x * blockDim.x + threadIdx.x;
    if (i < N_NODES) g_deg[i] = 0;
}
__global__ void hist_kernel(const int* __restrict__ dst) {
    int e = blockIdx.x * blockDim.x + threadIdx.x;
    if (e < N_EDGES) atomicAdd(&g_deg[dst[e]], 1);
}
__global__ void scan1_kernel() {
    __shared__ int s[1024];
    int t = threadIdx.x;
    int i = blockIdx.x * 1024 + t;
    int v = (i < N_NODES) ? g_deg[i] : 0;
    s[t] = v;
    __syncthreads();
    for (int d = 1; d < 1024; d <<= 1) {
        int tmp = (t >= d) ? s[t - d] : 0;
        __syncthreads();
        s[t] += tmp;
        __syncthreads();
    }
    if (i < N_NODES) g_off[i] = s[t] - v;
    if (t == 1023) g_bsum[blockIdx.x] = s[1023];
}
__global__ void scan23_kernel() {
    __shared__ int red[64];
    __shared__ int base_s;
    int t = threadIdx.x;
    if (t < 64) red[t] = (t < NB_SCAN && t < (int)blockIdx.x) ? g_bsum[t] : 0;
    __syncthreads();
    if (t < 32) {
        int s = red[t] + red[t + 32];
        for (int d = 16; d > 0; d >>= 1) s += __shfl_down_sync(0xffffffffu, s, d);
        if (t == 0) base_s = s;
    }
    __syncthreads();
    int i = blockIdx.x * 1024 + t;
    if (i < N_NODES) {
        int o = g_off[i] + base_s;
        g_off[i] = o;
        g_cur[i] = o;
    }
}
__global__ void scatter_kernel(const int* __restrict__ src,
                               const int* __restrict__ dst,
                               const float* __restrict__ ew) {
    int e = blockIdx.x * blockDim.x + threadIdx.x;
    if (e < N_EDGES) {
        int d = dst[e];
        int pos = atomicAdd(&g_cur[d], 1);
        g_edge[pos] = make_uint2((uint32_t)src[e], __float_as_uint(ew[e]));
    }
}

// ---------------- merged weight prep -----------------------------------------
// [0, 32768)            : emb  (n = i>>8, k2 = i&255)
// [32768, 32768+24576)  : W1/W2 (3 layers x 128 x 64)
// [57344, 57344+4096)   : readout (64 x 64)
__global__ void prep_all_kernel(const float* __restrict__ We,
                                const float* __restrict__ W1,
                                const float* __restrict__ W2,
                                const float* __restrict__ Wr) {
    int idx = blockIdx.x * blockDim.x + threadIdx.x;
    uint32_t hi, lo;
    if (idx < 32768) {
        int n = idx >> 8, k2 = idx & 255;
        split2(We[(size_t)(2 * k2) * HID + n], We[(size_t)(2 * k2 + 1) * HID + n], hi, lo);
        g_eBh[idx] = hi;
        g_eBl[idx] = lo;
    } else if (idx < 32768 + N_LAYERS * HID * 64) {
        int j = idx - 32768;
        int l = j / (HID * 64);
        int rem = j - l * HID * 64;
        int n = rem >> 6, k2 = rem & 63;
        const float* w1 = W1 + (size_t)l * HID * HID;
        const float* w2 = W2 + (size_t)l * HID * HID;
        split2(w1[(2 * k2) * HID + n], w1[(2 * k2 + 1) * HID + n], hi, lo);
        g_W1h[j] = hi; g_W1l[j] = lo;
        split2(w2[(2 * k2) * HID + n], w2[(2 * k2 + 1) * HID + n], hi, lo);
        g_W2h[j] = hi; g_W2l[j] = lo;
    } else if (idx < 32768 + N_LAYERS * HID * 64 + 4096) {
        int j = idx - 32768 - N_LAYERS * HID * 64;
        int n = j >> 6, k2 = j & 63;
        hi = 0; lo = 0;
        if (n < OUT_DIM)
            split2(Wr[(2 * k2) * OUT_DIM + n], Wr[(2 * k2 + 1) * OUT_DIM + n], hi, lo);
        g_roh[j] = hi;
        g_rol[j] = lo;
    }
}
#define PREP_TOTAL (32768 + N_LAYERS * HID * 64 + 4096)

// ---------------- emb GEMM: double-buffered k-loop (R9) ---------------------
#define ST 36
#define CHW (128 * ST)
#define BUFW (4 * CHW)
__global__ void __launch_bounds__(512, 1)
emb_gemm_kernel(const float* __restrict__ A, const float* __restrict__ bias, int M) {
    extern __shared__ uint32_t sh[];

    const int tid = threadIdx.x, lane = tid & 31, wid = tid >> 5;
    const int g = lane >> 2, tg = lane & 3;
    const int wm = wid & 7, wn = wid >> 3;
    const int row0 = blockIdx.x * 128;

    const int lr = lane & 7, lo8 = (lane >> 3) & 1, hi16 = (lane >> 4) & 1;
    const uint32_t shB = smem_u32(sh);
    const int aRowOff = (wm * 16 + lr + 8 * lo8) * ST + 4 * hi16;
    const int bRowOff = (wn * 64 + lr + 8 * hi16) * ST + 4 * lo8;

    float4 aR[4];
    uint4  bRh[2], bRl[2];

#pragma unroll
    for (int it = 0; it < 4; it++) {
        int e = tid + it * 512;
        int m = e >> 4, j = e & 15;
        int r = row0 + m;
        aR[it] = make_float4(0.f, 0.f, 0.f, 0.f);
        if (r < M) aR[it] = *(const float4*)(A + (size_t)r * IN_DIM + j * 4);
    }
#pragma unroll
    for (int it = 0; it < 2; it++) {
        int e = tid + it * 512;
        int n = e >> 3, q = e & 7;
        bRh[it] = *(const uint4*)(g_eBh + n * 256 + q * 4);
        bRl[it] = *(const uint4*)(g_eBl + n * 256 + q * 4);
    }
    {
        uint32_t* Ah = sh;            uint32_t* Al = sh + CHW;
        uint32_t* Bh = sh + 2 * CHW;  uint32_t* Bl = sh + 3 * CHW;
#pragma unroll
        for (int it = 0; it < 4; it++) {
            int e = tid + it * 512;
            int m = e >> 4, j = e & 15;
            uint32_t h0, l0, h1, l1;
            split2(aR[it].x, aR[it].y, h0, l0);
            split2(aR[it].z, aR[it].w, h1, l1);
            int o = m * ST + j * 2;
            Ah[o] = h0; Ah[o + 1] = h1;
            Al[o] = l0; Al[o + 1] = l1;
        }
#pragma unroll
        for (int it = 0; it < 2; it++) {
            int e = tid + it * 512;
            int n = e >> 3, q = e & 7;
            int o = n * ST + q * 4;
            *(uint4*)(Bh + o) = bRh[it];
            *(uint4*)(Bl + o) = bRl[it];
        }
    }
    __syncthreads();

    float c[8][4];
#pragma unroll
    for (int ni = 0; ni < 8; ni++)
#pragma unroll
        for (int q = 0; q < 4; q++) c[ni][q] = 0.f;

    const int NCH = IN_DIM / 64;
    for (int ci = 0; ci < NCH; ci++) {
        const int p = ci & 1;
        const uint32_t base = shB + (uint32_t)p * BUFW * 4u;
        const uint32_t AhB = base, AlB = base + CHW * 4u;
        const uint32_t BhB = base + 2u * CHW * 4u, BlB = base + 3u * CHW * 4u;

        if (ci + 1 < NCH) {
            int kn = (ci + 1) * 64, kn2 = kn >> 1;
#pragma unroll
            for (int it = 0; it < 4; it++) {
                int e = tid + it * 512;
                int m = e >> 4, j = e & 15;
                int r = row0 + m;
                aR[it] = make_float4(0.f, 0.f, 0.f, 0.f);
                if (r < M) aR[it] = *(const float4*)(A + (size_t)r * IN_DIM + kn + j * 4);
            }
#pragma unroll
            for (int it = 0; it < 2; it++) {
                int e = tid + it * 512;
                int n = e >> 3, q = e & 7;
                bRh[it] = *(const uint4*)(g_eBh + n * 256 + kn2 + q * 4);
                bRl[it] = *(const uint4*)(g_eBl + n * 256 + kn2 + q * 4);
            }
        }

#pragma unroll
        for (int ks2 = 0; ks2 < 32; ks2 += 8) {
            uint32_t a0, a1, a2, a3, l0, l1, l2, l3;
            ldsm_x4(a0, a1, a2, a3, AhB + (uint32_t)(aRowOff + ks2) * 4u);
            ldsm_x4(l0, l1, l2, l3, AlB + (uint32_t)(aRowOff + ks2) * 4u);
            uint32_t bh[8][2], bl[8][2];
#pragma unroll
            for (int q = 0; q < 4; q++) {
                uint32_t r0, r1, r2, r3;
                ldsm_x4(r0, r1, r2, r3, BhB + (uint32_t)(bRowOff + q * 16 * ST + ks2) * 4u);
                bh[2 * q][0] = r0; bh[2 * q][1] = r1;
                bh[2 * q + 1][0] = r2; bh[2 * q + 1][1] = r3;
                ldsm_x4(r0, r1, r2, r3, BlB + (uint32_t)(bRowOff + q * 16 * ST + ks2) * 4u);
                bl[2 * q][0] = r0; bl[2 * q][1] = r1;
                bl[2 * q + 1][0] = r2; bl[2 * q + 1][1] = r3;
            }
#pragma unroll
            for (int ni = 0; ni < 8; ni++) {
                mma_bf16(c[ni], a0, a1, a2, a3, bh[ni][0], bh[ni][1]);
                mma_bf16(c[ni], a0, a1, a2, a3, bl[ni][0], bl[ni][1]);
                mma_bf16(c[ni], l0, l1, l2, l3, bh[ni][0], bh[ni][1]);
            }
        }

        if (ci + 1 < NCH) {
            uint32_t* Ah = sh + (p ^ 1) * BUFW;
            uint32_t* Al = Ah + CHW;
            uint32_t* Bh = Ah + 2 * CHW;
            uint32_t* Bl = Ah + 3 * CHW;
#pragma unroll
            for (int it = 0; it < 4; it++) {
                int e = tid + it * 512;
                int m = e >> 4, j = e & 15;
                uint32_t h0, l0, h1, l1;
                split2(aR[it].x, aR[it].y, h0, l0);
                split2(aR[it].z, aR[it].w, h1, l1);
                int o = m * ST + j * 2;
                Ah[o] = h0; Ah[o + 1] = h1;
                Al[o] = l0; Al[o + 1] = l1;
            }
#pragma unroll
            for (int it = 0; it < 2; it++) {
                int e = tid + it * 512;
                int n = e >> 3, q = e & 7;
                int o = n * ST + q * 4;
                *(uint4*)(Bh + o) = bRh[it];
                *(uint4*)(Bl + o) = bRl[it];
            }
            __syncthreads();
        }
    }

#pragma unroll
    for (int half = 0; half < 2; half++) {
        int row = row0 + wm * 16 + g + half * 8;
        if (row >= M) continue;
#pragma unroll
        for (int ni = 0; ni < 8; ni++) {
            int col = wn * 64 + ni * 8 + tg * 2;
            float2 o;
            o.x = c[ni][half * 2 + 0] + bias[col];
            o.y = c[ni][half * 2 + 1] + bias[col + 1];
            *(float2*)(g_h + (size_t)row * HID + col) = o;
        }
    }
}

// ---------------- aggregation (unroll 4) -------------------------------------
__global__ void agg_kernel() {
    int node = (blockIdx.x * blockDim.x + threadIdx.x) >> 5;
    int lane = threadIdx.x & 31;
    if (node >= N_NODES) return;
    int s = g_off[node];
    int d = g_deg[node];
    float4 acc = *(const float4*)(g_h + (size_t)node * HID + lane * 4);
    int i = 0;
    for (; i + 4 <= d; i += 4) {
        uint2 e0 = g_edge[s + i];
        uint2 e1 = g_edge[s + i + 1];
        uint2 e2 = g_edge[s + i + 2];
        uint2 e3 = g_edge[s + i + 3];
        float w0 = __uint_as_float(e0.y);
        float w1 = __uint_as_float(e1.y);
        float w2 = __uint_as_float(e2.y);
        float w3 = __uint_as_float(e3.y);
        float4 h0 = *(const float4*)(g_h + (size_t)e0.x * HID + lane * 4);
        float4 h1 = *(const float4*)(g_h + (size_t)e1.x * HID + lane * 4);
        float4 h2 = *(const float4*)(g_h + (size_t)e2.x * HID + lane * 4);
        float4 h3 = *(const float4*)(g_h + (size_t)e3.x * HID + lane * 4);
        acc.x += w0 * h0.x + w1 * h1.x + w2 * h2.x + w3 * h3.x;
        acc.y += w0 * h0.y + w1 * h1.y + w2 * h2.y + w3 * h3.y;
        acc.z += w0 * h0.z + w1 * h1.z + w2 * h2.z + w3 * h3.z;
        acc.w += w0 * h0.w + w1 * h1.w + w2 * h2.w + w3 * h3.w;
    }
    for (; i < d; i++) {
        uint2 e0 = g_edge[s + i];
        float w0 = __uint_as_float(e0.y);
        float4 h0 = *(const float4*)(g_h + (size_t)e0.x * HID + lane * 4);
        acc.x += w0 * h0.x; acc.y += w0 * h0.y;
        acc.z += w0 * h0.z; acc.w += w0 * h0.w;
    }
    *(float4*)(g_z + (size_t)node * HID + lane * 4) = acc;
}

// ------ persistent MLP: 2 async warp-groups share weights (R14) --------------
#define ST2 68
#define BARG() asm volatile("bar.sync %0, %1;" :: "r"(grp + 1), "r"(256) : "memory")
__global__ void __launch_bounds__(512, 1)
mlp_fused_kernel(const uint32_t* __restrict__ W1h, const uint32_t* __restrict__ W1l,
                 const uint32_t* __restrict__ W2h, const uint32_t* __restrict__ W2l,
                 const float* __restrict__ b1, const float* __restrict__ b2, int M) {
    extern __shared__ uint32_t sh[];
    uint32_t* Wh1 = sh + 4 * 64 * ST2;
    uint32_t* Wl1 = Wh1 + 128 * ST2;
    uint32_t* Wh2 = Wl1 + 128 * ST2;
    uint32_t* Wl2 = Wh2 + 128 * ST2;

    const int tid = threadIdx.x, lane = tid & 31, wid = tid >> 5;
    const int grp = wid >> 3;
    const int wg  = wid & 7;
    const int tg_ = tid & 255;
    const int g = lane >> 2, tg = lane & 3;
    const int wm = wg & 3, wn = wg >> 2;

    uint32_t* Ah = sh + grp * 2 * 64 * ST2;
    uint32_t* Al = Ah + 64 * ST2;

    const int lr = lane & 7, lo8 = (lane >> 3) & 1, hi16 = (lane >> 4) & 1;
    const uint32_t AhB  = smem_u32(Ah),  AlB  = smem_u32(Al);
    const uint32_t Wh1B = smem_u32(Wh1), Wl1B = smem_u32(Wl1);
    const uint32_t Wh2B = smem_u32(Wh2), Wl2B = smem_u32(Wl2);
    const int aRowOff = (wm * 16 + lr + 8 * lo8) * ST2 + 4 * hi16;
    const int bRowOff = (wn * 64 + lr + 8 * hi16) * ST2 + 4 * lo8;

#pragma unroll
    for (int it = 0; it < 4; it++) {
        int e = tid + it * 512;
        int n = e >> 4, q = e & 15;
        int o = n * ST2 + q * 4;
        *(uint4*)(Wh1 + o) = *(const uint4*)(W1h + n * 64 + q * 4);
        *(uint4*)(Wl1 + o) = *(const uint4*)(W1l + n * 64 + q * 4);
        *(uint4*)(Wh2 + o) = *(const uint4*)(W2h + n * 64 + q * 4);
        *(uint4*)(Wl2 + o) = *(const uint4*)(W2l + n * 64 + q * 4);
    }
    __syncthreads();

    const int stride = gridDim.x * 2;
    const int t0 = blockIdx.x * 2 + grp;

    float4 zR[8];
    {
        const int row0 = t0 * 64;
#pragma unroll
        for (int it = 0; it < 8; it++) {
            int e = tg_ + it * 256;
            int m = e >> 5, j = e & 31;
            int r = row0 + m;
            zR[it] = make_float4(0.f, 0.f, 0.f, 0.f);
            if (r < M) zR[it] = *(const float4*)(g_z + (size_t)r * HID + j * 4);
        }
    }

    for (int tile = t0; tile < NT64; tile += stride) {
        const int row0 = tile * 64;
        BARG();

#pragma unroll
        for (int it = 0; it < 8; it++) {
            int e = tg_ + it * 256;
            int m = e >> 5, j = e & 31;
            uint32_t h0, l0, h1, l1;
            split2(zR[it].x, zR[it].y, h0, l0);
            split2(zR[it].z, zR[it].w, h1, l1);
            int o = m * ST2 + j * 2;
            Ah[o] = h0; Ah[o + 1] = h1;
            Al[o] = l0; Al[o + 1] = l1;
        }
        if (tile + stride < NT64) {
            const int nrow0 = (tile + stride) * 64;
#pragma unroll
            for (int it = 0; it < 8; it++) {
                int e = tg_ + it * 256;
                int m = e >> 5, j = e & 31;
                int r = nrow0 + m;
                zR[it] = make_float4(0.f, 0.f, 0.f, 0.f);
                if (r < M) zR[it] = *(const float4*)(g_z + (size_t)r * HID + j * 4);
            }
        }
        BARG();

        float c[8][4];
#pragma unroll
        for (int ni = 0; ni < 8; ni++)
#pragma unroll
            for (int q = 0; q < 4; q++) c[ni][q] = 0.f;

        // GEMM1
#pragma unroll
        for (int ks2 = 0; ks2 < 64; ks2 += 8) {
            uint32_t a0, a1, a2, a3, l0, l1, l2, l3;
            ldsm_x4(a0, a1, a2, a3, AhB + (uint32_t)(aRowOff + ks2) * 4u);
            ldsm_x4(l0, l1, l2, l3, AlB + (uint32_t)(aRowOff + ks2) * 4u);
            uint32_t bh[8][2], bl[8][2];
#pragma unroll
            for (int q = 0; q < 4; q++) {
                uint32_t r0, r1, r2, r3;
                ldsm_x4(r0, r1, r2, r3, Wh1B + (uint32_t)(bRowOff + q * 16 * ST2 + ks2) * 4u);
                bh[2 * q][0] = r0; bh[2 * q][1] = r1;
                bh[2 * q + 1][0] = r2; bh[2 * q + 1][1] = r3;
                ldsm_x4(r0, r1, r2, r3, Wl1B + (uint32_t)(bRowOff + q * 16 * ST2 + ks2) * 4u);
                bl[2 * q][0] = r0; bl[2 * q][1] = r1;
                bl[2 * q + 1][0] = r2; bl[2 * q + 1][1] = r3;
            }
#pragma unroll
            for (int ni = 0; ni < 8; ni++) {
                mma_bf16(c[ni], a0, a1, a2, a3, bh[ni][0], bh[ni][1]);
                mma_bf16(c[ni], a0, a1, a2, a3, bl[ni][0], bl[ni][1]);
                mma_bf16(c[ni], l0, l1, l2, l3, bh[ni][0], bh[ni][1]);
            }
        }
        BARG();

#pragma unroll
        for (int ni = 0; ni < 8; ni++) {
            int col = wn * 64 + ni * 8 + tg * 2;
            float bb0 = b1[col], bb1 = b1[col + 1];
            int k2 = wn * 32 + ni * 4 + tg;
            int r0 = wm * 16 + g;
            uint32_t hi, lo;
            split2(fmaxf(c[ni][0] + bb0, 0.f), fmaxf(c[ni][1] + bb1, 0.f), hi, lo);
            Ah[r0 * ST2 + k2] = hi; Al[r0 * ST2 + k2] = lo;
            split2(fmaxf(c[ni][2] + bb0, 0.f), fmaxf(c[ni][3] + bb1, 0.f), hi, lo);
            Ah[(r0 + 8) * ST2 + k2] = hi; Al[(r0 + 8) * ST2 + k2] = lo;
        }
        BARG();

#pragma unroll
        for (int ni = 0; ni < 8; ni++)
#pragma unroll
            for (int q = 0; q < 4; q++) c[ni][q] = 0.f;

        // GEMM2
#pragma unroll
        for (int ks2 = 0; ks2 < 64; ks2 += 8) {
            uint32_t a0, a1, a2, a3, l0, l1, l2, l3;
            ldsm_x4(a0, a1, a2, a3, AhB + (uint32_t)(aRowOff + ks2) * 4u);
            ldsm_x4(l0, l1, l2, l3, AlB + (uint32_t)(aRowOff + ks2) * 4u);
            uint32_t bh[8][2], bl[8][2];
#pragma unroll
            for (int q = 0; q < 4; q++) {
                uint32_t r0, r1, r2, r3;
                ldsm_x4(r0, r1, r2, r3, Wh2B + (uint32_t)(bRowOff + q * 16 * ST2 + ks2) * 4u);
                bh[2 * q][0] = r0; bh[2 * q][1] = r1;
                bh[2 * q + 1][0] = r2; bh[2 * q + 1][1] = r3;
                ldsm_x4(r0, r1, r2, r3, Wl2B + (uint32_t)(bRowOff + q * 16 * ST2 + ks2) * 4u);
                bl[2 * q][0] = r0; bl[2 * q][1] = r1;
                bl[2 * q + 1][0] = r2; bl[2 * q + 1][1] = r3;
            }
#pragma unroll
            for (int ni = 0; ni < 8; ni++) {
                mma_bf16(c[ni], a0, a1, a2, a3, bh[ni][0], bh[ni][1]);
                mma_bf16(c[ni], a0, a1, a2, a3, bl[ni][0], bl[ni][1]);
                mma_bf16(c[ni], l0, l1, l2, l3, bh[ni][0], bh[ni][1]);
            }
        }

#pragma unroll
        for (int half = 0; half < 2; half++) {
            int row = row0 + wm * 16 + g + half * 8;
            if (row >= M) continue;
#pragma unroll
            for (int ni = 0; ni < 8; ni++) {
                int col = wn * 64 + ni * 8 + tg * 2;
                float2 o;
                o.x = fmaxf(c[ni][half * 2 + 0] + b2[col], 0.f);
                o.y = fmaxf(c[ni][half * 2 + 1] + b2[col + 1], 0.f);
                *(float2*)(g_h + (size_t)row * HID + col) = o;
            }
        }
    }
}

// ---------------- MMA readout (R13) ------------------------------------------
__global__ void __launch_bounds__(256, 2)
readout_mma_kernel(const float* __restrict__ br, float* __restrict__ out, int M) {
    extern __shared__ uint32_t sh[];
    uint32_t* Ah = sh;
    uint32_t* Al = sh + 128 * ST2;
    uint32_t* Rh = sh + 2 * 128 * ST2;
    uint32_t* Rl = sh + 2 * 128 * ST2 + 64 * ST2;

    const int tid = threadIdx.x, lane = tid & 31, wid = tid >> 5;
    const int g = lane >> 2, tg = lane & 3;
    const int wm = wid;
    const int row0 = blockIdx.x * 128;

    const int lr = lane & 7, lo8 = (lane >> 3) & 1, hi16 = (lane >> 4) & 1;
    const uint32_t AhB = smem_u32(Ah), AlB = smem_u32(Al);
    const uint32_t RhB = smem_u32(Rh), RlB = smem_u32(Rl);
    const int aRowOff = (wm * 16 + lr + 8 * lo8) * ST2 + 4 * hi16;
    const int bRowOff = (lr + 8 * hi16) * ST2 + 4 * lo8;

#pragma unroll
    for (int it = 0; it < 16; it++) {
        int e = tid + it * 256;
        int m = e >> 5, j = e & 31;
        int r = row0 + m;
        float4 v = make_float4(0.f, 0.f, 0.f, 0.f);
        if (r < M) v = *(const float4*)(g_h + (size_t)r * HID + j * 4);
        uint32_t h0, l0, h1, l1;
        split2(v.x, v.y, h0, l0);
        split2(v.z, v.w, h1, l1);
        int o = m * ST2 + j * 2;
        Ah[o] = h0; Ah[o + 1] = h1;
        Al[o] = l0; Al[o + 1] = l1;
    }
#pragma unroll
    for (int it = 0; it < 4; it++) {
        int e = tid + it * 256;
        int n = e >> 4, q = e & 15;
        int o = n * ST2 + q * 4;
        *(uint4*)(Rh + o) = *(const uint4*)(g_roh + n * 64 + q * 4);
        *(uint4*)(Rl + o) = *(const uint4*)(g_rol + n * 64 + q * 4);
    }
    __syncthreads();

    float c[5][4];
#pragma unroll
    for (int ni = 0; ni < 5; ni++)
#pragma unroll
        for (int q = 0; q < 4; q++) c[ni][q] = 0.f;

#pragma unroll
    for (int ks2 = 0; ks2 < 64; ks2 += 8) {
        uint32_t a0, a1, a2, a3, l0, l1, l2, l3;
        ldsm_x4(a0, a1, a2, a3, AhB + (uint32_t)(aRowOff + ks2) * 4u);
        ldsm_x4(l0, l1, l2, l3, AlB + (uint32_t)(aRowOff + ks2) * 4u);
        uint32_t bh[6][2], bl[6][2];
#pragma unroll
        for (int q = 0; q < 3; q++) {
            uint32_t r0, r1, r2, r3;
            ldsm_x4(r0, r1, r2, r3, RhB + (uint32_t)(bRowOff + q * 16 * ST2 + ks2) * 4u);
            bh[2 * q][0] = r0; bh[2 * q][1] = r1;
            bh[2 * q + 1][0] = r2; bh[2 * q + 1][1] = r3;
            ldsm_x4(r0, r1, r2, r3, RlB + (uint32_t)(bRowOff + q * 16 * ST2 + ks2) * 4u);
            bl[2 * q][0] = r0; bl[2 * q][1] = r1;
            bl[2 * q + 1][0] = r2; bl[2 * q + 1][1] = r3;
        }
#pragma unroll
        for (int ni = 0; ni < 5; ni++) {
            mma_bf16(c[ni], a0, a1, a2, a3, bh[ni][0], bh[ni][1]);
            mma_bf16(c[ni], a0, a1, a2, a3, bl[ni][0], bl[ni][1]);
            mma_bf16(c[ni], l0, l1, l2, l3, bh[ni][0], bh[ni][1]);
        }
    }

#pragma unroll
    for (int half = 0; half < 2; half++) {
        int row = row0 + wm * 16 + g + half * 8;
        if (row >= M) continue;
#pragma unroll
        for (int ni = 0; ni < 5; ni++) {
            int col = ni * 8 + tg * 2;
            if (col >= OUT_DIM) continue;
            float2 o;
            o.x = c[ni][half * 2 + 0] + br[col];
            o.y = c[ni][half * 2 + 1] + br[col + 1];
            *(float2*)(out + (size_t)row * OUT_DIM + col) = o;
        }
    }
}

// ---------------- launch ----------------------------------------------------
extern "C" void kernel_launch(void* const* d_in, const int* in_sizes, int n_in,
                              void* d_out, int out_size) {
    const float* features = (const float*)d_in[0];
    const int*   src      = (const int*)  d_in[1];
    const int*   dst      = (const int*)  d_in[2];
    const float* edge_w   = (const float*)d_in[3];
    const float* emb_W    = (const float*)d_in[4];
    const float* emb_b    = (const float*)d_in[5];
    const float* W1       = (const float*)d_in[6];
    const float* b1       = (const float*)d_in[7];
    const float* W2       = (const float*)d_in[8];
    const float* b2       = (const float*)d_in[9];
    const float* ro_W     = (const float*)d_in[10];
    const float* ro_b     = (const float*)d_in[11];
    float* out = (float*)d_out;

    const int emb_smem = 2 * 4 * 128 * ST * (int)sizeof(uint32_t);
    const int mlp_smem = (4 * 64 + 4 * 128) * ST2 * (int)sizeof(uint32_t);
    const int ro_smem  = (2 * 128 + 2 * 64) * ST2 * (int)sizeof(uint32_t);
    cudaFuncSetAttribute(emb_gemm_kernel,    cudaFuncAttributeMaxDynamicSharedMemorySize, emb_smem);
    cudaFuncSetAttribute(mlp_fused_kernel,   cudaFuncAttributeMaxDynamicSharedMemorySize, mlp_smem);
    cudaFuncSetAttribute(readout_mma_kernel, cudaFuncAttributeMaxDynamicSharedMemorySize, ro_smem);

    uint32_t *d_W1h, *d_W1l, *d_W2h, *d_W2l;
    cudaGetSymbolAddress((void**)&d_W1h, g_W1h);
    cudaGetSymbolAddress((void**)&d_W1l, g_W1l);
    cudaGetSymbolAddress((void**)&d_W2h, g_W2h);
    cudaGetSymbolAddress((void**)&d_W2l, g_W2l);

    cudaStream_t side = cudaStreamPerThread;
    cudaEvent_t evA, evB;
    cudaEventCreateWithFlags(&evA, cudaEventDisableTiming);
    cudaEventCreateWithFlags(&evB, cudaEventDisableTiming);

    cudaEventRecord(evA, 0);
    cudaStreamWaitEvent(side, evA, 0);

    prep_all_kernel<<<(PREP_TOTAL + 255) / 256, 256>>>(emb_W, W1, W2, ro_W);  // main
    zero_deg_kernel<<<(N_NODES + 255) / 256, 256, 0, side>>>();               // side
    emb_gemm_kernel<<<N_TILES, 512, emb_smem>>>(features, emb_b, N_NODES);    // main
    hist_kernel<<<(N_EDGES + 255) / 256, 256, 0, side>>>(dst);
    scan1_kernel<<<NB_SCAN, 1024, 0, side>>>();
    scan23_kernel<<<NB_SCAN, 1024, 0, side>>>();
    scatter_kernel<<<(N_EDGES + 255) / 256, 256, 0, side>>>(src, dst, edge_w);

    cudaEventRecord(evB, side);
    cudaStreamWaitEvent(0, evB, 0);

    const int agg_blocks = (N_NODES * 32 + 255) / 256;
    for (int l = 0; l < N_LAYERS; l++) {
        agg_kernel<<<agg_blocks, 256>>>();
        mlp_fused_kernel<<<148, 512, mlp_smem>>>(
            d_W1h + (size_t)l * HID * 64, d_W1l + (size_t)l * HID * 64,
            d_W2h + (size_t)l * HID * 64, d_W2l + (size_t)l * HID * 64,
            b1 + (size_t)l * HID, b2 + (size_t)l * HID, N_NODES);
    }
    readout_mma_kernel<<<N_TILES, 256, ro_smem>>>(ro_b, out, N_NODES);
}

// round 16
// speedup vs baseline: 1.4186x; 1.0285x over previous
#include <cuda_runtime.h>
#include <cuda_bf16.h>
#include <cstdint>

#define N_NODES 50000
#define N_EDGES 625000
#define IN_DIM  512
#define HID     128
#define OUT_DIM 40
#define N_LAYERS 3
#define NB_SCAN ((N_NODES + 1023) / 1024)
#define N_TILES ((N_NODES + 127) / 128)
#define NT64 ((N_NODES + 63) / 64)

// ---------------- scratch ---------------------------------------------------
__device__ float g_h[N_NODES * HID];
__device__ float g_z[N_NODES * HID];
__device__ int   g_deg[N_NODES];
__device__ int   g_off[N_NODES];
__device__ int   g_cur[N_NODES];
__device__ uint2 g_edge[N_EDGES];
__device__ int   g_bsum[64];
__device__ uint32_t g_eBh[HID * (IN_DIM / 2)];
__device__ uint32_t g_eBl[HID * (IN_DIM / 2)];
__device__ uint32_t g_W1h[N_LAYERS * HID * (HID / 2)];
__device__ uint32_t g_W1l[N_LAYERS * HID * (HID / 2)];
__device__ uint32_t g_W2h[N_LAYERS * HID * (HID / 2)];
__device__ uint32_t g_W2l[N_LAYERS * HID * (HID / 2)];
__device__ uint32_t g_roh[64 * 64];
__device__ uint32_t g_rol[64 * 64];

// ---------------- helpers ----------------------------------------------------
__device__ __forceinline__ uint32_t smem_u32(const void* p) {
    uint32_t a;
    asm("{ .reg .u64 t; cvta.to.shared.u64 t, %1; cvt.u32.u64 %0, t; }" : "=r"(a) : "l"(p));
    return a;
}
__device__ __forceinline__ void split2(float v0, float v1, uint32_t& hi, uint32_t& lo) {
    uint16_t h0, h1, l0, l1;
    asm("cvt.rn.bf16.f32 %0, %1;" : "=h"(h0) : "f"(v0));
    asm("cvt.rn.bf16.f32 %0, %1;" : "=h"(h1) : "f"(v1));
    float r0 = v0 - __uint_as_float((uint32_t)h0 << 16);
    float r1 = v1 - __uint_as_float((uint32_t)h1 << 16);
    asm("cvt.rn.bf16.f32 %0, %1;" : "=h"(l0) : "f"(r0));
    asm("cvt.rn.bf16.f32 %0, %1;" : "=h"(l1) : "f"(r1));
    hi = ((uint32_t)h1 << 16) | h0;
    lo = ((uint32_t)l1 << 16) | l0;
}
__device__ __forceinline__ void mma_bf16(float* c, uint32_t a0, uint32_t a1,
                                         uint32_t a2, uint32_t a3,
                                         uint32_t b0, uint32_t b1) {
    asm volatile("mma.sync.aligned.m16n8k16.row.col.f32.bf16.bf16.f32 "
                 "{%0,%1,%2,%3}, {%4,%5,%6,%7}, {%8,%9}, {%0,%1,%2,%3};"
                 : "+f"(c[0]), "+f"(c[1]), "+f"(c[2]), "+f"(c[3])
                 : "r"(a0), "r"(a1), "r"(a2), "r"(a3), "r"(b0), "r"(b1));
}
__device__ __forceinline__ void ldsm_x4(uint32_t& r0, uint32_t& r1, uint32_t& r2,
                                        uint32_t& r3, uint32_t addr) {
    asm volatile("ldmatrix.sync.aligned.m8n8.x4.shared.b16 {%0,%1,%2,%3}, [%4];"
                 : "=r"(r0), "=r"(r1), "=r"(r2), "=r"(r3) : "r"(addr));
}

// ---------------- CSR build -------------------------------------------------
__global__ void zero_deg_kernel() {
    int i = blockIdx.x * blockDim.x + threadIdx.x;
    if (i < N_NODES) g_deg[i] = 0;
}
__global__ void hist_kernel(const int* __restrict__ dst) {
    int e = blockIdx.x * blockDim.x + threadIdx.x;
    if (e < N_EDGES) atomicAdd(&g_deg[dst[e]], 1);
}
__global__ void scan1_kernel() {
    __shared__ int s[1024];
    int t = threadIdx.x;
    int i = blockIdx.x * 1024 + t;
    int v = (i < N_NODES) ? g_deg[i] : 0;
    s[t] = v;
    __syncthreads();
    for (int d = 1; d < 1024; d <<= 1) {
        int tmp = (t >= d) ? s[t - d] : 0;
        __syncthreads();
        s[t] += tmp;
        __syncthreads();
    }
    if (i < N_NODES) g_off[i] = s[t] - v;
    if (t == 1023) g_bsum[blockIdx.x] = s[1023];
}
__global__ void scan23_kernel() {
    __shared__ int red[64];
    __shared__ int base_s;
    int t = threadIdx.x;
    if (t < 64) red[t] = (t < NB_SCAN && t < (int)blockIdx.x) ? g_bsum[t] : 0;
    __syncthreads();
    if (t < 32) {
        int s = red[t] + red[t + 32];
        for (int d = 16; d > 0; d >>= 1) s += __shfl_down_sync(0xffffffffu, s, d);
        if (t == 0) base_s = s;
    }
    __syncthreads();
    int i = blockIdx.x * 1024 + t;
    if (i < N_NODES) {
        int o = g_off[i] + base_s;
        g_off[i] = o;
        g_cur[i] = o;
    }
}
__global__ void scatter_kernel(const int* __restrict__ src,
                               const int* __restrict__ dst,
                               const float* __restrict__ ew) {
    int e = blockIdx.x * blockDim.x + threadIdx.x;
    if (e < N_EDGES) {
        int d = dst[e];
        int pos = atomicAdd(&g_cur[d], 1);
        g_edge[pos] = make_uint2((uint32_t)src[e], __float_as_uint(ew[e]));
    }
}

// ---------------- merged weight prep -----------------------------------------
__global__ void prep_all_kernel(const float* __restrict__ We,
                                const float* __restrict__ W1,
                                const float* __restrict__ W2,
                                const float* __restrict__ Wr) {
    int idx = blockIdx.x * blockDim.x + threadIdx.x;
    uint32_t hi, lo;
    if (idx < 32768) {
        int n = idx >> 8, k2 = idx & 255;
        split2(We[(size_t)(2 * k2) * HID + n], We[(size_t)(2 * k2 + 1) * HID + n], hi, lo);
        g_eBh[idx] = hi;
        g_eBl[idx] = lo;
    } else if (idx < 32768 + N_LAYERS * HID * 64) {
        int j = idx - 32768;
        int l = j / (HID * 64);
        int rem = j - l * HID * 64;
        int n = rem >> 6, k2 = rem & 63;
        const float* w1 = W1 + (size_t)l * HID * HID;
        const float* w2 = W2 + (size_t)l * HID * HID;
        split2(w1[(2 * k2) * HID + n], w1[(2 * k2 + 1) * HID + n], hi, lo);
        g_W1h[j] = hi; g_W1l[j] = lo;
        split2(w2[(2 * k2) * HID + n], w2[(2 * k2 + 1) * HID + n], hi, lo);
        g_W2h[j] = hi; g_W2l[j] = lo;
    } else if (idx < 32768 + N_LAYERS * HID * 64 + 4096) {
        int j = idx - 32768 - N_LAYERS * HID * 64;
        int n = j >> 6, k2 = j & 63;
        hi = 0; lo = 0;
        if (n < OUT_DIM)
            split2(Wr[(2 * k2) * OUT_DIM + n], Wr[(2 * k2 + 1) * OUT_DIM + n], hi, lo);
        g_roh[j] = hi;
        g_rol[j] = lo;
    }
}
#define PREP_TOTAL (32768 + N_LAYERS * HID * 64 + 4096)

// ---------------- emb GEMM: double-buffered k-loop (R9) ---------------------
#define ST 36
#define CHW (128 * ST)
#define BUFW (4 * CHW)
__global__ void __launch_bounds__(512, 1)
emb_gemm_kernel(const float* __restrict__ A, const float* __restrict__ bias, int M) {
    extern __shared__ uint32_t sh[];

    const int tid = threadIdx.x, lane = tid & 31, wid = tid >> 5;
    const int g = lane >> 2, tg = lane & 3;
    const int wm = wid & 7, wn = wid >> 3;
    const int row0 = blockIdx.x * 128;

    const int lr = lane & 7, lo8 = (lane >> 3) & 1, hi16 = (lane >> 4) & 1;
    const uint32_t shB = smem_u32(sh);
    const int aRowOff = (wm * 16 + lr + 8 * lo8) * ST + 4 * hi16;
    const int bRowOff = (wn * 64 + lr + 8 * hi16) * ST + 4 * lo8;

    float4 aR[4];
    uint4  bRh[2], bRl[2];

#pragma unroll
    for (int it = 0; it < 4; it++) {
        int e = tid + it * 512;
        int m = e >> 4, j = e & 15;
        int r = row0 + m;
        aR[it] = make_float4(0.f, 0.f, 0.f, 0.f);
        if (r < M) aR[it] = *(const float4*)(A + (size_t)r * IN_DIM + j * 4);
    }
#pragma unroll
    for (int it = 0; it < 2; it++) {
        int e = tid + it * 512;
        int n = e >> 3, q = e & 7;
        bRh[it] = *(const uint4*)(g_eBh + n * 256 + q * 4);
        bRl[it] = *(const uint4*)(g_eBl + n * 256 + q * 4);
    }
    {
        uint32_t* Ah = sh;            uint32_t* Al = sh + CHW;
        uint32_t* Bh = sh + 2 * CHW;  uint32_t* Bl = sh + 3 * CHW;
#pragma unroll
        for (int it = 0; it < 4; it++) {
            int e = tid + it * 512;
            int m = e >> 4, j = e & 15;
            uint32_t h0, l0, h1, l1;
            split2(aR[it].x, aR[it].y, h0, l0);
            split2(aR[it].z, aR[it].w, h1, l1);
            int o = m * ST + j * 2;
            Ah[o] = h0; Ah[o + 1] = h1;
            Al[o] = l0; Al[o + 1] = l1;
        }
#pragma unroll
        for (int it = 0; it < 2; it++) {
            int e = tid + it * 512;
            int n = e >> 3, q = e & 7;
            int o = n * ST + q * 4;
            *(uint4*)(Bh + o) = bRh[it];
            *(uint4*)(Bl + o) = bRl[it];
        }
    }
    __syncthreads();

    float c[8][4];
#pragma unroll
    for (int ni = 0; ni < 8; ni++)
#pragma unroll
        for (int q = 0; q < 4; q++) c[ni][q] = 0.f;

    const int NCH = IN_DIM / 64;
    for (int ci = 0; ci < NCH; ci++) {
        const int p = ci & 1;
        const uint32_t base = shB + (uint32_t)p * BUFW * 4u;
        const uint32_t AhB = base, AlB = base + CHW * 4u;
        const uint32_t BhB = base + 2u * CHW * 4u, BlB = base + 3u * CHW * 4u;

        if (ci + 1 < NCH) {
            int kn = (ci + 1) * 64, kn2 = kn >> 1;
#pragma unroll
            for (int it = 0; it < 4; it++) {
                int e = tid + it * 512;
                int m = e >> 4, j = e & 15;
                int r = row0 + m;
                aR[it] = make_float4(0.f, 0.f, 0.f, 0.f);
                if (r < M) aR[it] = *(const float4*)(A + (size_t)r * IN_DIM + kn + j * 4);
            }
#pragma unroll
            for (int it = 0; it < 2; it++) {
                int e = tid + it * 512;
                int n = e >> 3, q = e & 7;
                bRh[it] = *(const uint4*)(g_eBh + n * 256 + kn2 + q * 4);
                bRl[it] = *(const uint4*)(g_eBl + n * 256 + kn2 + q * 4);
            }
        }

#pragma unroll
        for (int ks2 = 0; ks2 < 32; ks2 += 8) {
            uint32_t a0, a1, a2, a3, l0, l1, l2, l3;
            ldsm_x4(a0, a1, a2, a3, AhB + (uint32_t)(aRowOff + ks2) * 4u);
            ldsm_x4(l0, l1, l2, l3, AlB + (uint32_t)(aRowOff + ks2) * 4u);
            uint32_t bh[8][2], bl[8][2];
#pragma unroll
            for (int q = 0; q < 4; q++) {
                uint32_t r0, r1, r2, r3;
                ldsm_x4(r0, r1, r2, r3, BhB + (uint32_t)(bRowOff + q * 16 * ST + ks2) * 4u);
                bh[2 * q][0] = r0; bh[2 * q][1] = r1;
                bh[2 * q + 1][0] = r2; bh[2 * q + 1][1] = r3;
                ldsm_x4(r0, r1, r2, r3, BlB + (uint32_t)(bRowOff + q * 16 * ST + ks2) * 4u);
                bl[2 * q][0] = r0; bl[2 * q][1] = r1;
                bl[2 * q + 1][0] = r2; bl[2 * q + 1][1] = r3;
            }
#pragma unroll
            for (int ni = 0; ni < 8; ni++) {
                mma_bf16(c[ni], a0, a1, a2, a3, bh[ni][0], bh[ni][1]);
                mma_bf16(c[ni], a0, a1, a2, a3, bl[ni][0], bl[ni][1]);
                mma_bf16(c[ni], l0, l1, l2, l3, bh[ni][0], bh[ni][1]);
            }
        }

        if (ci + 1 < NCH) {
            uint32_t* Ah = sh + (p ^ 1) * BUFW;
            uint32_t* Al = Ah + CHW;
            uint32_t* Bh = Ah + 2 * CHW;
            uint32_t* Bl = Ah + 3 * CHW;
#pragma unroll
            for (int it = 0; it < 4; it++) {
                int e = tid + it * 512;
                int m = e >> 4, j = e & 15;
                uint32_t h0, l0, h1, l1;
                split2(aR[it].x, aR[it].y, h0, l0);
                split2(aR[it].z, aR[it].w, h1, l1);
                int o = m * ST + j * 2;
                Ah[o] = h0; Ah[o + 1] = h1;
                Al[o] = l0; Al[o + 1] = l1;
            }
#pragma unroll
            for (int it = 0; it < 2; it++) {
                int e = tid + it * 512;
                int n = e >> 3, q = e & 7;
                int o = n * ST + q * 4;
                *(uint4*)(Bh + o) = bRh[it];
                *(uint4*)(Bl + o) = bRl[it];
            }
            __syncthreads();
        }
    }

#pragma unroll
    for (int half = 0; half < 2; half++) {
        int row = row0 + wm * 16 + g + half * 8;
        if (row >= M) continue;
#pragma unroll
        for (int ni = 0; ni < 8; ni++) {
            int col = wn * 64 + ni * 8 + tg * 2;
            float2 o;
            o.x = c[ni][half * 2 + 0] + bias[col];
            o.y = c[ni][half * 2 + 1] + bias[col + 1];
            *(float2*)(g_h + (size_t)row * HID + col) = o;
        }
    }
}

// ---------------- aggregation (unroll 4, PDL-aware) --------------------------
__global__ void agg_kernel() {
    cudaGridDependencySynchronize();
    int node = (blockIdx.x * blockDim.x + threadIdx.x) >> 5;
    int lane = threadIdx.x & 31;
    if (node >= N_NODES) return;
    int s = g_off[node];
    int d = g_deg[node];
    float4 acc = *(const float4*)(g_h + (size_t)node * HID + lane * 4);
    int i = 0;
    for (; i + 4 <= d; i += 4) {
        uint2 e0 = g_edge[s + i];
        uint2 e1 = g_edge[s + i + 1];
        uint2 e2 = g_edge[s + i + 2];
        uint2 e3 = g_edge[s + i + 3];
        float w0 = __uint_as_float(e0.y);
        float w1 = __uint_as_float(e1.y);
        float w2 = __uint_as_float(e2.y);
        float w3 = __uint_as_float(e3.y);
        float4 h0 = *(const float4*)(g_h + (size_t)e0.x * HID + lane * 4);
        float4 h1 = *(const float4*)(g_h + (size_t)e1.x * HID + lane * 4);
        float4 h2 = *(const float4*)(g_h + (size_t)e2.x * HID + lane * 4);
        float4 h3 = *(const float4*)(g_h + (size_t)e3.x * HID + lane * 4);
        acc.x += w0 * h0.x + w1 * h1.x + w2 * h2.x + w3 * h3.x;
        acc.y += w0 * h0.y + w1 * h1.y + w2 * h2.y + w3 * h3.y;
        acc.z += w0 * h0.z + w1 * h1.z + w2 * h2.z + w3 * h3.z;
        acc.w += w0 * h0.w + w1 * h1.w + w2 * h2.w + w3 * h3.w;
    }
    for (; i < d; i++) {
        uint2 e0 = g_edge[s + i];
        float w0 = __uint_as_float(e0.y);
        float4 h0 = *(const float4*)(g_h + (size_t)e0.x * HID + lane * 4);
        acc.x += w0 * h0.x; acc.y += w0 * h0.y;
        acc.z += w0 * h0.z; acc.w += w0 * h0.w;
    }
    *(float4*)(g_z + (size_t)node * HID + lane * 4) = acc;
}

// ------ persistent MLP: 2 async warp-groups, PDL weight-staging prologue -----
#define ST2 68
#define BARG() asm volatile("bar.sync %0, %1;" :: "r"(grp + 1), "r"(256) : "memory")
__global__ void __launch_bounds__(512, 1)
mlp_fused_kernel(const uint32_t* __restrict__ W1h, const uint32_t* __restrict__ W1l,
                 const uint32_t* __restrict__ W2h, const uint32_t* __restrict__ W2l,
                 const float* __restrict__ b1, const float* __restrict__ b2, int M) {
    extern __shared__ uint32_t sh[];
    uint32_t* Wh1 = sh + 4 * 64 * ST2;
    uint32_t* Wl1 = Wh1 + 128 * ST2;
    uint32_t* Wh2 = Wl1 + 128 * ST2;
    uint32_t* Wl2 = Wh2 + 128 * ST2;

    const int tid = threadIdx.x, lane = tid & 31, wid = tid >> 5;
    const int grp = wid >> 3;
    const int wg  = wid & 7;
    const int tg_ = tid & 255;
    const int g = lane >> 2, tg = lane & 3;
    const int wm = wg & 3, wn = wg >> 2;

    uint32_t* Ah = sh + grp * 2 * 64 * ST2;
    uint32_t* Al = Ah + 64 * ST2;

    const int lr = lane & 7, lo8 = (lane >> 3) & 1, hi16 = (lane >> 4) & 1;
    const uint32_t AhB  = smem_u32(Ah),  AlB  = smem_u32(Al);
    const uint32_t Wh1B = smem_u32(Wh1), Wl1B = smem_u32(Wl1);
    const uint32_t Wh2B = smem_u32(Wh2), Wl2B = smem_u32(Wl2);
    const int aRowOff = (wm * 16 + lr + 8 * lo8) * ST2 + 4 * hi16;
    const int bRowOff = (wn * 64 + lr + 8 * hi16) * ST2 + 4 * lo8;

    // independent prologue: weight staging (g_W* written long before)
#pragma unroll
    for (int it = 0; it < 4; it++) {
        int e = tid + it * 512;
        int n = e >> 4, q = e & 15;
        int o = n * ST2 + q * 4;
        *(uint4*)(Wh1 + o) = *(const uint4*)(W1h + n * 64 + q * 4);
        *(uint4*)(Wl1 + o) = *(const uint4*)(W1l + n * 64 + q * 4);
        *(uint4*)(Wh2 + o) = *(const uint4*)(W2h + n * 64 + q * 4);
        *(uint4*)(Wl2 + o) = *(const uint4*)(W2l + n * 64 + q * 4);
    }
    cudaGridDependencySynchronize();   // wait for producer (agg) completion
    __syncthreads();

    const int stride = gridDim.x * 2;
    const int t0 = blockIdx.x * 2 + grp;

    float4 zR[8];
    {
        const int row0 = t0 * 64;
#pragma unroll
        for (int it = 0; it < 8; it++) {
            int e = tg_ + it * 256;
            int m = e >> 5, j = e & 31;
            int r = row0 + m;
            zR[it] = make_float4(0.f, 0.f, 0.f, 0.f);
            if (r < M) zR[it] = *(const float4*)(g_z + (size_t)r * HID + j * 4);
        }
    }

    for (int tile = t0; tile < NT64; tile += stride) {
        const int row0 = tile * 64;
        BARG();

#pragma unroll
        for (int it = 0; it < 8; it++) {
            int e = tg_ + it * 256;
            int m = e >> 5, j = e & 31;
            uint32_t h0, l0, h1, l1;
            split2(zR[it].x, zR[it].y, h0, l0);
            split2(zR[it].z, zR[it].w, h1, l1);
            int o = m * ST2 + j * 2;
            Ah[o] = h0; Ah[o + 1] = h1;
            Al[o] = l0; Al[o + 1] = l1;
        }
        if (tile + stride < NT64) {
            const int nrow0 = (tile + stride) * 64;
#pragma unroll
            for (int it = 0; it < 8; it++) {
                int e = tg_ + it * 256;
                int m = e >> 5, j = e & 31;
                int r = nrow0 + m;
                zR[it] = make_float4(0.f, 0.f, 0.f, 0.f);
                if (r < M) zR[it] = *(const float4*)(g_z + (size_t)r * HID + j * 4);
            }
        }
        BARG();

        float c[8][4];
#pragma unroll
        for (int ni = 0; ni < 8; ni++)
#pragma unroll
            for (int q = 0; q < 4; q++) c[ni][q] = 0.f;

        // GEMM1
#pragma unroll
        for (int ks2 = 0; ks2 < 64; ks2 += 8) {
            uint32_t a0, a1, a2, a3, l0, l1, l2, l3;
            ldsm_x4(a0, a1, a2, a3, AhB + (uint32_t)(aRowOff + ks2) * 4u);
            ldsm_x4(l0, l1, l2, l3, AlB + (uint32_t)(aRowOff + ks2) * 4u);
            uint32_t bh[8][2], bl[8][2];
#pragma unroll
            for (int q = 0; q < 4; q++) {
                uint32_t r0, r1, r2, r3;
                ldsm_x4(r0, r1, r2, r3, Wh1B + (uint32_t)(bRowOff + q * 16 * ST2 + ks2) * 4u);
                bh[2 * q][0] = r0; bh[2 * q][1] = r1;
                bh[2 * q + 1][0] = r2; bh[2 * q + 1][1] = r3;
                ldsm_x4(r0, r1, r2, r3, Wl1B + (uint32_t)(bRowOff + q * 16 * ST2 + ks2) * 4u);
                bl[2 * q][0] = r0; bl[2 * q][1] = r1;
                bl[2 * q + 1][0] = r2; bl[2 * q + 1][1] = r3;
            }
#pragma unroll
            for (int ni = 0; ni < 8; ni++) {
                mma_bf16(c[ni], a0, a1, a2, a3, bh[ni][0], bh[ni][1]);
                mma_bf16(c[ni], a0, a1, a2, a3, bl[ni][0], bl[ni][1]);
                mma_bf16(c[ni], l0, l1, l2, l3, bh[ni][0], bh[ni][1]);
            }
        }
        BARG();

#pragma unroll
        for (int ni = 0; ni < 8; ni++) {
            int col = wn * 64 + ni * 8 + tg * 2;
            float bb0 = b1[col], bb1 = b1[col + 1];
            int k2 = wn * 32 + ni * 4 + tg;
            int r0 = wm * 16 + g;
            uint32_t hi, lo;
            split2(fmaxf(c[ni][0] + bb0, 0.f), fmaxf(c[ni][1] + bb1, 0.f), hi, lo);
            Ah[r0 * ST2 + k2] = hi; Al[r0 * ST2 + k2] = lo;
            split2(fmaxf(c[ni][2] + bb0, 0.f), fmaxf(c[ni][3] + bb1, 0.f), hi, lo);
            Ah[(r0 + 8) * ST2 + k2] = hi; Al[(r0 + 8) * ST2 + k2] = lo;
        }
        BARG();

#pragma unroll
        for (int ni = 0; ni < 8; ni++)
#pragma unroll
            for (int q = 0; q < 4; q++) c[ni][q] = 0.f;

        // GEMM2
#pragma unroll
        for (int ks2 = 0; ks2 < 64; ks2 += 8) {
            uint32_t a0, a1, a2, a3, l0, l1, l2, l3;
            ldsm_x4(a0, a1, a2, a3, AhB + (uint32_t)(aRowOff + ks2) * 4u);
            ldsm_x4(l0, l1, l2, l3, AlB + (uint32_t)(aRowOff + ks2) * 4u);
            uint32_t bh[8][2], bl[8][2];
#pragma unroll
            for (int q = 0; q < 4; q++) {
                uint32_t r0, r1, r2, r3;
                ldsm_x4(r0, r1, r2, r3, Wh2B + (uint32_t)(bRowOff + q * 16 * ST2 + ks2) * 4u);
                bh[2 * q][0] = r0; bh[2 * q][1] = r1;
                bh[2 * q + 1][0] = r2; bh[2 * q + 1][1] = r3;
                ldsm_x4(r0, r1, r2, r3, Wl2B + (uint32_t)(bRowOff + q * 16 * ST2 + ks2) * 4u);
                bl[2 * q][0] = r0; bl[2 * q][1] = r1;
                bl[2 * q + 1][0] = r2; bl[2 * q + 1][1] = r3;
            }
#pragma unroll
            for (int ni = 0; ni < 8; ni++) {
                mma_bf16(c[ni], a0, a1, a2, a3, bh[ni][0], bh[ni][1]);
                mma_bf16(c[ni], a0, a1, a2, a3, bl[ni][0], bl[ni][1]);
                mma_bf16(c[ni], l0, l1, l2, l3, bh[ni][0], bh[ni][1]);
            }
        }

#pragma unroll
        for (int half = 0; half < 2; half++) {
            int row = row0 + wm * 16 + g + half * 8;
            if (row >= M) continue;
#pragma unroll
            for (int ni = 0; ni < 8; ni++) {
                int col = wn * 64 + ni * 8 + tg * 2;
                float2 o;
                o.x = fmaxf(c[ni][half * 2 + 0] + b2[col], 0.f);
                o.y = fmaxf(c[ni][half * 2 + 1] + b2[col + 1], 0.f);
                *(float2*)(g_h + (size_t)row * HID + col) = o;
            }
        }
    }
}

// ---------------- MMA readout (PDL: ro staging first) -------------------------
__global__ void __launch_bounds__(256, 2)
readout_mma_kernel(const float* __restrict__ br, float* __restrict__ out, int M) {
    extern __shared__ uint32_t sh[];
    uint32_t* Ah = sh;
    uint32_t* Al = sh + 128 * ST2;
    uint32_t* Rh = sh + 2 * 128 * ST2;
    uint32_t* Rl = sh + 2 * 128 * ST2 + 64 * ST2;

    const int tid = threadIdx.x, lane = tid & 31, wid = tid >> 5;
    const int g = lane >> 2, tg = lane & 3;
    const int wm = wid;
    const int row0 = blockIdx.x * 128;

    const int lr = lane & 7, lo8 = (lane >> 3) & 1, hi16 = (lane >> 4) & 1;
    const uint32_t AhB = smem_u32(Ah), AlB = smem_u32(Al);
    const uint32_t RhB = smem_u32(Rh), RlB = smem_u32(Rl);
    const int aRowOff = (wm * 16 + lr + 8 * lo8) * ST2 + 4 * hi16;
    const int bRowOff = (lr + 8 * hi16) * ST2 + 4 * lo8;

    // independent prologue: stage ro weights
#pragma unroll
    for (int it = 0; it < 4; it++) {
        int e = tid + it * 256;
        int n = e >> 4, q = e & 15;
        int o = n * ST2 + q * 4;
        *(uint4*)(Rh + o) = *(const uint4*)(g_roh + n * 64 + q * 4);
        *(uint4*)(Rl + o) = *(const uint4*)(g_rol + n * 64 + q * 4);
    }
    cudaGridDependencySynchronize();

#pragma unroll
    for (int it = 0; it < 16; it++) {
        int e = tid + it * 256;
        int m = e >> 5, j = e & 31;
        int r = row0 + m;
        float4 v = make_float4(0.f, 0.f, 0.f, 0.f);
        if (r < M) v = *(const float4*)(g_h + (size_t)r * HID + j * 4);
        uint32_t h0, l0, h1, l1;
        split2(v.x, v.y, h0, l0);
        split2(v.z, v.w, h1, l1);
        int o = m * ST2 + j * 2;
        Ah[o] = h0; Ah[o + 1] = h1;
        Al[o] = l0; Al[o + 1] = l1;
    }
    __syncthreads();

    float c[5][4];
#pragma unroll
    for (int ni = 0; ni < 5; ni++)
#pragma unroll
        for (int q = 0; q < 4; q++) c[ni][q] = 0.f;

#pragma unroll
    for (int ks2 = 0; ks2 < 64; ks2 += 8) {
        uint32_t a0, a1, a2, a3, l0, l1, l2, l3;
        ldsm_x4(a0, a1, a2, a3, AhB + (uint32_t)(aRowOff + ks2) * 4u);
        ldsm_x4(l0, l1, l2, l3, AlB + (uint32_t)(aRowOff + ks2) * 4u);
        uint32_t bh[6][2], bl[6][2];
#pragma unroll
        for (int q = 0; q < 3; q++) {
            uint32_t r0, r1, r2, r3;
            ldsm_x4(r0, r1, r2, r3, RhB + (uint32_t)(bRowOff + q * 16 * ST2 + ks2) * 4u);
            bh[2 * q][0] = r0; bh[2 * q][1] = r1;
            bh[2 * q + 1][0] = r2; bh[2 * q + 1][1] = r3;
            ldsm_x4(r0, r1, r2, r3, RlB + (uint32_t)(bRowOff + q * 16 * ST2 + ks2) * 4u);
            bl[2 * q][0] = r0; bl[2 * q][1] = r1;
            bl[2 * q + 1][0] = r2; bl[2 * q + 1][1] = r3;
        }
#pragma unroll
        for (int ni = 0; ni < 5; ni++) {
            mma_bf16(c[ni], a0, a1, a2, a3, bh[ni][0], bh[ni][1]);
            mma_bf16(c[ni], a0, a1, a2, a3, bl[ni][0], bl[ni][1]);
            mma_bf16(c[ni], l0, l1, l2, l3, bh[ni][0], bh[ni][1]);
        }
    }

#pragma unroll
    for (int half = 0; half < 2; half++) {
        int row = row0 + wm * 16 + g + half * 8;
        if (row >= M) continue;
#pragma unroll
        for (int ni = 0; ni < 5; ni++) {
            int col = ni * 8 + tg * 2;
            if (col >= OUT_DIM) continue;
            float2 o;
            o.x = c[ni][half * 2 + 0] + br[col];
            o.y = c[ni][half * 2 + 1] + br[col + 1];
            *(float2*)(out + (size_t)row * OUT_DIM + col) = o;
        }
    }
}

// ---------------- launch ----------------------------------------------------
template <typename K, typename... Args>
static void pdl_launch(K k, dim3 gd, dim3 bd, size_t smem, Args... args) {
    cudaLaunchConfig_t cfg = {};
    cfg.gridDim = gd;
    cfg.blockDim = bd;
    cfg.dynamicSmemBytes = smem;
    cfg.stream = 0;
    cudaLaunchAttribute at[1];
    at[0].id = cudaLaunchAttributeProgrammaticStreamSerialization;
    at[0].val.programmaticStreamSerializationAllowed = 1;
    cfg.attrs = at;
    cfg.numAttrs = 1;
    cudaLaunchKernelEx(&cfg, k, args...);
}

extern "C" void kernel_launch(void* const* d_in, const int* in_sizes, int n_in,
                              void* d_out, int out_size) {
    const float* features = (const float*)d_in[0];
    const int*   src      = (const int*)  d_in[1];
    const int*   dst      = (const int*)  d_in[2];
    const float* edge_w   = (const float*)d_in[3];
    const float* emb_W    = (const float*)d_in[4];
    const float* emb_b    = (const float*)d_in[5];
    const float* W1       = (const float*)d_in[6];
    const float* b1       = (const float*)d_in[7];
    const float* W2       = (const float*)d_in[8];
    const float* b2       = (const float*)d_in[9];
    const float* ro_W     = (const float*)d_in[10];
    const float* ro_b     = (const float*)d_in[11];
    float* out = (float*)d_out;

    const int emb_smem = 2 * 4 * 128 * ST * (int)sizeof(uint32_t);
    const int mlp_smem = (4 * 64 + 4 * 128) * ST2 * (int)sizeof(uint32_t);
    const int ro_smem  = (2 * 128 + 2 * 64) * ST2 * (int)sizeof(uint32_t);
    cudaFuncSetAttribute(emb_gemm_kernel,    cudaFuncAttributeMaxDynamicSharedMemorySize, emb_smem);
    cudaFuncSetAttribute(mlp_fused_kernel,   cudaFuncAttributeMaxDynamicSharedMemorySize, mlp_smem);
    cudaFuncSetAttribute(readout_mma_kernel, cudaFuncAttributeMaxDynamicSharedMemorySize, ro_smem);

    uint32_t *d_W1h, *d_W1l, *d_W2h, *d_W2l;
    cudaGetSymbolAddress((void**)&d_W1h, g_W1h);
    cudaGetSymbolAddress((void**)&d_W1l, g_W1l);
    cudaGetSymbolAddress((void**)&d_W2h, g_W2h);
    cudaGetSymbolAddress((void**)&d_W2l, g_W2l);

    cudaStream_t side = cudaStreamPerThread;
    cudaEvent_t evA, evB;
    cudaEventCreateWithFlags(&evA, cudaEventDisableTiming);
    cudaEventCreateWithFlags(&evB, cudaEventDisableTiming);

    cudaEventRecord(evA, 0);
    cudaStreamWaitEvent(side, evA, 0);

    prep_all_kernel<<<(PREP_TOTAL + 255) / 256, 256>>>(emb_W, W1, W2, ro_W);  // main
    zero_deg_kernel<<<(N_NODES + 255) / 256, 256, 0, side>>>();               // side
    emb_gemm_kernel<<<N_TILES, 512, emb_smem>>>(features, emb_b, N_NODES);    // main
    hist_kernel<<<(N_EDGES + 255) / 256, 256, 0, side>>>(dst);
    scan1_kernel<<<NB_SCAN, 1024, 0, side>>>();
    scan23_kernel<<<NB_SCAN, 1024, 0, side>>>();
    scatter_kernel<<<(N_EDGES + 255) / 256, 256, 0, side>>>(src, dst, edge_w);

    cudaEventRecord(evB, side);
    cudaStreamWaitEvent(0, evB, 0);

    const int agg_blocks = (N_NODES * 32 + 255) / 256;
    for (int l = 0; l < N_LAYERS; l++) {
        if (l == 0)
            agg_kernel<<<agg_blocks, 256>>>();         // normal: upstream dep via event
        else
            pdl_launch(agg_kernel, dim3(agg_blocks), dim3(256), 0);
        pdl_launch(mlp_fused_kernel, dim3(148), dim3(512), (size_t)mlp_smem,
                   (const uint32_t*)(d_W1h + (size_t)l * HID * 64),
                   (const uint32_t*)(d_W1l + (size_t)l * HID * 64),
                   (const uint32_t*)(d_W2h + (size_t)l * HID * 64),
                   (const uint32_t*)(d_W2l + (size_t)l * HID * 64),
                   (const float*)(b1 + (size_t)l * HID),
                   (const float*)(b2 + (size_t)l * HID), (int)N_NODES);
    }
    pdl_launch(readout_mma_kernel, dim3(N_TILES), dim3(256), (size_t)ro_smem,
               (const float*)ro_b, (float*)out, (int)N_NODES);
}

// round 17
// speedup vs baseline: 1.4234x; 1.0034x over previous
#include <cuda_runtime.h>
#include <cuda_bf16.h>
#include <cstdint>

#define N_NODES 50000
#define N_EDGES 625000
#define IN_DIM  512
#define HID     128
#define OUT_DIM 40
#define N_LAYERS 3
#define NB_SCAN ((N_NODES + 1023) / 1024)
#define N_TILES ((N_NODES + 127) / 128)
#define NT64 ((N_NODES + 63) / 64)

// ---------------- scratch ---------------------------------------------------
__device__ float g_h[N_NODES * HID];
__device__ float g_z[N_NODES * HID];
__device__ int   g_deg[N_NODES];
__device__ int   g_off[N_NODES];
__device__ int   g_cur[N_NODES];
__device__ uint2 g_edge[N_EDGES];
__device__ int   g_bsum[64];
__device__ uint32_t g_eBh[HID * (IN_DIM / 2)];
__device__ uint32_t g_eBl[HID * (IN_DIM / 2)];
__device__ uint32_t g_W1h[N_LAYERS * HID * (HID / 2)];
__device__ uint32_t g_W1l[N_LAYERS * HID * (HID / 2)];
__device__ uint32_t g_W2h[N_LAYERS * HID * (HID / 2)];
__device__ uint32_t g_W2l[N_LAYERS * HID * (HID / 2)];
__device__ uint32_t g_roh[64 * 64];
__device__ uint32_t g_rol[64 * 64];

// ---------------- helpers ----------------------------------------------------
__device__ __forceinline__ uint32_t smem_u32(const void* p) {
    uint32_t a;
    asm("{ .reg .u64 t; cvta.to.shared.u64 t, %1; cvt.u32.u64 %0, t; }" : "=r"(a) : "l"(p));
    return a;
}
__device__ __forceinline__ void split2(float v0, float v1, uint32_t& hi, uint32_t& lo) {
    uint16_t h0, h1, l0, l1;
    asm("cvt.rn.bf16.f32 %0, %1;" : "=h"(h0) : "f"(v0));
    asm("cvt.rn.bf16.f32 %0, %1;" : "=h"(h1) : "f"(v1));
    float r0 = v0 - __uint_as_float((uint32_t)h0 << 16);
    float r1 = v1 - __uint_as_float((uint32_t)h1 << 16);
    asm("cvt.rn.bf16.f32 %0, %1;" : "=h"(l0) : "f"(r0));
    asm("cvt.rn.bf16.f32 %0, %1;" : "=h"(l1) : "f"(r1));
    hi = ((uint32_t)h1 << 16) | h0;
    lo = ((uint32_t)l1 << 16) | l0;
}
__device__ __forceinline__ void mma_bf16(float* c, uint32_t a0, uint32_t a1,
                                         uint32_t a2, uint32_t a3,
                                         uint32_t b0, uint32_t b1) {
    asm volatile("mma.sync.aligned.m16n8k16.row.col.f32.bf16.bf16.f32 "
                 "{%0,%1,%2,%3}, {%4,%5,%6,%7}, {%8,%9}, {%0,%1,%2,%3};"
                 : "+f"(c[0]), "+f"(c[1]), "+f"(c[2]), "+f"(c[3])
                 : "r"(a0), "r"(a1), "r"(a2), "r"(a3), "r"(b0), "r"(b1));
}
__device__ __forceinline__ void ldsm_x4(uint32_t& r0, uint32_t& r1, uint32_t& r2,
                                        uint32_t& r3, uint32_t addr) {
    asm volatile("ldmatrix.sync.aligned.m8n8.x4.shared.b16 {%0,%1,%2,%3}, [%4];"
                 : "=r"(r0), "=r"(r1), "=r"(r2), "=r"(r3) : "r"(addr));
}

// ---------------- CSR build -------------------------------------------------
__global__ void zero_deg_kernel() {
    int i = blockIdx.x * blockDim.x + threadIdx.x;
    if (i < N_NODES) g_deg[i] = 0;
}
__global__ void hist_kernel(const int* __restrict__ dst) {
    int e = blockIdx.x * blockDim.x + threadIdx.x;
    if (e < N_EDGES) atomicAdd(&g_deg[dst[e]], 1);
}
__global__ void scan1_kernel() {
    __shared__ int s[1024];
    int t = threadIdx.x;
    int i = blockIdx.x * 1024 + t;
    int v = (i < N_NODES) ? g_deg[i] : 0;
    s[t] = v;
    __syncthreads();
    for (int d = 1; d < 1024; d <<= 1) {
        int tmp = (t >= d) ? s[t - d] : 0;
        __syncthreads();
        s[t] += tmp;
        __syncthreads();
    }
    if (i < N_NODES) g_off[i] = s[t] - v;
    if (t == 1023) g_bsum[blockIdx.x] = s[1023];
}
__global__ void scan23_kernel() {
    __shared__ int red[64];
    __shared__ int base_s;
    int t = threadIdx.x;
    if (t < 64) red[t] = (t < NB_SCAN && t < (int)blockIdx.x) ? g_bsum[t] : 0;
    __syncthreads();
    if (t < 32) {
        int s = red[t] + red[t + 32];
        for (int d = 16; d > 0; d >>= 1) s += __shfl_down_sync(0xffffffffu, s, d);
        if (t == 0) base_s = s;
    }
    __syncthreads();
    int i = blockIdx.x * 1024 + t;
    if (i < N_NODES) {
        int o = g_off[i] + base_s;
        g_off[i] = o;
        g_cur[i] = o;
    }
}
__global__ void scatter_kernel(const int* __restrict__ src,
                               const int* __restrict__ dst,
                               const float* __restrict__ ew) {
    int e = blockIdx.x * blockDim.x + threadIdx.x;
    if (e < N_EDGES) {
        int d = dst[e];
        int pos = atomicAdd(&g_cur[d], 1);
        g_edge[pos] = make_uint2((uint32_t)src[e], __float_as_uint(ew[e]));
    }
}

// ---------------- merged weight prep -----------------------------------------
__global__ void prep_all_kernel(const float* __restrict__ We,
                                const float* __restrict__ W1,
                                const float* __restrict__ W2,
                                const float* __restrict__ Wr) {
    int idx = blockIdx.x * blockDim.x + threadIdx.x;
    uint32_t hi, lo;
    if (idx < 32768) {
        int n = idx >> 8, k2 = idx & 255;
        split2(We[(size_t)(2 * k2) * HID + n], We[(size_t)(2 * k2 + 1) * HID + n], hi, lo);
        g_eBh[idx] = hi;
        g_eBl[idx] = lo;
    } else if (idx < 32768 + N_LAYERS * HID * 64) {
        int j = idx - 32768;
        int l = j / (HID * 64);
        int rem = j - l * HID * 64;
        int n = rem >> 6, k2 = rem & 63;
        const float* w1 = W1 + (size_t)l * HID * HID;
        const float* w2 = W2 + (size_t)l * HID * HID;
        split2(w1[(2 * k2) * HID + n], w1[(2 * k2 + 1) * HID + n], hi, lo);
        g_W1h[j] = hi; g_W1l[j] = lo;
        split2(w2[(2 * k2) * HID + n], w2[(2 * k2 + 1) * HID + n], hi, lo);
        g_W2h[j] = hi; g_W2l[j] = lo;
    } else if (idx < 32768 + N_LAYERS * HID * 64 + 4096) {
        int j = idx - 32768 - N_LAYERS * HID * 64;
        int n = j >> 6, k2 = j & 63;
        hi = 0; lo = 0;
        if (n < OUT_DIM)
            split2(Wr[(2 * k2) * OUT_DIM + n], Wr[(2 * k2 + 1) * OUT_DIM + n], hi, lo);
        g_roh[j] = hi;
        g_rol[j] = lo;
    }
}
#define PREP_TOTAL (32768 + N_LAYERS * HID * 64 + 4096)

// ---------------- emb GEMM: double-buffered, PDL A-prologue ------------------
#define ST 36
#define CHW (128 * ST)
#define BUFW (4 * CHW)
__global__ void __launch_bounds__(512, 1)
emb_gemm_kernel(const float* __restrict__ A, const float* __restrict__ bias, int M) {
    extern __shared__ uint32_t sh[];

    const int tid = threadIdx.x, lane = tid & 31, wid = tid >> 5;
    const int g = lane >> 2, tg = lane & 3;
    const int wm = wid & 7, wn = wid >> 3;
    const int row0 = blockIdx.x * 128;

    const int lr = lane & 7, lo8 = (lane >> 3) & 1, hi16 = (lane >> 4) & 1;
    const uint32_t shB = smem_u32(sh);
    const int aRowOff = (wm * 16 + lr + 8 * lo8) * ST + 4 * hi16;
    const int bRowOff = (wn * 64 + lr + 8 * hi16) * ST + 4 * lo8;

    float4 aR[4];
    uint4  bRh[2], bRl[2];

    // independent prologue: A loads (features = harness input, not prep output)
#pragma unroll
    for (int it = 0; it < 4; it++) {
        int e = tid + it * 512;
        int m = e >> 4, j = e & 15;
        int r = row0 + m;
        aR[it] = make_float4(0.f, 0.f, 0.f, 0.f);
        if (r < M) aR[it] = *(const float4*)(A + (size_t)r * IN_DIM + j * 4);
    }
    cudaGridDependencySynchronize();   // prep_all done -> g_eB* valid
#pragma unroll
    for (int it = 0; it < 2; it++) {
        int e = tid + it * 512;
        int n = e >> 3, q = e & 7;
        bRh[it] = *(const uint4*)(g_eBh + n * 256 + q * 4);
        bRl[it] = *(const uint4*)(g_eBl + n * 256 + q * 4);
    }
    {
        uint32_t* Ah = sh;            uint32_t* Al = sh + CHW;
        uint32_t* Bh = sh + 2 * CHW;  uint32_t* Bl = sh + 3 * CHW;
#pragma unroll
        for (int it = 0; it < 4; it++) {
            int e = tid + it * 512;
            int m = e >> 4, j = e & 15;
            uint32_t h0, l0, h1, l1;
            split2(aR[it].x, aR[it].y, h0, l0);
            split2(aR[it].z, aR[it].w, h1, l1);
            int o = m * ST + j * 2;
            Ah[o] = h0; Ah[o + 1] = h1;
            Al[o] = l0; Al[o + 1] = l1;
        }
#pragma unroll
        for (int it = 0; it < 2; it++) {
            int e = tid + it * 512;
            int n = e >> 3, q = e & 7;
            int o = n * ST + q * 4;
            *(uint4*)(Bh + o) = bRh[it];
            *(uint4*)(Bl + o) = bRl[it];
        }
    }
    __syncthreads();

    float c[8][4];
#pragma unroll
    for (int ni = 0; ni < 8; ni++)
#pragma unroll
        for (int q = 0; q < 4; q++) c[ni][q] = 0.f;

    const int NCH = IN_DIM / 64;
    for (int ci = 0; ci < NCH; ci++) {
        const int p = ci & 1;
        const uint32_t base = shB + (uint32_t)p * BUFW * 4u;
        const uint32_t AhB = base, AlB = base + CHW * 4u;
        const uint32_t BhB = base + 2u * CHW * 4u, BlB = base + 3u * CHW * 4u;

        if (ci + 1 < NCH) {
            int kn = (ci + 1) * 64, kn2 = kn >> 1;
#pragma unroll
            for (int it = 0; it < 4; it++) {
                int e = tid + it * 512;
                int m = e >> 4, j = e & 15;
                int r = row0 + m;
                aR[it] = make_float4(0.f, 0.f, 0.f, 0.f);
                if (r < M) aR[it] = *(const float4*)(A + (size_t)r * IN_DIM + kn + j * 4);
            }
#pragma unroll
            for (int it = 0; it < 2; it++) {
                int e = tid + it * 512;
                int n = e >> 3, q = e & 7;
                bRh[it] = *(const uint4*)(g_eBh + n * 256 + kn2 + q * 4);
                bRl[it] = *(const uint4*)(g_eBl + n * 256 + kn2 + q * 4);
            }
        }

#pragma unroll
        for (int ks2 = 0; ks2 < 32; ks2 += 8) {
            uint32_t a0, a1, a2, a3, l0, l1, l2, l3;
            ldsm_x4(a0, a1, a2, a3, AhB + (uint32_t)(aRowOff + ks2) * 4u);
            ldsm_x4(l0, l1, l2, l3, AlB + (uint32_t)(aRowOff + ks2) * 4u);
            uint32_t bh[8][2], bl[8][2];
#pragma unroll
            for (int q = 0; q < 4; q++) {
                uint32_t r0, r1, r2, r3;
                ldsm_x4(r0, r1, r2, r3, BhB + (uint32_t)(bRowOff + q * 16 * ST + ks2) * 4u);
                bh[2 * q][0] = r0; bh[2 * q][1] = r1;
                bh[2 * q + 1][0] = r2; bh[2 * q + 1][1] = r3;
                ldsm_x4(r0, r1, r2, r3, BlB + (uint32_t)(bRowOff + q * 16 * ST + ks2) * 4u);
                bl[2 * q][0] = r0; bl[2 * q][1] = r1;
                bl[2 * q + 1][0] = r2; bl[2 * q + 1][1] = r3;
            }
#pragma unroll
            for (int ni = 0; ni < 8; ni++) {
                mma_bf16(c[ni], a0, a1, a2, a3, bh[ni][0], bh[ni][1]);
                mma_bf16(c[ni], a0, a1, a2, a3, bl[ni][0], bl[ni][1]);
                mma_bf16(c[ni], l0, l1, l2, l3, bh[ni][0], bh[ni][1]);
            }
        }

        if (ci + 1 < NCH) {
            uint32_t* Ah = sh + (p ^ 1) * BUFW;
            uint32_t* Al = Ah + CHW;
            uint32_t* Bh = Ah + 2 * CHW;
            uint32_t* Bl = Ah + 3 * CHW;
#pragma unroll
            for (int it = 0; it < 4; it++) {
                int e = tid + it * 512;
                int m = e >> 4, j = e & 15;
                uint32_t h0, l0, h1, l1;
                split2(aR[it].x, aR[it].y, h0, l0);
                split2(aR[it].z, aR[it].w, h1, l1);
                int o = m * ST + j * 2;
                Ah[o] = h0; Ah[o + 1] = h1;
                Al[o] = l0; Al[o + 1] = l1;
            }
#pragma unroll
            for (int it = 0; it < 2; it++) {
                int e = tid + it * 512;
                int n = e >> 3, q = e & 7;
                int o = n * ST + q * 4;
                *(uint4*)(Bh + o) = bRh[it];
                *(uint4*)(Bl + o) = bRl[it];
            }
            __syncthreads();
        }
    }

#pragma unroll
    for (int half = 0; half < 2; half++) {
        int row = row0 + wm * 16 + g + half * 8;
        if (row >= M) continue;
#pragma unroll
        for (int ni = 0; ni < 8; ni++) {
            int col = wn * 64 + ni * 8 + tg * 2;
            float2 o;
            o.x = c[ni][half * 2 + 0] + bias[col];
            o.y = c[ni][half * 2 + 1] + bias[col + 1];
            *(float2*)(g_h + (size_t)row * HID + col) = o;
        }
    }
}

// ---------------- aggregation (unroll 4, PDL-aware) --------------------------
__global__ void agg_kernel() {
    cudaGridDependencySynchronize();
    int node = (blockIdx.x * blockDim.x + threadIdx.x) >> 5;
    int lane = threadIdx.x & 31;
    if (node >= N_NODES) return;
    int s = g_off[node];
    int d = g_deg[node];
    float4 acc = *(const float4*)(g_h + (size_t)node * HID + lane * 4);
    int i = 0;
    for (; i + 4 <= d; i += 4) {
        uint2 e0 = g_edge[s + i];
        uint2 e1 = g_edge[s + i + 1];
        uint2 e2 = g_edge[s + i + 2];
        uint2 e3 = g_edge[s + i + 3];
        float w0 = __uint_as_float(e0.y);
        float w1 = __uint_as_float(e1.y);
        float w2 = __uint_as_float(e2.y);
        float w3 = __uint_as_float(e3.y);
        float4 h0 = *(const float4*)(g_h + (size_t)e0.x * HID + lane * 4);
        float4 h1 = *(const float4*)(g_h + (size_t)e1.x * HID + lane * 4);
        float4 h2 = *(const float4*)(g_h + (size_t)e2.x * HID + lane * 4);
        float4 h3 = *(const float4*)(g_h + (size_t)e3.x * HID + lane * 4);
        acc.x += w0 * h0.x + w1 * h1.x + w2 * h2.x + w3 * h3.x;
        acc.y += w0 * h0.y + w1 * h1.y + w2 * h2.y + w3 * h3.y;
        acc.z += w0 * h0.z + w1 * h1.z + w2 * h2.z + w3 * h3.z;
        acc.w += w0 * h0.w + w1 * h1.w + w2 * h2.w + w3 * h3.w;
    }
    for (; i < d; i++) {
        uint2 e0 = g_edge[s + i];
        float w0 = __uint_as_float(e0.y);
        float4 h0 = *(const float4*)(g_h + (size_t)e0.x * HID + lane * 4);
        acc.x += w0 * h0.x; acc.y += w0 * h0.y;
        acc.z += w0 * h0.z; acc.w += w0 * h0.w;
    }
    *(float4*)(g_z + (size_t)node * HID + lane * 4) = acc;
}

// ------ persistent MLP: 2 async warp-groups, PDL weight-staging prologue -----
#define ST2 68
#define BARG() asm volatile("bar.sync %0, %1;" :: "r"(grp + 1), "r"(256) : "memory")
__global__ void __launch_bounds__(512, 1)
mlp_fused_kernel(const uint32_t* __restrict__ W1h, const uint32_t* __restrict__ W1l,
                 const uint32_t* __restrict__ W2h, const uint32_t* __restrict__ W2l,
                 const float* __restrict__ b1, const float* __restrict__ b2, int M) {
    extern __shared__ uint32_t sh[];
    uint32_t* Wh1 = sh + 4 * 64 * ST2;
    uint32_t* Wl1 = Wh1 + 128 * ST2;
    uint32_t* Wh2 = Wl1 + 128 * ST2;
    uint32_t* Wl2 = Wh2 + 128 * ST2;

    const int tid = threadIdx.x, lane = tid & 31, wid = tid >> 5;
    const int grp = wid >> 3;
    const int wg  = wid & 7;
    const int tg_ = tid & 255;
    const int g = lane >> 2, tg = lane & 3;
    const int wm = wg & 3, wn = wg >> 2;

    uint32_t* Ah = sh + grp * 2 * 64 * ST2;
    uint32_t* Al = Ah + 64 * ST2;

    const int lr = lane & 7, lo8 = (lane >> 3) & 1, hi16 = (lane >> 4) & 1;
    const uint32_t AhB  = smem_u32(Ah),  AlB  = smem_u32(Al);
    const uint32_t Wh1B = smem_u32(Wh1), Wl1B = smem_u32(Wl1);
    const uint32_t Wh2B = smem_u32(Wh2), Wl2B = smem_u32(Wl2);
    const int aRowOff = (wm * 16 + lr + 8 * lo8) * ST2 + 4 * hi16;
    const int bRowOff = (wn * 64 + lr + 8 * hi16) * ST2 + 4 * lo8;

#pragma unroll
    for (int it = 0; it < 4; it++) {
        int e = tid + it * 512;
        int n = e >> 4, q = e & 15;
        int o = n * ST2 + q * 4;
        *(uint4*)(Wh1 + o) = *(const uint4*)(W1h + n * 64 + q * 4);
        *(uint4*)(Wl1 + o) = *(const uint4*)(W1l + n * 64 + q * 4);
        *(uint4*)(Wh2 + o) = *(const uint4*)(W2h + n * 64 + q * 4);
        *(uint4*)(Wl2 + o) = *(const uint4*)(W2l + n * 64 + q * 4);
    }
    cudaGridDependencySynchronize();
    __syncthreads();

    const int stride = gridDim.x * 2;
    const int t0 = blockIdx.x * 2 + grp;

    float4 zR[8];
    {
        const int row0 = t0 * 64;
#pragma unroll
        for (int it = 0; it < 8; it++) {
            int e = tg_ + it * 256;
            int m = e >> 5, j = e & 31;
            int r = row0 + m;
            zR[it] = make_float4(0.f, 0.f, 0.f, 0.f);
            if (r < M) zR[it] = *(const float4*)(g_z + (size_t)r * HID + j * 4);
        }
    }

    for (int tile = t0; tile < NT64; tile += stride) {
        const int row0 = tile * 64;
        BARG();

#pragma unroll
        for (int it = 0; it < 8; it++) {
            int e = tg_ + it * 256;
            int m = e >> 5, j = e & 31;
            uint32_t h0, l0, h1, l1;
            split2(zR[it].x, zR[it].y, h0, l0);
            split2(zR[it].z, zR[it].w, h1, l1);
            int o = m * ST2 + j * 2;
            Ah[o] = h0; Ah[o + 1] = h1;
            Al[o] = l0; Al[o + 1] = l1;
        }
        if (tile + stride < NT64) {
            const int nrow0 = (tile + stride) * 64;
#pragma unroll
            for (int it = 0; it < 8; it++) {
                int e = tg_ + it * 256;
                int m = e >> 5, j = e & 31;
                int r = nrow0 + m;
                zR[it] = make_float4(0.f, 0.f, 0.f, 0.f);
                if (r < M) zR[it] = *(const float4*)(g_z + (size_t)r * HID + j * 4);
            }
        }
        BARG();

        float c[8][4];
#pragma unroll
        for (int ni = 0; ni < 8; ni++)
#pragma unroll
            for (int q = 0; q < 4; q++) c[ni][q] = 0.f;

        // GEMM1
#pragma unroll
        for (int ks2 = 0; ks2 < 64; ks2 += 8) {
            uint32_t a0, a1, a2, a3, l0, l1, l2, l3;
            ldsm_x4(a0, a1, a2, a3, AhB + (uint32_t)(aRowOff + ks2) * 4u);
            ldsm_x4(l0, l1, l2, l3, AlB + (uint32_t)(aRowOff + ks2) * 4u);
            uint32_t bh[8][2], bl[8][2];
#pragma unroll
            for (int q = 0; q < 4; q++) {
                uint32_t r0, r1, r2, r3;
                ldsm_x4(r0, r1, r2, r3, Wh1B + (uint32_t)(bRowOff + q * 16 * ST2 + ks2) * 4u);
                bh[2 * q][0] = r0; bh[2 * q][1] = r1;
                bh[2 * q + 1][0] = r2; bh[2 * q + 1][1] = r3;
                ldsm_x4(r0, r1, r2, r3, Wl1B + (uint32_t)(bRowOff + q * 16 * ST2 + ks2) * 4u);
                bl[2 * q][0] = r0; bl[2 * q][1] = r1;
                bl[2 * q + 1][0] = r2; bl[2 * q + 1][1] = r3;
            }
#pragma unroll
            for (int ni = 0; ni < 8; ni++) {
                mma_bf16(c[ni], a0, a1, a2, a3, bh[ni][0], bh[ni][1]);
                mma_bf16(c[ni], a0, a1, a2, a3, bl[ni][0], bl[ni][1]);
                mma_bf16(c[ni], l0, l1, l2, l3, bh[ni][0], bh[ni][1]);
            }
        }
        BARG();

#pragma unroll
        for (int ni = 0; ni < 8; ni++) {
            int col = wn * 64 + ni * 8 + tg * 2;
            float bb0 = b1[col], bb1 = b1[col + 1];
            int k2 = wn * 32 + ni * 4 + tg;
            int r0 = wm * 16 + g;
            uint32_t hi, lo;
            split2(fmaxf(c[ni][0] + bb0, 0.f), fmaxf(c[ni][1] + bb1, 0.f), hi, lo);
            Ah[r0 * ST2 + k2] = hi; Al[r0 * ST2 + k2] = lo;
            split2(fmaxf(c[ni][2] + bb0, 0.f), fmaxf(c[ni][3] + bb1, 0.f), hi, lo);
            Ah[(r0 + 8) * ST2 + k2] = hi; Al[(r0 + 8) * ST2 + k2] = lo;
        }
        BARG();

#pragma unroll
        for (int ni = 0; ni < 8; ni++)
#pragma unroll
            for (int q = 0; q < 4; q++) c[ni][q] = 0.f;

        // GEMM2
#pragma unroll
        for (int ks2 = 0; ks2 < 64; ks2 += 8) {
            uint32_t a0, a1, a2, a3, l0, l1, l2, l3;
            ldsm_x4(a0, a1, a2, a3, AhB + (uint32_t)(aRowOff + ks2) * 4u);
            ldsm_x4(l0, l1, l2, l3, AlB + (uint32_t)(aRowOff + ks2) * 4u);
            uint32_t bh[8][2], bl[8][2];
#pragma unroll
            for (int q = 0; q < 4; q++) {
                uint32_t r0, r1, r2, r3;
                ldsm_x4(r0, r1, r2, r3, Wh2B + (uint32_t)(bRowOff + q * 16 * ST2 + ks2) * 4u);
                bh[2 * q][0] = r0; bh[2 * q][1] = r1;
                bh[2 * q + 1][0] = r2; bh[2 * q + 1][1] = r3;
                ldsm_x4(r0, r1, r2, r3, Wl2B + (uint32_t)(bRowOff + q * 16 * ST2 + ks2) * 4u);
                bl[2 * q][0] = r0; bl[2 * q][1] = r1;
                bl[2 * q + 1][0] = r2; bl[2 * q + 1][1] = r3;
            }
#pragma unroll
            for (int ni = 0; ni < 8; ni++) {
                mma_bf16(c[ni], a0, a1, a2, a3, bh[ni][0], bh[ni][1]);
                mma_bf16(c[ni], a0, a1, a2, a3, bl[ni][0], bl[ni][1]);
                mma_bf16(c[ni], l0, l1, l2, l3, bh[ni][0], bh[ni][1]);
            }
        }

#pragma unroll
        for (int half = 0; half < 2; half++) {
            int row = row0 + wm * 16 + g + half * 8;
            if (row >= M) continue;
#pragma unroll
            for (int ni = 0; ni < 8; ni++) {
                int col = wn * 64 + ni * 8 + tg * 2;
                float2 o;
                o.x = fmaxf(c[ni][half * 2 + 0] + b2[col], 0.f);
                o.y = fmaxf(c[ni][half * 2 + 1] + b2[col + 1], 0.f);
                *(float2*)(g_h + (size_t)row * HID + col) = o;
            }
        }
    }
}

// ---------------- MMA readout (PDL) ------------------------------------------
__global__ void __launch_bounds__(256, 2)
readout_mma_kernel(const float* __restrict__ br, float* __restrict__ out, int M) {
    extern __shared__ uint32_t sh[];
    uint32_t* Ah = sh;
    uint32_t* Al = sh + 128 * ST2;
    uint32_t* Rh = sh + 2 * 128 * ST2;
    uint32_t* Rl = sh + 2 * 128 * ST2 + 64 * ST2;

    const int tid = threadIdx.x, lane = tid & 31, wid = tid >> 5;
    const int g = lane >> 2, tg = lane & 3;
    const int wm = wid;
    const int row0 = blockIdx.x * 128;

    const int lr = lane & 7, lo8 = (lane >> 3) & 1, hi16 = (lane >> 4) & 1;
    const uint32_t AhB = smem_u32(Ah), AlB = smem_u32(Al);
    const uint32_t RhB = smem_u32(Rh), RlB = smem_u32(Rl);
    const int aRowOff = (wm * 16 + lr + 8 * lo8) * ST2 + 4 * hi16;
    const int bRowOff = (lr + 8 * hi16) * ST2 + 4 * lo8;

#pragma unroll
    for (int it = 0; it < 4; it++) {
        int e = tid + it * 256;
        int n = e >> 4, q = e & 15;
        int o = n * ST2 + q * 4;
        *(uint4*)(Rh + o) = *(const uint4*)(g_roh + n * 64 + q * 4);
        *(uint4*)(Rl + o) = *(const uint4*)(g_rol + n * 64 + q * 4);
    }
    cudaGridDependencySynchronize();

#pragma unroll
    for (int it = 0; it < 16; it++) {
        int e = tid + it * 256;
        int m = e >> 5, j = e & 31;
        int r = row0 + m;
        float4 v = make_float4(0.f, 0.f, 0.f, 0.f);
        if (r < M) v = *(const float4*)(g_h + (size_t)r * HID + j * 4);
        uint32_t h0, l0, h1, l1;
        split2(v.x, v.y, h0, l0);
        split2(v.z, v.w, h1, l1);
        int o = m * ST2 + j * 2;
        Ah[o] = h0; Ah[o + 1] = h1;
        Al[o] = l0; Al[o + 1] = l1;
    }
    __syncthreads();

    float c[5][4];
#pragma unroll
    for (int ni = 0; ni < 5; ni++)
#pragma unroll
        for (int q = 0; q < 4; q++) c[ni][q] = 0.f;

#pragma unroll
    for (int ks2 = 0; ks2 < 64; ks2 += 8) {
        uint32_t a0, a1, a2, a3, l0, l1, l2, l3;
        ldsm_x4(a0, a1, a2, a3, AhB + (uint32_t)(aRowOff + ks2) * 4u);
        ldsm_x4(l0, l1, l2, l3, AlB + (uint32_t)(aRowOff + ks2) * 4u);
        uint32_t bh[6][2], bl[6][2];
#pragma unroll
        for (int q = 0; q < 3; q++) {
            uint32_t r0, r1, r2, r3;
            ldsm_x4(r0, r1, r2, r3, RhB + (uint32_t)(bRowOff + q * 16 * ST2 + ks2) * 4u);
            bh[2 * q][0] = r0; bh[2 * q][1] = r1;
            bh[2 * q + 1][0] = r2; bh[2 * q + 1][1] = r3;
            ldsm_x4(r0, r1, r2, r3, RlB + (uint32_t)(bRowOff + q * 16 * ST2 + ks2) * 4u);
            bl[2 * q][0] = r0; bl[2 * q][1] = r1;
            bl[2 * q + 1][0] = r2; bl[2 * q + 1][1] = r3;
        }
#pragma unroll
        for (int ni = 0; ni < 5; ni++) {
            mma_bf16(c[ni], a0, a1, a2, a3, bh[ni][0], bh[ni][1]);
            mma_bf16(c[ni], a0, a1, a2, a3, bl[ni][0], bl[ni][1]);
            mma_bf16(c[ni], l0, l1, l2, l3, bh[ni][0], bh[ni][1]);
        }
    }

#pragma unroll
    for (int half = 0; half < 2; half++) {
        int row = row0 + wm * 16 + g + half * 8;
        if (row >= M) continue;
#pragma unroll
        for (int ni = 0; ni < 5; ni++) {
            int col = ni * 8 + tg * 2;
            if (col >= OUT_DIM) continue;
            float2 o;
            o.x = c[ni][half * 2 + 0] + br[col];
            o.y = c[ni][half * 2 + 1] + br[col + 1];
            *(float2*)(out + (size_t)row * OUT_DIM + col) = o;
        }
    }
}

// ---------------- launch ----------------------------------------------------
template <typename K, typename... Args>
static void pdl_launch(K k, dim3 gd, dim3 bd, size_t smem, Args... args) {
    cudaLaunchConfig_t cfg = {};
    cfg.gridDim = gd;
    cfg.blockDim = bd;
    cfg.dynamicSmemBytes = smem;
    cfg.stream = 0;
    cudaLaunchAttribute at[1];
    at[0].id = cudaLaunchAttributeProgrammaticStreamSerialization;
    at[0].val.programmaticStreamSerializationAllowed = 1;
    cfg.attrs = at;
    cfg.numAttrs = 1;
    cudaLaunchKernelEx(&cfg, k, args...);
}

extern "C" void kernel_launch(void* const* d_in, const int* in_sizes, int n_in,
                              void* d_out, int out_size) {
    const float* features = (const float*)d_in[0];
    const int*   src      = (const int*)  d_in[1];
    const int*   dst      = (const int*)  d_in[2];
    const float* edge_w   = (const float*)d_in[3];
    const float* emb_W    = (const float*)d_in[4];
    const float* emb_b    = (const float*)d_in[5];
    const float* W1       = (const float*)d_in[6];
    const float* b1       = (const float*)d_in[7];
    const float* W2       = (const float*)d_in[8];
    const float* b2       = (const float*)d_in[9];
    const float* ro_W     = (const float*)d_in[10];
    const float* ro_b     = (const float*)d_in[11];
    float* out = (float*)d_out;

    const int emb_smem = 2 * 4 * 128 * ST * (int)sizeof(uint32_t);
    const int mlp_smem = (4 * 64 + 4 * 128) * ST2 * (int)sizeof(uint32_t);
    const int ro_smem  = (2 * 128 + 2 * 64) * ST2 * (int)sizeof(uint32_t);
    cudaFuncSetAttribute(emb_gemm_kernel,    cudaFuncAttributeMaxDynamicSharedMemorySize, emb_smem);
    cudaFuncSetAttribute(mlp_fused_kernel,   cudaFuncAttributeMaxDynamicSharedMemorySize, mlp_smem);
    cudaFuncSetAttribute(readout_mma_kernel, cudaFuncAttributeMaxDynamicSharedMemorySize, ro_smem);

    uint32_t *d_W1h, *d_W1l, *d_W2h, *d_W2l;
    cudaGetSymbolAddress((void**)&d_W1h, g_W1h);
    cudaGetSymbolAddress((void**)&d_W1l, g_W1l);
    cudaGetSymbolAddress((void**)&d_W2h, g_W2h);
    cudaGetSymbolAddress((void**)&d_W2l, g_W2l);

    cudaStream_t side = cudaStreamPerThread;
    cudaEvent_t evA, evB;
    cudaEventCreateWithFlags(&evA, cudaEventDisableTiming);
    cudaEventCreateWithFlags(&evB, cudaEventDisableTiming);

    cudaEventRecord(evA, 0);
    cudaStreamWaitEvent(side, evA, 0);

    prep_all_kernel<<<(PREP_TOTAL + 255) / 256, 256>>>(emb_W, W1, W2, ro_W);  // main
    zero_deg_kernel<<<(N_NODES + 255) / 256, 256, 0, side>>>();               // side
    pdl_launch(emb_gemm_kernel, dim3(N_TILES), dim3(512), (size_t)emb_smem,
               (const float*)features, (const float*)emb_b, (int)N_NODES);    // main, PDL
    hist_kernel<<<(N_EDGES + 255) / 256, 256, 0, side>>>(dst);
    scan1_kernel<<<NB_SCAN, 1024, 0, side>>>();
    scan23_kernel<<<NB_SCAN, 1024, 0, side>>>();
    scatter_kernel<<<(N_EDGES + 255) / 256, 256, 0, side>>>(src, dst, edge_w);

    cudaEventRecord(evB, side);
    cudaStreamWaitEvent(0, evB, 0);

    const int agg_blocks = (N_NODES * 32 + 255) / 256;
    for (int l = 0; l < N_LAYERS; l++) {
        pdl_launch(agg_kernel, dim3(agg_blocks), dim3(256), 0);
        pdl_launch(mlp_fused_kernel, dim3(148), dim3(512), (size_t)mlp_smem,
                   (const uint32_t*)(d_W1h + (size_t)l * HID * 64),
                   (const uint32_t*)(d_W1l + (size_t)l * HID * 64),
                   (const uint32_t*)(d_W2h + (size_t)l * HID * 64),
                   (const uint32_t*)(d_W2l + (size_t)l * HID * 64),
                   (const float*)(b1 + (size_t)l * HID),
                   (const float*)(b2 + (size_t)l * HID), (int)N_NODES);
    }
    pdl_launch(readout_mma_kernel, dim3(N_TILES), dim3(256), (size_t)ro_smem,
               (const float*)ro_b, (float*)out, (int)N_NODES);
}